// round 2
// baseline (speedup 1.0000x reference)
#include <cuda_runtime.h>
#include <cstdint>

// Problem constants
#define CDIM 32
#define HDIM 3200
#define BDIM 1024
#define RDIM 500
#define KDIM 30
#define N2_DIM 1030
#define NITER 200

// Scratch (device globals; no allocation allowed)
__device__ float g_h1[BDIM * HDIM];
__device__ float g_h2[BDIM * HDIM];
__device__ float g_cost[BDIM * RDIM];
__device__ float g_Sinv[KDIM * KDIM];

// ---------------------------------------------------------------------------
// Generic fp32 GEMM:  C[M,N] = act(A[M,K] @ B[N,K]^T + bias[N])
// A row-major [M,K], B row-major [N,K] (both K-contiguous).
// ---------------------------------------------------------------------------
template <int BM, int BN, int BK, int TM, int TN, bool LRELU>
__global__ void sgemm_nt(const float* __restrict__ A, const float* __restrict__ B,
                         const float* __restrict__ bias, float* __restrict__ C,
                         int M, int N, int K) {
  constexpr int NTH = (BM / TM) * (BN / TN);
  __shared__ float As[BK][BM];
  __shared__ float Bs[BK][BN];
  const int tid = threadIdx.x;
  const int row0 = blockIdx.y * BM;
  const int col0 = blockIdx.x * BN;
  const int tx = tid % (BN / TN);
  const int ty = tid / (BN / TN);

  float acc[TM][TN];
#pragma unroll
  for (int i = 0; i < TM; i++)
#pragma unroll
    for (int j = 0; j < TN; j++) acc[i][j] = 0.f;

  for (int k0 = 0; k0 < K; k0 += BK) {
#pragma unroll
    for (int idx = tid; idx < BM * BK; idx += NTH) {
      int r = idx / BK, kk = idx % BK;
      int gr = row0 + r;
      As[kk][r] = (gr < M) ? A[(size_t)gr * K + k0 + kk] : 0.f;
    }
#pragma unroll
    for (int idx = tid; idx < BN * BK; idx += NTH) {
      int r = idx / BK, kk = idx % BK;
      int gc = col0 + r;
      Bs[kk][r] = (gc < N) ? B[(size_t)gc * K + k0 + kk] : 0.f;
    }
    __syncthreads();
#pragma unroll
    for (int kk = 0; kk < BK; kk++) {
      float a[TM], b[TN];
#pragma unroll
      for (int i = 0; i < TM; i++) a[i] = As[kk][ty * TM + i];
#pragma unroll
      for (int j = 0; j < TN; j++) b[j] = Bs[kk][tx * TN + j];
#pragma unroll
      for (int i = 0; i < TM; i++)
#pragma unroll
        for (int j = 0; j < TN; j++) acc[i][j] += a[i] * b[j];
    }
    __syncthreads();
  }

#pragma unroll
  for (int i = 0; i < TM; i++) {
    int gr = row0 + ty * TM + i;
    if (gr >= M) continue;
#pragma unroll
    for (int j = 0; j < TN; j++) {
      int gc = col0 + tx * TN + j;
      if (gc >= N) continue;
      float v = acc[i][j] + bias[gc];
      if (LRELU) v = (v > 0.f) ? v : 0.1f * v;
      C[(size_t)gr * N + gc] = v;
    }
  }
}

// ---------------------------------------------------------------------------
// Setup: S = I + 0.5 * W W^T  (30x30), invert via Gauss-Jordan (S is SPD).
// ---------------------------------------------------------------------------
__global__ void setup_sinv(const float* __restrict__ W, float* __restrict__ Sinv) {
  __shared__ float aug[KDIM][64];
  __shared__ float fac[KDIM];
  __shared__ float pivinv;
  const int tid = threadIdx.x;  // 256 threads

  // S part
  for (int idx = tid; idx < KDIM * KDIM; idx += 256) {
    int a = idx / KDIM, b = idx % KDIM;
    float s = 0.f;
    for (int j = 0; j < RDIM; j++) s += W[a * RDIM + j] * W[b * RDIM + j];
    aug[a][b] = 0.5f * s + (a == b ? 1.f : 0.f);
  }
  // identity part (cols 30..63)
  for (int idx = tid; idx < KDIM * 34; idx += 256) {
    int a = idx / 34, c = 30 + idx % 34;
    aug[a][c] = (c - 30 == a) ? 1.f : 0.f;
  }
  __syncthreads();

  for (int i = 0; i < KDIM; i++) {
    if (tid == 0) pivinv = 1.f / aug[i][i];
    __syncthreads();
    if (tid < 64) aug[i][tid] *= pivinv;
    __syncthreads();
    if (tid < KDIM) fac[tid] = aug[tid][i];
    __syncthreads();
    for (int idx = tid; idx < KDIM * 64; idx += 256) {
      int r = idx / 64, c = idx % 64;
      if (r != i) aug[r][c] -= fac[r] * aug[i][c];
    }
    __syncthreads();
  }
  for (int idx = tid; idx < KDIM * KDIM; idx += 256)
    Sinv[idx] = aug[idx / KDIM][30 + idx % KDIM];
}

// ---------------------------------------------------------------------------
// Persistent ADMM kernel. 4 batch rows per block, 256 threads, 200 iterations.
// State per row: p = x + u (n2 = 1030 floats). z - u = |p|, u = min(p, 0).
//
// Per iteration (rho = 1, so 1+rho = 2):
//   v_r = cost + |p_r|;  rhs2 = v_r + |p_s| - 2
//   g = W v_r;  c = W rhs2                       (fused matvec, warp-reduced)
//   rhs1 = g + |p_k| - 2*cap;  t = rhs1 - 0.5 c
//   y1 = Sinv t;  wt_j = (W^T y1)_j              (W columns cached in regs)
//   x_r = 0.5 v_r - 0.25 (wt + rhs2)
//   x_k = 0.5 (|p_k| - y1)
//   x_s = 0.5 |p_s| + 0.25 (wt - rhs2)
//   p_* <- x_* + min(p_*, 0)
// ---------------------------------------------------------------------------
#define AROWS 4
#define PADR 512

__global__ __launch_bounds__(256, 2)
void admm_kernel(const float* __restrict__ cost, const float* __restrict__ W,
                 const float* __restrict__ cap, const float* __restrict__ SinvG,
                 float* __restrict__ out) {
  extern __shared__ float sm[];
  float* Ws   = sm;                    // [30][512]
  float* cst  = Ws + KDIM * PADR;      // [4][512]
  float* vr   = cst + AROWS * PADR;    // [4][512]
  float* rh   = vr + AROWS * PADR;     // [4][512]
  float* pr   = rh + AROWS * PADR;     // [4][512]
  float* ps   = pr + AROWS * PADR;     // [4][512]
  float* pk   = ps + AROWS * PADR;     // [4][32]
  float* gk   = pk + AROWS * 32;       // [4][32]
  float* ck   = gk + AROWS * 32;       // [4][32]
  float* y1s  = ck + AROWS * 32;       // [4][32]
  float* ts   = y1s + AROWS * 32;      // [4][32]
  float* Ssm  = ts + AROWS * 32;       // [30][33] padded
  float* cap2 = Ssm + KDIM * 33;       // [32]

  const int tid = threadIdx.x;
  const int lane = tid & 31;
  const int wid = tid >> 5;           // 0..7
  const int row0 = blockIdx.x * AROWS;

  // ---- init ----
  for (int idx = tid; idx < KDIM * PADR; idx += 256) {
    int k = idx >> 9, j = idx & (PADR - 1);
    Ws[idx] = (j < RDIM) ? W[k * RDIM + j] : 0.f;
  }
  for (int idx = tid; idx < AROWS * PADR; idx += 256) {
    int r = idx >> 9, j = idx & (PADR - 1);
    cst[idx] = (j < RDIM) ? cost[(size_t)(row0 + r) * RDIM + j] : 0.f;
    vr[idx] = 0.f; rh[idx] = 0.f; pr[idx] = 0.f; ps[idx] = 0.f;
  }
  if (tid < 32) cap2[tid] = (tid < KDIM) ? 2.f * cap[tid] : 0.f;
  for (int idx = tid; idx < KDIM * 33; idx += 256) {
    int k = idx / 33, m = idx % 33;
    Ssm[idx] = (m < KDIM) ? SinvG[k * KDIM + m] : 0.f;
  }
  if (tid < AROWS * 32) { pk[tid] = 0.f; gk[tid] = 0.f; ck[tid] = 0.f; y1s[tid] = 0.f; ts[tid] = 0.f; }
  __syncthreads();

  // W columns for the transpose matvec (iteration-invariant, in registers)
  const int j0 = tid;
  const int j1 = tid + 256;
  float Wr0[KDIM], Wr1[KDIM];
#pragma unroll
  for (int k = 0; k < KDIM; k++) {
    Wr0[k] = Ws[k * PADR + j0];
    Wr1[k] = Ws[k * PADR + j1];  // padded: zero for j1 >= 500
  }

  const int r_w = wid & 3;      // row handled by this warp in M1
  const int half = wid >> 2;    // k-half (0: k 0..14, 1: k 15..29)

  for (int it = 0; it < NITER; it++) {
    // ---- E: v_r, rhs2 ----
#pragma unroll
    for (int r = 0; r < AROWS; r++) {
      {
        float prv = pr[r * PADR + j0], psv = ps[r * PADR + j0];
        float v = cst[r * PADR + j0] + fabsf(prv);
        vr[r * PADR + j0] = v;
        rh[r * PADR + j0] = v + fabsf(psv) - 2.f;
      }
      if (j1 < RDIM) {
        float prv = pr[r * PADR + j1], psv = ps[r * PADR + j1];
        float v = cst[r * PADR + j1] + fabsf(prv);
        vr[r * PADR + j1] = v;
        rh[r * PADR + j1] = v + fabsf(psv) - 2.f;
      }
    }
    __syncthreads();

    // ---- M1: g = W v_r, c = W rhs2 (fused) ----
    {
      float vreg[16], rreg[16];
#pragma unroll
      for (int m = 0; m < 16; m++) {
        vreg[m] = vr[r_w * PADR + lane + 32 * m];
        rreg[m] = rh[r_w * PADR + lane + 32 * m];
      }
      for (int kk = 0; kk < 15; kk++) {
        int k = half * 15 + kk;
        float ag = 0.f, ac = 0.f;
#pragma unroll
        for (int m = 0; m < 16; m++) {
          float w = Ws[k * PADR + lane + 32 * m];
          ag += w * vreg[m];
          ac += w * rreg[m];
        }
#pragma unroll
        for (int o = 16; o > 0; o >>= 1) {
          ag += __shfl_down_sync(0xffffffffu, ag, o);
          ac += __shfl_down_sync(0xffffffffu, ac, o);
        }
        if (lane == 0) { gk[r_w * 32 + k] = ag; ck[r_w * 32 + k] = ac; }
      }
    }
    __syncthreads();

    // ---- Solve: y1 = Sinv (rhs1 - 0.5 c), update p_k ----
    if (wid < AROWS) {
      const int r = wid;
      float pkv = 0.f;
      if (lane < KDIM) {
        pkv = pk[r * 32 + lane];
        float rhs1 = gk[r * 32 + lane] + fabsf(pkv) - cap2[lane];
        ts[r * 32 + lane] = rhs1 - 0.5f * ck[r * 32 + lane];
      }
      __syncwarp(0xffffffffu);
      if (lane < KDIM) {
        float y = 0.f;
#pragma unroll
        for (int m = 0; m < KDIM; m++) y += Ssm[lane * 33 + m] * ts[r * 32 + m];
        y1s[r * 32 + lane] = y;
        float xk = 0.5f * (fabsf(pkv) - y);
        pk[r * 32 + lane] = xk + fminf(pkv, 0.f);
        if (it == NITER - 1)
          out[(size_t)(row0 + r) * N2_DIM + RDIM + lane] = xk;
      }
    }
    __syncthreads();

    // ---- M2: wt = W^T y1 (W in regs), update p_r / p_s ----
#pragma unroll
    for (int r = 0; r < AROWS; r++) {
      float wt0 = 0.f, wt1 = 0.f;
#pragma unroll
      for (int k = 0; k < KDIM; k++) {
        float y = y1s[r * 32 + k];
        wt0 += Wr0[k] * y;
        wt1 += Wr1[k] * y;
      }
      {
        float v = vr[r * PADR + j0], rr = rh[r * PADR + j0];
        float prv = pr[r * PADR + j0], psv = ps[r * PADR + j0];
        float xr = 0.5f * v - 0.25f * (wt0 + rr);
        float xs = 0.5f * fabsf(psv) + 0.25f * (wt0 - rr);
        pr[r * PADR + j0] = xr + fminf(prv, 0.f);
        ps[r * PADR + j0] = xs + fminf(psv, 0.f);
        if (it == NITER - 1) {
          out[(size_t)(row0 + r) * N2_DIM + j0] = xr;
          out[(size_t)(row0 + r) * N2_DIM + RDIM + KDIM + j0] = xs;
        }
      }
      if (j1 < RDIM) {
        float v = vr[r * PADR + j1], rr = rh[r * PADR + j1];
        float prv = pr[r * PADR + j1], psv = ps[r * PADR + j1];
        float xr = 0.5f * v - 0.25f * (wt1 + rr);
        float xs = 0.5f * fabsf(psv) + 0.25f * (wt1 - rr);
        pr[r * PADR + j1] = xr + fminf(prv, 0.f);
        ps[r * PADR + j1] = xs + fminf(psv, 0.f);
        if (it == NITER - 1) {
          out[(size_t)(row0 + r) * N2_DIM + j1] = xr;
          out[(size_t)(row0 + r) * N2_DIM + RDIM + KDIM + j1] = xs;
        }
      }
    }
    __syncthreads();
  }
}

// ---------------------------------------------------------------------------
extern "C" void kernel_launch(void* const* d_in, const int* in_sizes, int n_in,
                              void* d_out, int out_size) {
  const float* d   = (const float*)d_in[0];  // [1024,32]
  const float* W1  = (const float*)d_in[1];  // [3200,32]
  const float* b1  = (const float*)d_in[2];  // [3200]
  const float* W2  = (const float*)d_in[3];  // [3200,3200]
  const float* b2  = (const float*)d_in[4];  // [3200]
  const float* W3  = (const float*)d_in[5];  // [500,3200]
  const float* b3  = (const float*)d_in[6];  // [500]
  const float* Wm  = (const float*)d_in[7];  // [30,500]
  const float* cap = (const float*)d_in[8];  // [30]
  float* out = (float*)d_out;                // [1024,1030]

  float *h1, *h2, *cost, *sinv;
  cudaGetSymbolAddress((void**)&h1, g_h1);
  cudaGetSymbolAddress((void**)&h2, g_h2);
  cudaGetSymbolAddress((void**)&cost, g_cost);
  cudaGetSymbolAddress((void**)&sinv, g_Sinv);

  // Precompute Sinv = (I + 0.5 W W^T)^-1
  setup_sinv<<<1, 256>>>(Wm, sinv);

  // MLP
  sgemm_nt<128, 128, 8, 8, 8, true><<<dim3(25, 8), 256>>>(d, W1, b1, h1, BDIM, HDIM, CDIM);
  sgemm_nt<128, 128, 8, 8, 8, true><<<dim3(25, 8), 256>>>(h1, W2, b2, h2, BDIM, HDIM, HDIM);
  sgemm_nt<64, 64, 8, 4, 4, false><<<dim3(8, 16), 256>>>(h2, W3, b3, cost, BDIM, RDIM, HDIM);

  // ADMM (persistent, 4 rows/block)
  const int smem_bytes = (KDIM * PADR + 5 * AROWS * PADR + 5 * AROWS * 32 + KDIM * 33 + 32) * (int)sizeof(float);
  cudaFuncSetAttribute(admm_kernel, cudaFuncAttributeMaxDynamicSharedMemorySize, smem_bytes);
  admm_kernel<<<BDIM / AROWS, 256, smem_bytes>>>(cost, Wm, cap, sinv, out);
}

// round 4
// speedup vs baseline: 1.7488x; 1.7488x over previous
#include <cuda_runtime.h>
#include <cuda_bf16.h>
#include <cstdint>

// Problem constants
#define CDIM 32
#define HDIM 3200
#define BDIM 1024
#define RDIM 500
#define KDIM 30
#define N2_DIM 1030
#define NITER 200

// ---------------------------------------------------------------------------
// Device-global scratch (no allocation allowed)
// ---------------------------------------------------------------------------
__device__ __nv_bfloat16 g_dh[BDIM * CDIM],  g_dl[BDIM * CDIM];
__device__ __nv_bfloat16 g_W1h[HDIM * CDIM], g_W1l[HDIM * CDIM];
__device__ __nv_bfloat16 g_W2h[HDIM * HDIM], g_W2l[HDIM * HDIM];
__device__ __nv_bfloat16 g_W3h[RDIM * HDIM], g_W3l[RDIM * HDIM];
__device__ __nv_bfloat16 g_h1h[BDIM * HDIM], g_h1l[BDIM * HDIM];
__device__ __nv_bfloat16 g_h2h[BDIM * HDIM], g_h2l[BDIM * HDIM];
__device__ float g_cost[BDIM * RDIM];
__device__ float g_Sinv[KDIM * KDIM];

// ---------------------------------------------------------------------------
// PTX helpers (plain sm_80+/sm_90 features only — no arch-'a' gated instrs)
// ---------------------------------------------------------------------------
__device__ __forceinline__ uint32_t smem_u32(const void* p) {
  uint32_t a;
  asm("{ .reg .u64 t; cvta.to.shared.u64 t, %1; cvt.u32.u64 %0, t; }" : "=r"(a) : "l"(p));
  return a;
}
__device__ __forceinline__ void ldsm4(uint32_t* r, uint32_t a) {
  asm volatile("ldmatrix.sync.aligned.m8n8.x4.shared.b16 {%0,%1,%2,%3}, [%4];"
               : "=r"(r[0]), "=r"(r[1]), "=r"(r[2]), "=r"(r[3]) : "r"(a));
}
__device__ __forceinline__ void mma16816(float* c, const uint32_t* a, const uint32_t* b) {
  asm volatile(
      "mma.sync.aligned.m16n8k16.row.col.f32.bf16.bf16.f32 "
      "{%0,%1,%2,%3}, {%4,%5,%6,%7}, {%8,%9}, {%0,%1,%2,%3};"
      : "+f"(c[0]), "+f"(c[1]), "+f"(c[2]), "+f"(c[3])
      : "r"(a[0]), "r"(a[1]), "r"(a[2]), "r"(a[3]), "r"(b[0]), "r"(b[1]));
}
#define CP_COMMIT() asm volatile("cp.async.commit_group;" ::: "memory")
#define CP_WAIT(n)  asm volatile("cp.async.wait_group %0;" :: "n"(n) : "memory")

// ---------------------------------------------------------------------------
// fp32 -> (bf16 hi, bf16 lo) split, 4-wide
// ---------------------------------------------------------------------------
__global__ void cvt_split4(const float* __restrict__ in, __nv_bfloat16* __restrict__ hi,
                           __nv_bfloat16* __restrict__ lo, int n4) {
  int i = blockIdx.x * 256 + threadIdx.x;
  if (i >= n4) return;
  float4 v = reinterpret_cast<const float4*>(in)[i];
  __nv_bfloat16 h0 = __float2bfloat16_rn(v.x), h1 = __float2bfloat16_rn(v.y);
  __nv_bfloat16 h2 = __float2bfloat16_rn(v.z), h3 = __float2bfloat16_rn(v.w);
  __nv_bfloat16 l0 = __float2bfloat16_rn(v.x - __bfloat162float(h0));
  __nv_bfloat16 l1 = __float2bfloat16_rn(v.y - __bfloat162float(h1));
  __nv_bfloat16 l2 = __float2bfloat16_rn(v.z - __bfloat162float(h2));
  __nv_bfloat16 l3 = __float2bfloat16_rn(v.w - __bfloat162float(h3));
  uint2 ph, pl;
  ph.x = ((uint32_t)__bfloat16_as_ushort(h1) << 16) | __bfloat16_as_ushort(h0);
  ph.y = ((uint32_t)__bfloat16_as_ushort(h3) << 16) | __bfloat16_as_ushort(h2);
  pl.x = ((uint32_t)__bfloat16_as_ushort(l1) << 16) | __bfloat16_as_ushort(l0);
  pl.y = ((uint32_t)__bfloat16_as_ushort(l3) << 16) | __bfloat16_as_ushort(l2);
  reinterpret_cast<uint2*>(hi)[i] = ph;
  reinterpret_cast<uint2*>(lo)[i] = pl;
}

// ---------------------------------------------------------------------------
// Async tile loader: 128 rows x 64 bf16 (128 B/row), SW128 swizzle, cp.async 16B
// ---------------------------------------------------------------------------
__device__ __forceinline__ void load_tile_async(uint32_t tile, const __nv_bfloat16* __restrict__ g,
                                                int row0, int rmax, int ldk, int k0, int kmax,
                                                int tid) {
#pragma unroll
  for (int t = 0; t < 4; t++) {
    int v = tid + t * 256;          // 0..1023
    int r = v >> 3;                 // tile row 0..127
    int cs = v & 7;                 // 16B segment
    int gr = row0 + r;
    int gk = k0 + cs * 8;
    uint32_t bo = ((uint32_t)r << 7) + ((uint32_t)cs << 4);
    uint32_t sw = bo ^ ((bo >> 3) & 0x70);
    uint32_t dst = tile + sw;
    if (gr < rmax && gk < kmax) {
      const void* src = g + (size_t)gr * ldk + gk;
      asm volatile("cp.async.cg.shared.global [%0], [%1], 16;" :: "r"(dst), "l"(src));
    } else {
      asm volatile("st.shared.v4.b32 [%0], {%1,%1,%1,%1};" :: "r"(dst), "r"(0u));
    }
  }
}

// ---------------------------------------------------------------------------
// bf16x3 split GEMM via mma.sync m16n8k16:
//   C[M,N] = act((Ah+Al)[M,K] @ (Bh+Bl)[N,K]^T + bias)  ~=  AhBh + AlBh + AhBl
// 128x128 CTA, BK=64, double-buffered cp.async. 8 warps, 64x32 per warp.
// ---------------------------------------------------------------------------
template <bool LRELU, bool SPLIT>
__global__ __launch_bounds__(256, 1)
void mma_gemm(const __nv_bfloat16* __restrict__ Ah, const __nv_bfloat16* __restrict__ Al,
              const __nv_bfloat16* __restrict__ Bh, const __nv_bfloat16* __restrict__ Bl,
              const float* __restrict__ bias, float* __restrict__ Cf,
              __nv_bfloat16* __restrict__ Ch, __nv_bfloat16* __restrict__ Cl,
              int M, int N, int K) {
  extern __shared__ char smem[];
  const uint32_t sb = smem_u32(smem);
  const int tid = threadIdx.x, wid = tid >> 5, lane = tid & 31;
  const int m0 = blockIdx.y * 128, n0 = blockIdx.x * 128;
  const int warp_m = wid & 1;    // 0..1 -> 64-row groups
  const int warp_n = wid >> 1;   // 0..3 -> 32-col groups

  // Stage layout: stage*65536 + {Ah:0, Al:16384, Bh:32768, Bl:49152}
  const int NC = (K + 63) / 64;

  float acc[4][4][4];
#pragma unroll
  for (int mt = 0; mt < 4; mt++)
#pragma unroll
    for (int nt = 0; nt < 4; nt++)
#pragma unroll
      for (int i = 0; i < 4; i++) acc[mt][nt][i] = 0.f;

  // Prologue: load stage 0
  {
    uint32_t tb = sb;
    load_tile_async(tb + 0,     Ah, m0, M, K, 0, K, tid);
    load_tile_async(tb + 16384, Al, m0, M, K, 0, K, tid);
    load_tile_async(tb + 32768, Bh, n0, N, K, 0, K, tid);
    load_tile_async(tb + 49152, Bl, n0, N, K, 0, K, tid);
    CP_COMMIT();
  }

  // Per-lane ldmatrix address components (row/segment within tile)
  const int a_r = (lane & 15);               // A: rows m+0..15
  const uint32_t a_koff = (lane & 16) ? 16u : 0u;  // A: k segment select
  const int b_r = ((lane & 16) ? 8 : 0) + (lane & 7);  // B: rows n+{0..7|8..15}
  const uint32_t b_koff = (lane & 8) ? 16u : 0u;

  for (int c = 0; c < NC; c++) {
    if (c + 1 < NC) {
      uint32_t tb = sb + ((c + 1) & 1) * 65536;
      int k0 = (c + 1) * 64;
      load_tile_async(tb + 0,     Ah, m0, M, K, k0, K, tid);
      load_tile_async(tb + 16384, Al, m0, M, K, k0, K, tid);
      load_tile_async(tb + 32768, Bh, n0, N, K, k0, K, tid);
      load_tile_async(tb + 49152, Bl, n0, N, K, k0, K, tid);
      CP_COMMIT();
      CP_WAIT(1);
    } else {
      CP_WAIT(0);
    }
    __syncthreads();

    const uint32_t tb = sb + (c & 1) * 65536;
#pragma unroll
    for (int ks = 0; ks < 4; ks++) {
      const uint32_t kb = ks * 32;
      uint32_t ah[4][4], al[4][4], bh[8], bl[8];
#pragma unroll
      for (int mt = 0; mt < 4; mt++) {
        uint32_t bo = ((uint32_t)(warp_m * 64 + mt * 16 + a_r) << 7) + kb + a_koff;
        uint32_t sw = bo ^ ((bo >> 3) & 0x70);
        ldsm4(ah[mt], tb + sw);
        ldsm4(al[mt], tb + 16384 + sw);
      }
#pragma unroll
      for (int g2 = 0; g2 < 2; g2++) {
        uint32_t bo = ((uint32_t)(warp_n * 32 + g2 * 16 + b_r) << 7) + kb + b_koff;
        uint32_t sw = bo ^ ((bo >> 3) & 0x70);
        ldsm4(bh + g2 * 4, tb + 32768 + sw);
        ldsm4(bl + g2 * 4, tb + 49152 + sw);
      }
#pragma unroll
      for (int mt = 0; mt < 4; mt++)
#pragma unroll
        for (int nt = 0; nt < 4; nt++) {
          mma16816(acc[mt][nt], ah[mt], bh + nt * 2);
          mma16816(acc[mt][nt], al[mt], bh + nt * 2);
          mma16816(acc[mt][nt], ah[mt], bl + nt * 2);
        }
    }
    __syncthreads();
  }

  // Epilogue: bias + optional lrelu, write fp32 or bf16 hi/lo split
#pragma unroll
  for (int mt = 0; mt < 4; mt++) {
#pragma unroll
    for (int nt = 0; nt < 4; nt++) {
#pragma unroll
      for (int i = 0; i < 4; i++) {
        int row = m0 + warp_m * 64 + mt * 16 + (lane >> 2) + ((i & 2) ? 8 : 0);
        int col = n0 + warp_n * 32 + nt * 8 + ((lane & 3) << 1) + (i & 1);
        if (col < N) {
          float v = acc[mt][nt][i] + bias[col];
          if (LRELU) v = (v > 0.f) ? v : 0.1f * v;
          if (SPLIT) {
            __nv_bfloat16 h = __float2bfloat16_rn(v);
            Ch[(size_t)row * N + col] = h;
            Cl[(size_t)row * N + col] = __float2bfloat16_rn(v - __bfloat162float(h));
          } else {
            Cf[(size_t)row * N + col] = v;
          }
        }
      }
    }
  }
}

// ---------------------------------------------------------------------------
// Setup: S = I + 0.5 * W W^T (30x30), invert via Gauss-Jordan.
// ---------------------------------------------------------------------------
__global__ void setup_sinv(const float* __restrict__ W, float* __restrict__ Sinv) {
  __shared__ float aug[KDIM][64];
  __shared__ float fac[KDIM];
  __shared__ float pivinv;
  const int tid = threadIdx.x;  // 256 threads

  for (int idx = tid; idx < KDIM * KDIM; idx += 256) {
    int a = idx / KDIM, b = idx % KDIM;
    float s = 0.f;
    for (int j = 0; j < RDIM; j++) s += W[a * RDIM + j] * W[b * RDIM + j];
    aug[a][b] = 0.5f * s + (a == b ? 1.f : 0.f);
  }
  for (int idx = tid; idx < KDIM * 34; idx += 256) {
    int a = idx / 34, c = 30 + idx % 34;
    aug[a][c] = (c - 30 == a) ? 1.f : 0.f;
  }
  __syncthreads();

  for (int i = 0; i < KDIM; i++) {
    if (tid == 0) pivinv = 1.f / aug[i][i];
    __syncthreads();
    if (tid < 64) aug[i][tid] *= pivinv;
    __syncthreads();
    if (tid < KDIM) fac[tid] = aug[tid][i];
    __syncthreads();
    for (int idx = tid; idx < KDIM * 64; idx += 256) {
      int r = idx / 64, c = idx % 64;
      if (r != i) aug[r][c] -= fac[r] * aug[i][c];
    }
    __syncthreads();
  }
  for (int idx = tid; idx < KDIM * KDIM; idx += 256)
    Sinv[idx] = aug[idx / KDIM][30 + idx % KDIM];
}

// ---------------------------------------------------------------------------
// Persistent ADMM kernel (unchanged from R2 passing version).
// ---------------------------------------------------------------------------
#define AROWS 4
#define PADR 512

__global__ __launch_bounds__(256, 2)
void admm_kernel(const float* __restrict__ cost, const float* __restrict__ W,
                 const float* __restrict__ cap, const float* __restrict__ SinvG,
                 float* __restrict__ out) {
  extern __shared__ float sm[];
  float* Ws   = sm;
  float* cst  = Ws + KDIM * PADR;
  float* vr   = cst + AROWS * PADR;
  float* rh   = vr + AROWS * PADR;
  float* pr   = rh + AROWS * PADR;
  float* ps   = pr + AROWS * PADR;
  float* pk   = ps + AROWS * PADR;
  float* gk   = pk + AROWS * 32;
  float* ck   = gk + AROWS * 32;
  float* y1s  = ck + AROWS * 32;
  float* ts   = y1s + AROWS * 32;
  float* Ssm  = ts + AROWS * 32;
  float* cap2 = Ssm + KDIM * 33;

  const int tid = threadIdx.x;
  const int lane = tid & 31;
  const int wid = tid >> 5;
  const int row0 = blockIdx.x * AROWS;

  for (int idx = tid; idx < KDIM * PADR; idx += 256) {
    int k = idx >> 9, j = idx & (PADR - 1);
    Ws[idx] = (j < RDIM) ? W[k * RDIM + j] : 0.f;
  }
  for (int idx = tid; idx < AROWS * PADR; idx += 256) {
    int r = idx >> 9, j = idx & (PADR - 1);
    cst[idx] = (j < RDIM) ? cost[(size_t)(row0 + r) * RDIM + j] : 0.f;
    vr[idx] = 0.f; rh[idx] = 0.f; pr[idx] = 0.f; ps[idx] = 0.f;
  }
  if (tid < 32) cap2[tid] = (tid < KDIM) ? 2.f * cap[tid] : 0.f;
  for (int idx = tid; idx < KDIM * 33; idx += 256) {
    int k = idx / 33, m = idx % 33;
    Ssm[idx] = (m < KDIM) ? SinvG[k * KDIM + m] : 0.f;
  }
  if (tid < AROWS * 32) { pk[tid] = 0.f; gk[tid] = 0.f; ck[tid] = 0.f; y1s[tid] = 0.f; ts[tid] = 0.f; }
  __syncthreads();

  const int j0 = tid;
  const int j1 = tid + 256;
  float Wr0[KDIM], Wr1[KDIM];
#pragma unroll
  for (int k = 0; k < KDIM; k++) {
    Wr0[k] = Ws[k * PADR + j0];
    Wr1[k] = Ws[k * PADR + j1];
  }

  const int r_w = wid & 3;
  const int half = wid >> 2;

  for (int it = 0; it < NITER; it++) {
#pragma unroll
    for (int r = 0; r < AROWS; r++) {
      {
        float prv = pr[r * PADR + j0], psv = ps[r * PADR + j0];
        float v = cst[r * PADR + j0] + fabsf(prv);
        vr[r * PADR + j0] = v;
        rh[r * PADR + j0] = v + fabsf(psv) - 2.f;
      }
      if (j1 < RDIM) {
        float prv = pr[r * PADR + j1], psv = ps[r * PADR + j1];
        float v = cst[r * PADR + j1] + fabsf(prv);
        vr[r * PADR + j1] = v;
        rh[r * PADR + j1] = v + fabsf(psv) - 2.f;
      }
    }
    __syncthreads();

    {
      float vreg[16], rreg[16];
#pragma unroll
      for (int m = 0; m < 16; m++) {
        vreg[m] = vr[r_w * PADR + lane + 32 * m];
        rreg[m] = rh[r_w * PADR + lane + 32 * m];
      }
      for (int kk = 0; kk < 15; kk++) {
        int k = half * 15 + kk;
        float ag = 0.f, ac = 0.f;
#pragma unroll
        for (int m = 0; m < 16; m++) {
          float w = Ws[k * PADR + lane + 32 * m];
          ag += w * vreg[m];
          ac += w * rreg[m];
        }
#pragma unroll
        for (int o = 16; o > 0; o >>= 1) {
          ag += __shfl_down_sync(0xffffffffu, ag, o);
          ac += __shfl_down_sync(0xffffffffu, ac, o);
        }
        if (lane == 0) { gk[r_w * 32 + k] = ag; ck[r_w * 32 + k] = ac; }
      }
    }
    __syncthreads();

    if (wid < AROWS) {
      const int r = wid;
      float pkv = 0.f;
      if (lane < KDIM) {
        pkv = pk[r * 32 + lane];
        float rhs1 = gk[r * 32 + lane] + fabsf(pkv) - cap2[lane];
        ts[r * 32 + lane] = rhs1 - 0.5f * ck[r * 32 + lane];
      }
      __syncwarp(0xffffffffu);
      if (lane < KDIM) {
        float y = 0.f;
#pragma unroll
        for (int m = 0; m < KDIM; m++) y += Ssm[lane * 33 + m] * ts[r * 32 + m];
        y1s[r * 32 + lane] = y;
        float xk = 0.5f * (fabsf(pkv) - y);
        pk[r * 32 + lane] = xk + fminf(pkv, 0.f);
        if (it == NITER - 1)
          out[(size_t)(row0 + r) * N2_DIM + RDIM + lane] = xk;
      }
    }
    __syncthreads();

#pragma unroll
    for (int r = 0; r < AROWS; r++) {
      float wt0 = 0.f, wt1 = 0.f;
#pragma unroll
      for (int k = 0; k < KDIM; k++) {
        float y = y1s[r * 32 + k];
        wt0 += Wr0[k] * y;
        wt1 += Wr1[k] * y;
      }
      {
        float v = vr[r * PADR + j0], rr = rh[r * PADR + j0];
        float prv = pr[r * PADR + j0], psv = ps[r * PADR + j0];
        float xr = 0.5f * v - 0.25f * (wt0 + rr);
        float xs = 0.5f * fabsf(psv) + 0.25f * (wt0 - rr);
        pr[r * PADR + j0] = xr + fminf(prv, 0.f);
        ps[r * PADR + j0] = xs + fminf(psv, 0.f);
        if (it == NITER - 1) {
          out[(size_t)(row0 + r) * N2_DIM + j0] = xr;
          out[(size_t)(row0 + r) * N2_DIM + RDIM + KDIM + j0] = xs;
        }
      }
      if (j1 < RDIM) {
        float v = vr[r * PADR + j1], rr = rh[r * PADR + j1];
        float prv = pr[r * PADR + j1], psv = ps[r * PADR + j1];
        float xr = 0.5f * v - 0.25f * (wt1 + rr);
        float xs = 0.5f * fabsf(psv) + 0.25f * (wt1 - rr);
        pr[r * PADR + j1] = xr + fminf(prv, 0.f);
        ps[r * PADR + j1] = xs + fminf(psv, 0.f);
        if (it == NITER - 1) {
          out[(size_t)(row0 + r) * N2_DIM + j1] = xr;
          out[(size_t)(row0 + r) * N2_DIM + RDIM + KDIM + j1] = xs;
        }
      }
    }
    __syncthreads();
  }
}

// ---------------------------------------------------------------------------
extern "C" void kernel_launch(void* const* d_in, const int* in_sizes, int n_in,
                              void* d_out, int out_size) {
  const float* d   = (const float*)d_in[0];  // [1024,32]
  const float* W1  = (const float*)d_in[1];  // [3200,32]
  const float* b1  = (const float*)d_in[2];  // [3200]
  const float* W2  = (const float*)d_in[3];  // [3200,3200]
  const float* b2  = (const float*)d_in[4];  // [3200]
  const float* W3  = (const float*)d_in[5];  // [500,3200]
  const float* b3  = (const float*)d_in[6];  // [500]
  const float* Wm  = (const float*)d_in[7];  // [30,500]
  const float* cap = (const float*)d_in[8];  // [30]
  float* out = (float*)d_out;                // [1024,1030]

  __nv_bfloat16 *dh, *dl, *w1h, *w1l, *w2h, *w2l, *w3h, *w3l, *h1h, *h1l, *h2h, *h2l;
  float *cost, *sinv;
  cudaGetSymbolAddress((void**)&dh, g_dh);   cudaGetSymbolAddress((void**)&dl, g_dl);
  cudaGetSymbolAddress((void**)&w1h, g_W1h); cudaGetSymbolAddress((void**)&w1l, g_W1l);
  cudaGetSymbolAddress((void**)&w2h, g_W2h); cudaGetSymbolAddress((void**)&w2l, g_W2l);
  cudaGetSymbolAddress((void**)&w3h, g_W3h); cudaGetSymbolAddress((void**)&w3l, g_W3l);
  cudaGetSymbolAddress((void**)&h1h, g_h1h); cudaGetSymbolAddress((void**)&h1l, g_h1l);
  cudaGetSymbolAddress((void**)&h2h, g_h2h); cudaGetSymbolAddress((void**)&h2l, g_h2l);
  cudaGetSymbolAddress((void**)&cost, g_cost);
  cudaGetSymbolAddress((void**)&sinv, g_Sinv);

  // Split inputs into bf16 hi/lo
  cvt_split4<<<(BDIM * CDIM / 4 + 255) / 256, 256>>>(d, dh, dl, BDIM * CDIM / 4);
  cvt_split4<<<(HDIM * CDIM / 4 + 255) / 256, 256>>>(W1, w1h, w1l, HDIM * CDIM / 4);
  cvt_split4<<<(HDIM * HDIM / 4 + 255) / 256, 256>>>(W2, w2h, w2l, HDIM * HDIM / 4);
  cvt_split4<<<(RDIM * HDIM / 4 + 255) / 256, 256>>>(W3, w3h, w3l, RDIM * HDIM / 4);

  setup_sinv<<<1, 256>>>(Wm, sinv);

  const int gemm_smem = 2 * 65536;  // 131072 B
  cudaFuncSetAttribute(mma_gemm<true, true>, cudaFuncAttributeMaxDynamicSharedMemorySize, gemm_smem);
  cudaFuncSetAttribute(mma_gemm<false, false>, cudaFuncAttributeMaxDynamicSharedMemorySize, gemm_smem);

  // MLP on tensor cores (bf16x3 split via mma.sync)
  mma_gemm<true, true><<<dim3(HDIM / 128, BDIM / 128), 256, gemm_smem>>>(
      dh, dl, w1h, w1l, b1, nullptr, h1h, h1l, BDIM, HDIM, CDIM);
  mma_gemm<true, true><<<dim3(HDIM / 128, BDIM / 128), 256, gemm_smem>>>(
      h1h, h1l, w2h, w2l, b2, nullptr, h2h, h2l, BDIM, HDIM, HDIM);
  mma_gemm<false, false><<<dim3((RDIM + 127) / 128, BDIM / 128), 256, gemm_smem>>>(
      h2h, h2l, w3h, w3l, b3, cost, nullptr, nullptr, BDIM, RDIM, HDIM);

  // ADMM (persistent, 4 rows/block)
  const int admm_smem = (KDIM * PADR + 5 * AROWS * PADR + 5 * AROWS * 32 + KDIM * 33 + 32) * (int)sizeof(float);
  cudaFuncSetAttribute(admm_kernel, cudaFuncAttributeMaxDynamicSharedMemorySize, admm_smem);
  admm_kernel<<<BDIM / AROWS, 256, admm_smem>>>(cost, Wm, cap, sinv, out);
}

// round 5
// speedup vs baseline: 1.7512x; 1.0014x over previous
#include <cuda_runtime.h>
#include <cuda_bf16.h>
#include <cstdint>

// Problem constants
#define CDIM 32
#define HDIM 3200
#define BDIM 1024
#define RDIM 500
#define KDIM 30
#define N2_DIM 1030
#define NITER 200

// ---------------------------------------------------------------------------
// Device-global scratch (no allocation allowed)
// ---------------------------------------------------------------------------
__device__ __nv_bfloat16 g_dh[BDIM * CDIM],  g_dl[BDIM * CDIM];
__device__ __nv_bfloat16 g_W1h[HDIM * CDIM], g_W1l[HDIM * CDIM];
__device__ __nv_bfloat16 g_W2h[HDIM * HDIM], g_W2l[HDIM * HDIM];
__device__ __nv_bfloat16 g_W3h[RDIM * HDIM], g_W3l[RDIM * HDIM];
__device__ __nv_bfloat16 g_h1h[BDIM * HDIM], g_h1l[BDIM * HDIM];
__device__ __nv_bfloat16 g_h2h[BDIM * HDIM], g_h2l[BDIM * HDIM];
__device__ float g_cost[BDIM * RDIM];
__device__ float g_Sinv[KDIM * KDIM];

// ---------------------------------------------------------------------------
// PTX helpers (plain sm_80+/sm_90 features only — no arch-'a' gated instrs)
// ---------------------------------------------------------------------------
__device__ __forceinline__ uint32_t smem_u32(const void* p) {
  uint32_t a;
  asm("{ .reg .u64 t; cvta.to.shared.u64 t, %1; cvt.u32.u64 %0, t; }" : "=r"(a) : "l"(p));
  return a;
}
__device__ __forceinline__ void ldsm4(uint32_t* r, uint32_t a) {
  asm volatile("ldmatrix.sync.aligned.m8n8.x4.shared.b16 {%0,%1,%2,%3}, [%4];"
               : "=r"(r[0]), "=r"(r[1]), "=r"(r[2]), "=r"(r[3]) : "r"(a));
}
__device__ __forceinline__ void mma16816(float* c, const uint32_t* a, const uint32_t* b) {
  asm volatile(
      "mma.sync.aligned.m16n8k16.row.col.f32.bf16.bf16.f32 "
      "{%0,%1,%2,%3}, {%4,%5,%6,%7}, {%8,%9}, {%0,%1,%2,%3};"
      : "+f"(c[0]), "+f"(c[1]), "+f"(c[2]), "+f"(c[3])
      : "r"(a[0]), "r"(a[1]), "r"(a[2]), "r"(a[3]), "r"(b[0]), "r"(b[1]));
}
#define CP_COMMIT() asm volatile("cp.async.commit_group;" ::: "memory")
#define CP_WAIT(n)  asm volatile("cp.async.wait_group %0;" :: "n"(n) : "memory")

// ---------------------------------------------------------------------------
// fp32 -> (bf16 hi, bf16 lo) split, 4-wide
// ---------------------------------------------------------------------------
__global__ void cvt_split4(const float* __restrict__ in, __nv_bfloat16* __restrict__ hi,
                           __nv_bfloat16* __restrict__ lo, int n4) {
  int i = blockIdx.x * 256 + threadIdx.x;
  if (i >= n4) return;
  float4 v = reinterpret_cast<const float4*>(in)[i];
  __nv_bfloat16 h0 = __float2bfloat16_rn(v.x), h1 = __float2bfloat16_rn(v.y);
  __nv_bfloat16 h2 = __float2bfloat16_rn(v.z), h3 = __float2bfloat16_rn(v.w);
  __nv_bfloat16 l0 = __float2bfloat16_rn(v.x - __bfloat162float(h0));
  __nv_bfloat16 l1 = __float2bfloat16_rn(v.y - __bfloat162float(h1));
  __nv_bfloat16 l2 = __float2bfloat16_rn(v.z - __bfloat162float(h2));
  __nv_bfloat16 l3 = __float2bfloat16_rn(v.w - __bfloat162float(h3));
  uint2 ph, pl;
  ph.x = ((uint32_t)__bfloat16_as_ushort(h1) << 16) | __bfloat16_as_ushort(h0);
  ph.y = ((uint32_t)__bfloat16_as_ushort(h3) << 16) | __bfloat16_as_ushort(h2);
  pl.x = ((uint32_t)__bfloat16_as_ushort(l1) << 16) | __bfloat16_as_ushort(l0);
  pl.y = ((uint32_t)__bfloat16_as_ushort(l3) << 16) | __bfloat16_as_ushort(l2);
  reinterpret_cast<uint2*>(hi)[i] = ph;
  reinterpret_cast<uint2*>(lo)[i] = pl;
}

// ---------------------------------------------------------------------------
// Async tile loader: 128 rows x 64 bf16 (128 B/row), SW128 swizzle, cp.async 16B
// ---------------------------------------------------------------------------
__device__ __forceinline__ void load_tile_async(uint32_t tile, const __nv_bfloat16* __restrict__ g,
                                                int row0, int rmax, int ldk, int k0, int kmax,
                                                int tid) {
#pragma unroll
  for (int t = 0; t < 4; t++) {
    int v = tid + t * 256;          // 0..1023
    int r = v >> 3;                 // tile row 0..127
    int cs = v & 7;                 // 16B segment
    int gr = row0 + r;
    int gk = k0 + cs * 8;
    uint32_t bo = ((uint32_t)r << 7) + ((uint32_t)cs << 4);
    uint32_t sw = bo ^ ((bo >> 3) & 0x70);
    uint32_t dst = tile + sw;
    if (gr < rmax && gk < kmax) {
      const void* src = g + (size_t)gr * ldk + gk;
      asm volatile("cp.async.cg.shared.global [%0], [%1], 16;" :: "r"(dst), "l"(src));
    } else {
      asm volatile("st.shared.v4.b32 [%0], {%1,%1,%1,%1};" :: "r"(dst), "r"(0u));
    }
  }
}

// ---------------------------------------------------------------------------
// bf16x3 split GEMM via mma.sync m16n8k16:
//   C[M,N] = act((Ah+Al)[M,K] @ (Bh+Bl)[N,K]^T + bias)  ~=  AhBh + AlBh + AhBl
// 128x128 CTA, BK=64, double-buffered cp.async. 8 warps, 64x32 per warp.
// ---------------------------------------------------------------------------
template <bool LRELU, bool SPLIT>
__global__ __launch_bounds__(256, 1)
void mma_gemm(const __nv_bfloat16* __restrict__ Ah, const __nv_bfloat16* __restrict__ Al,
              const __nv_bfloat16* __restrict__ Bh, const __nv_bfloat16* __restrict__ Bl,
              const float* __restrict__ bias, float* __restrict__ Cf,
              __nv_bfloat16* __restrict__ Ch, __nv_bfloat16* __restrict__ Cl,
              int M, int N, int K) {
  extern __shared__ char smem[];
  const uint32_t sb = smem_u32(smem);
  const int tid = threadIdx.x, wid = tid >> 5, lane = tid & 31;
  const int m0 = blockIdx.y * 128, n0 = blockIdx.x * 128;
  const int warp_m = wid & 1;    // 0..1 -> 64-row groups
  const int warp_n = wid >> 1;   // 0..3 -> 32-col groups

  // Stage layout: stage*65536 + {Ah:0, Al:16384, Bh:32768, Bl:49152}
  const int NC = (K + 63) / 64;

  float acc[4][4][4];
#pragma unroll
  for (int mt = 0; mt < 4; mt++)
#pragma unroll
    for (int nt = 0; nt < 4; nt++)
#pragma unroll
      for (int i = 0; i < 4; i++) acc[mt][nt][i] = 0.f;

  // Prologue: load stage 0
  {
    uint32_t tb = sb;
    load_tile_async(tb + 0,     Ah, m0, M, K, 0, K, tid);
    load_tile_async(tb + 16384, Al, m0, M, K, 0, K, tid);
    load_tile_async(tb + 32768, Bh, n0, N, K, 0, K, tid);
    load_tile_async(tb + 49152, Bl, n0, N, K, 0, K, tid);
    CP_COMMIT();
  }

  // Per-lane ldmatrix address components (row/segment within tile)
  const int a_r = (lane & 15);               // A: rows m+0..15
  const uint32_t a_koff = (lane & 16) ? 16u : 0u;  // A: k segment select
  const int b_r = ((lane & 16) ? 8 : 0) + (lane & 7);  // B: rows n+{0..7|8..15}
  const uint32_t b_koff = (lane & 8) ? 16u : 0u;

  for (int c = 0; c < NC; c++) {
    if (c + 1 < NC) {
      uint32_t tb = sb + ((c + 1) & 1) * 65536;
      int k0 = (c + 1) * 64;
      load_tile_async(tb + 0,     Ah, m0, M, K, k0, K, tid);
      load_tile_async(tb + 16384, Al, m0, M, K, k0, K, tid);
      load_tile_async(tb + 32768, Bh, n0, N, K, k0, K, tid);
      load_tile_async(tb + 49152, Bl, n0, N, K, k0, K, tid);
      CP_COMMIT();
      CP_WAIT(1);
    } else {
      CP_WAIT(0);
    }
    __syncthreads();

    const uint32_t tb = sb + (c & 1) * 65536;
#pragma unroll
    for (int ks = 0; ks < 4; ks++) {
      const uint32_t kb = ks * 32;
      uint32_t ah[4][4], al[4][4], bh[8], bl[8];
#pragma unroll
      for (int mt = 0; mt < 4; mt++) {
        uint32_t bo = ((uint32_t)(warp_m * 64 + mt * 16 + a_r) << 7) + kb + a_koff;
        uint32_t sw = bo ^ ((bo >> 3) & 0x70);
        ldsm4(ah[mt], tb + sw);
        ldsm4(al[mt], tb + 16384 + sw);
      }
#pragma unroll
      for (int g2 = 0; g2 < 2; g2++) {
        uint32_t bo = ((uint32_t)(warp_n * 32 + g2 * 16 + b_r) << 7) + kb + b_koff;
        uint32_t sw = bo ^ ((bo >> 3) & 0x70);
        ldsm4(bh + g2 * 4, tb + 32768 + sw);
        ldsm4(bl + g2 * 4, tb + 49152 + sw);
      }
#pragma unroll
      for (int mt = 0; mt < 4; mt++)
#pragma unroll
        for (int nt = 0; nt < 4; nt++) {
          mma16816(acc[mt][nt], ah[mt], bh + nt * 2);
          mma16816(acc[mt][nt], al[mt], bh + nt * 2);
          mma16816(acc[mt][nt], ah[mt], bl + nt * 2);
        }
    }
    __syncthreads();
  }

  // Epilogue: bias + optional lrelu, write fp32 or bf16 hi/lo split
#pragma unroll
  for (int mt = 0; mt < 4; mt++) {
#pragma unroll
    for (int nt = 0; nt < 4; nt++) {
#pragma unroll
      for (int i = 0; i < 4; i++) {
        int row = m0 + warp_m * 64 + mt * 16 + (lane >> 2) + ((i & 2) ? 8 : 0);
        int col = n0 + warp_n * 32 + nt * 8 + ((lane & 3) << 1) + (i & 1);
        if (col < N) {
          float v = acc[mt][nt][i] + bias[col];
          if (LRELU) v = (v > 0.f) ? v : 0.1f * v;
          if (SPLIT) {
            __nv_bfloat16 h = __float2bfloat16_rn(v);
            Ch[(size_t)row * N + col] = h;
            Cl[(size_t)row * N + col] = __float2bfloat16_rn(v - __bfloat162float(h));
          } else {
            Cf[(size_t)row * N + col] = v;
          }
        }
      }
    }
  }
}

// ---------------------------------------------------------------------------
// Setup: S = I + 0.5 * W W^T (30x30), invert via Gauss-Jordan.
// ---------------------------------------------------------------------------
__global__ void setup_sinv(const float* __restrict__ W, float* __restrict__ Sinv) {
  __shared__ float aug[KDIM][64];
  __shared__ float fac[KDIM];
  __shared__ float pivinv;
  const int tid = threadIdx.x;  // 256 threads

  for (int idx = tid; idx < KDIM * KDIM; idx += 256) {
    int a = idx / KDIM, b = idx % KDIM;
    float s = 0.f;
    for (int j = 0; j < RDIM; j++) s += W[a * RDIM + j] * W[b * RDIM + j];
    aug[a][b] = 0.5f * s + (a == b ? 1.f : 0.f);
  }
  for (int idx = tid; idx < KDIM * 34; idx += 256) {
    int a = idx / 34, c = 30 + idx % 34;
    aug[a][c] = (c - 30 == a) ? 1.f : 0.f;
  }
  __syncthreads();

  for (int i = 0; i < KDIM; i++) {
    if (tid == 0) pivinv = 1.f / aug[i][i];
    __syncthreads();
    if (tid < 64) aug[i][tid] *= pivinv;
    __syncthreads();
    if (tid < KDIM) fac[tid] = aug[tid][i];
    __syncthreads();
    for (int idx = tid; idx < KDIM * 64; idx += 256) {
      int r = idx / 64, c = idx % 64;
      if (r != i) aug[r][c] -= fac[r] * aug[i][c];
    }
    __syncthreads();
  }
  for (int idx = tid; idx < KDIM * KDIM; idx += 256)
    Sinv[idx] = aug[idx / KDIM][30 + idx % KDIM];
}

// ---------------------------------------------------------------------------
// Persistent ADMM kernel (unchanged from R2 passing version).
// ---------------------------------------------------------------------------
#define AROWS 4
#define PADR 512

__global__ __launch_bounds__(256, 2)
void admm_kernel(const float* __restrict__ cost, const float* __restrict__ W,
                 const float* __restrict__ cap, const float* __restrict__ SinvG,
                 float* __restrict__ out) {
  extern __shared__ float sm[];
  float* Ws   = sm;
  float* cst  = Ws + KDIM * PADR;
  float* vr   = cst + AROWS * PADR;
  float* rh   = vr + AROWS * PADR;
  float* pr   = rh + AROWS * PADR;
  float* ps   = pr + AROWS * PADR;
  float* pk   = ps + AROWS * PADR;
  float* gk   = pk + AROWS * 32;
  float* ck   = gk + AROWS * 32;
  float* y1s  = ck + AROWS * 32;
  float* ts   = y1s + AROWS * 32;
  float* Ssm  = ts + AROWS * 32;
  float* cap2 = Ssm + KDIM * 33;

  const int tid = threadIdx.x;
  const int lane = tid & 31;
  const int wid = tid >> 5;
  const int row0 = blockIdx.x * AROWS;

  for (int idx = tid; idx < KDIM * PADR; idx += 256) {
    int k = idx >> 9, j = idx & (PADR - 1);
    Ws[idx] = (j < RDIM) ? W[k * RDIM + j] : 0.f;
  }
  for (int idx = tid; idx < AROWS * PADR; idx += 256) {
    int r = idx >> 9, j = idx & (PADR - 1);
    cst[idx] = (j < RDIM) ? cost[(size_t)(row0 + r) * RDIM + j] : 0.f;
    vr[idx] = 0.f; rh[idx] = 0.f; pr[idx] = 0.f; ps[idx] = 0.f;
  }
  if (tid < 32) cap2[tid] = (tid < KDIM) ? 2.f * cap[tid] : 0.f;
  for (int idx = tid; idx < KDIM * 33; idx += 256) {
    int k = idx / 33, m = idx % 33;
    Ssm[idx] = (m < KDIM) ? SinvG[k * KDIM + m] : 0.f;
  }
  if (tid < AROWS * 32) { pk[tid] = 0.f; gk[tid] = 0.f; ck[tid] = 0.f; y1s[tid] = 0.f; ts[tid] = 0.f; }
  __syncthreads();

  const int j0 = tid;
  const int j1 = tid + 256;
  float Wr0[KDIM], Wr1[KDIM];
#pragma unroll
  for (int k = 0; k < KDIM; k++) {
    Wr0[k] = Ws[k * PADR + j0];
    Wr1[k] = Ws[k * PADR + j1];
  }

  const int r_w = wid & 3;
  const int half = wid >> 2;

  for (int it = 0; it < NITER; it++) {
#pragma unroll
    for (int r = 0; r < AROWS; r++) {
      {
        float prv = pr[r * PADR + j0], psv = ps[r * PADR + j0];
        float v = cst[r * PADR + j0] + fabsf(prv);
        vr[r * PADR + j0] = v;
        rh[r * PADR + j0] = v + fabsf(psv) - 2.f;
      }
      if (j1 < RDIM) {
        float prv = pr[r * PADR + j1], psv = ps[r * PADR + j1];
        float v = cst[r * PADR + j1] + fabsf(prv);
        vr[r * PADR + j1] = v;
        rh[r * PADR + j1] = v + fabsf(psv) - 2.f;
      }
    }
    __syncthreads();

    {
      float vreg[16], rreg[16];
#pragma unroll
      for (int m = 0; m < 16; m++) {
        vreg[m] = vr[r_w * PADR + lane + 32 * m];
        rreg[m] = rh[r_w * PADR + lane + 32 * m];
      }
      for (int kk = 0; kk < 15; kk++) {
        int k = half * 15 + kk;
        float ag = 0.f, ac = 0.f;
#pragma unroll
        for (int m = 0; m < 16; m++) {
          float w = Ws[k * PADR + lane + 32 * m];
          ag += w * vreg[m];
          ac += w * rreg[m];
        }
#pragma unroll
        for (int o = 16; o > 0; o >>= 1) {
          ag += __shfl_down_sync(0xffffffffu, ag, o);
          ac += __shfl_down_sync(0xffffffffu, ac, o);
        }
        if (lane == 0) { gk[r_w * 32 + k] = ag; ck[r_w * 32 + k] = ac; }
      }
    }
    __syncthreads();

    if (wid < AROWS) {
      const int r = wid;
      float pkv = 0.f;
      if (lane < KDIM) {
        pkv = pk[r * 32 + lane];
        float rhs1 = gk[r * 32 + lane] + fabsf(pkv) - cap2[lane];
        ts[r * 32 + lane] = rhs1 - 0.5f * ck[r * 32 + lane];
      }
      __syncwarp(0xffffffffu);
      if (lane < KDIM) {
        float y = 0.f;
#pragma unroll
        for (int m = 0; m < KDIM; m++) y += Ssm[lane * 33 + m] * ts[r * 32 + m];
        y1s[r * 32 + lane] = y;
        float xk = 0.5f * (fabsf(pkv) - y);
        pk[r * 32 + lane] = xk + fminf(pkv, 0.f);
        if (it == NITER - 1)
          out[(size_t)(row0 + r) * N2_DIM + RDIM + lane] = xk;
      }
    }
    __syncthreads();

#pragma unroll
    for (int r = 0; r < AROWS; r++) {
      float wt0 = 0.f, wt1 = 0.f;
#pragma unroll
      for (int k = 0; k < KDIM; k++) {
        float y = y1s[r * 32 + k];
        wt0 += Wr0[k] * y;
        wt1 += Wr1[k] * y;
      }
      {
        float v = vr[r * PADR + j0], rr = rh[r * PADR + j0];
        float prv = pr[r * PADR + j0], psv = ps[r * PADR + j0];
        float xr = 0.5f * v - 0.25f * (wt0 + rr);
        float xs = 0.5f * fabsf(psv) + 0.25f * (wt0 - rr);
        pr[r * PADR + j0] = xr + fminf(prv, 0.f);
        ps[r * PADR + j0] = xs + fminf(psv, 0.f);
        if (it == NITER - 1) {
          out[(size_t)(row0 + r) * N2_DIM + j0] = xr;
          out[(size_t)(row0 + r) * N2_DIM + RDIM + KDIM + j0] = xs;
        }
      }
      if (j1 < RDIM) {
        float v = vr[r * PADR + j1], rr = rh[r * PADR + j1];
        float prv = pr[r * PADR + j1], psv = ps[r * PADR + j1];
        float xr = 0.5f * v - 0.25f * (wt1 + rr);
        float xs = 0.5f * fabsf(psv) + 0.25f * (wt1 - rr);
        pr[r * PADR + j1] = xr + fminf(prv, 0.f);
        ps[r * PADR + j1] = xs + fminf(psv, 0.f);
        if (it == NITER - 1) {
          out[(size_t)(row0 + r) * N2_DIM + j1] = xr;
          out[(size_t)(row0 + r) * N2_DIM + RDIM + KDIM + j1] = xs;
        }
      }
    }
    __syncthreads();
  }
}

// ---------------------------------------------------------------------------
extern "C" void kernel_launch(void* const* d_in, const int* in_sizes, int n_in,
                              void* d_out, int out_size) {
  const float* d   = (const float*)d_in[0];  // [1024,32]
  const float* W1  = (const float*)d_in[1];  // [3200,32]
  const float* b1  = (const float*)d_in[2];  // [3200]
  const float* W2  = (const float*)d_in[3];  // [3200,3200]
  const float* b2  = (const float*)d_in[4];  // [3200]
  const float* W3  = (const float*)d_in[5];  // [500,3200]
  const float* b3  = (const float*)d_in[6];  // [500]
  const float* Wm  = (const float*)d_in[7];  // [30,500]
  const float* cap = (const float*)d_in[8];  // [30]
  float* out = (float*)d_out;                // [1024,1030]

  __nv_bfloat16 *dh, *dl, *w1h, *w1l, *w2h, *w2l, *w3h, *w3l, *h1h, *h1l, *h2h, *h2l;
  float *cost, *sinv;
  cudaGetSymbolAddress((void**)&dh, g_dh);   cudaGetSymbolAddress((void**)&dl, g_dl);
  cudaGetSymbolAddress((void**)&w1h, g_W1h); cudaGetSymbolAddress((void**)&w1l, g_W1l);
  cudaGetSymbolAddress((void**)&w2h, g_W2h); cudaGetSymbolAddress((void**)&w2l, g_W2l);
  cudaGetSymbolAddress((void**)&w3h, g_W3h); cudaGetSymbolAddress((void**)&w3l, g_W3l);
  cudaGetSymbolAddress((void**)&h1h, g_h1h); cudaGetSymbolAddress((void**)&h1l, g_h1l);
  cudaGetSymbolAddress((void**)&h2h, g_h2h); cudaGetSymbolAddress((void**)&h2l, g_h2l);
  cudaGetSymbolAddress((void**)&cost, g_cost);
  cudaGetSymbolAddress((void**)&sinv, g_Sinv);

  // Split inputs into bf16 hi/lo
  cvt_split4<<<(BDIM * CDIM / 4 + 255) / 256, 256>>>(d, dh, dl, BDIM * CDIM / 4);
  cvt_split4<<<(HDIM * CDIM / 4 + 255) / 256, 256>>>(W1, w1h, w1l, HDIM * CDIM / 4);
  cvt_split4<<<(HDIM * HDIM / 4 + 255) / 256, 256>>>(W2, w2h, w2l, HDIM * HDIM / 4);
  cvt_split4<<<(RDIM * HDIM / 4 + 255) / 256, 256>>>(W3, w3h, w3l, RDIM * HDIM / 4);

  setup_sinv<<<1, 256>>>(Wm, sinv);

  const int gemm_smem = 2 * 65536;  // 131072 B
  cudaFuncSetAttribute(mma_gemm<true, true>, cudaFuncAttributeMaxDynamicSharedMemorySize, gemm_smem);
  cudaFuncSetAttribute(mma_gemm<false, false>, cudaFuncAttributeMaxDynamicSharedMemorySize, gemm_smem);

  // MLP on tensor cores (bf16x3 split via mma.sync)
  mma_gemm<true, true><<<dim3(HDIM / 128, BDIM / 128), 256, gemm_smem>>>(
      dh, dl, w1h, w1l, b1, nullptr, h1h, h1l, BDIM, HDIM, CDIM);
  mma_gemm<true, true><<<dim3(HDIM / 128, BDIM / 128), 256, gemm_smem>>>(
      h1h, h1l, w2h, w2l, b2, nullptr, h2h, h2l, BDIM, HDIM, HDIM);
  mma_gemm<false, false><<<dim3((RDIM + 127) / 128, BDIM / 128), 256, gemm_smem>>>(
      h2h, h2l, w3h, w3l, b3, cost, nullptr, nullptr, BDIM, RDIM, HDIM);

  // ADMM (persistent, 4 rows/block)
  const int admm_smem = (KDIM * PADR + 5 * AROWS * PADR + 5 * AROWS * 32 + KDIM * 33 + 32) * (int)sizeof(float);
  cudaFuncSetAttribute(admm_kernel, cudaFuncAttributeMaxDynamicSharedMemorySize, admm_smem);
  admm_kernel<<<BDIM / AROWS, 256, admm_smem>>>(cost, Wm, cap, sinv, out);
}

// round 6
// speedup vs baseline: 1.8809x; 1.0741x over previous
#include <cuda_runtime.h>
#include <cuda_bf16.h>
#include <cstdint>

// Problem constants
#define CDIM 32
#define HDIM 3200
#define BDIM 1024
#define RDIM 500
#define KDIM 30
#define N2_DIM 1030
#define NITER 200
#define KSPLIT 4
#define PSTRIDE 512

// ---------------------------------------------------------------------------
// Device-global scratch (no allocation allowed)
// ---------------------------------------------------------------------------
__device__ __nv_bfloat16 g_dh[BDIM * CDIM],  g_dl[BDIM * CDIM];
__device__ __nv_bfloat16 g_W1h[HDIM * CDIM], g_W1l[HDIM * CDIM];
__device__ __nv_bfloat16 g_W2h[HDIM * HDIM], g_W2l[HDIM * HDIM];
__device__ __nv_bfloat16 g_W3h[RDIM * HDIM], g_W3l[RDIM * HDIM];
__device__ __nv_bfloat16 g_h1h[BDIM * HDIM], g_h1l[BDIM * HDIM];
__device__ __nv_bfloat16 g_h2h[BDIM * HDIM], g_h2l[BDIM * HDIM];
__device__ float g_costP[KSPLIT * BDIM * PSTRIDE];
__device__ float g_cost[BDIM * RDIM];
__device__ float g_Sinv[KDIM * KDIM];

// ---------------------------------------------------------------------------
// PTX helpers (plain sm_80+/sm_90 features only — no arch-'a' gated instrs)
// ---------------------------------------------------------------------------
__device__ __forceinline__ uint32_t smem_u32(const void* p) {
  uint32_t a;
  asm("{ .reg .u64 t; cvta.to.shared.u64 t, %1; cvt.u32.u64 %0, t; }" : "=r"(a) : "l"(p));
  return a;
}
__device__ __forceinline__ void ldsm4(uint32_t* r, uint32_t a) {
  asm volatile("ldmatrix.sync.aligned.m8n8.x4.shared.b16 {%0,%1,%2,%3}, [%4];"
               : "=r"(r[0]), "=r"(r[1]), "=r"(r[2]), "=r"(r[3]) : "r"(a));
}
__device__ __forceinline__ void mma16816(float* c, const uint32_t* a, const uint32_t* b) {
  asm volatile(
      "mma.sync.aligned.m16n8k16.row.col.f32.bf16.bf16.f32 "
      "{%0,%1,%2,%3}, {%4,%5,%6,%7}, {%8,%9}, {%0,%1,%2,%3};"
      : "+f"(c[0]), "+f"(c[1]), "+f"(c[2]), "+f"(c[3])
      : "r"(a[0]), "r"(a[1]), "r"(a[2]), "r"(a[3]), "r"(b[0]), "r"(b[1]));
}
#define CP_COMMIT() asm volatile("cp.async.commit_group;" ::: "memory")
#define CP_WAIT(n)  asm volatile("cp.async.wait_group %0;" :: "n"(n) : "memory")

// SW64 swizzle for 64-byte rows (conflict-free ldmatrix over 8-row atoms)
__device__ __forceinline__ uint32_t sw64(uint32_t bo) { return bo ^ ((bo >> 3) & 0x30); }

// ---------------------------------------------------------------------------
// fp32 -> (bf16 hi, bf16 lo) split, 4-wide
// ---------------------------------------------------------------------------
__global__ void cvt_split4(const float* __restrict__ in, __nv_bfloat16* __restrict__ hi,
                           __nv_bfloat16* __restrict__ lo, int n4) {
  int i = blockIdx.x * 256 + threadIdx.x;
  if (i >= n4) return;
  float4 v = reinterpret_cast<const float4*>(in)[i];
  __nv_bfloat16 h0 = __float2bfloat16_rn(v.x), h1 = __float2bfloat16_rn(v.y);
  __nv_bfloat16 h2 = __float2bfloat16_rn(v.z), h3 = __float2bfloat16_rn(v.w);
  __nv_bfloat16 l0 = __float2bfloat16_rn(v.x - __bfloat162float(h0));
  __nv_bfloat16 l1 = __float2bfloat16_rn(v.y - __bfloat162float(h1));
  __nv_bfloat16 l2 = __float2bfloat16_rn(v.z - __bfloat162float(h2));
  __nv_bfloat16 l3 = __float2bfloat16_rn(v.w - __bfloat162float(h3));
  uint2 ph, pl;
  ph.x = ((uint32_t)__bfloat16_as_ushort(h1) << 16) | __bfloat16_as_ushort(h0);
  ph.y = ((uint32_t)__bfloat16_as_ushort(h3) << 16) | __bfloat16_as_ushort(h2);
  pl.x = ((uint32_t)__bfloat16_as_ushort(l1) << 16) | __bfloat16_as_ushort(l0);
  pl.y = ((uint32_t)__bfloat16_as_ushort(l3) << 16) | __bfloat16_as_ushort(l2);
  reinterpret_cast<uint2*>(hi)[i] = ph;
  reinterpret_cast<uint2*>(lo)[i] = pl;
}

// ---------------------------------------------------------------------------
// Async tile loader: 128 rows x 32 bf16 (64 B/row), SW64 swizzle, cp.async 16B
// 8 KB per array; 2 vectors per thread (256 threads).
// ---------------------------------------------------------------------------
__device__ __forceinline__ void load_tile_async(uint32_t tile, const __nv_bfloat16* __restrict__ g,
                                                int row0, int rmax, int ldk, int k0, int kend,
                                                int tid) {
#pragma unroll
  for (int t = 0; t < 2; t++) {
    int v = tid + t * 256;          // 0..511
    int r = v >> 2;                 // tile row 0..127
    int cs = v & 3;                 // 16B segment (4 per 64B row)
    int gr = row0 + r;
    int gk = k0 + cs * 8;
    uint32_t dst = tile + sw64(((uint32_t)r << 6) + ((uint32_t)cs << 4));
    if (gr < rmax && gk < kend) {
      const void* src = g + (size_t)gr * ldk + gk;
      asm volatile("cp.async.cg.shared.global [%0], [%1], 16;" :: "r"(dst), "l"(src));
    } else {
      asm volatile("st.shared.v4.b32 [%0], {%1,%1,%1,%1};" :: "r"(dst), "r"(0u));
    }
  }
}

// ---------------------------------------------------------------------------
// bf16x3 split GEMM via mma.sync m16n8k16:
//   C = act((Ah+Al)[M,K] @ (Bh+Bl)[N,K]^T + bias) ~= AhBh + AlBh + AhBl
// 128x128 CTA, BK=32, 3-stage cp.async, 2 CTAs/SM. 8 warps, 64x32 per warp.
// MODE 0: full-K, bias + lrelu, emit bf16 hi/lo (packed bf162 stores).
// MODE 1: split-K partial, raw fp32 accum to part buffer (stride PSTRIDE).
// ---------------------------------------------------------------------------
#define STAGE_B 32768  // 4 arrays x 8KB

template <int MODE>
__global__ __launch_bounds__(256, 2)
void mma_gemm(const __nv_bfloat16* __restrict__ Ah, const __nv_bfloat16* __restrict__ Al,
              const __nv_bfloat16* __restrict__ Bh, const __nv_bfloat16* __restrict__ Bl,
              const float* __restrict__ bias, float* __restrict__ Pf,
              __nv_bfloat16* __restrict__ Ch, __nv_bfloat16* __restrict__ Cl,
              int M, int N, int K, int kchunk) {
  extern __shared__ char smem[];
  const uint32_t sb = smem_u32(smem);
  const int tid = threadIdx.x, wid = tid >> 5, lane = tid & 31;
  const int m0 = blockIdx.y * 128, n0 = blockIdx.x * 128;
  const int warp_m = wid & 1;    // 0..1 -> 64-row groups
  const int warp_n = wid >> 1;   // 0..3 -> 32-col groups

  const int kbeg = (MODE == 1) ? blockIdx.z * kchunk : 0;
  const int kend = (kbeg + kchunk < K) ? (kbeg + kchunk) : K;
  const int NC = (kend - kbeg + 31) / 32;

  float acc[4][4][4];
#pragma unroll
  for (int mt = 0; mt < 4; mt++)
#pragma unroll
    for (int nt = 0; nt < 4; nt++)
#pragma unroll
      for (int i = 0; i < 4; i++) acc[mt][nt][i] = 0.f;

  // Prologue: stages 0,1
#pragma unroll
  for (int s = 0; s < 2; s++) {
    uint32_t tb = sb + s * STAGE_B;
    int k0 = kbeg + s * 32;
    load_tile_async(tb + 0,     Ah, m0, M, K, k0, kend, tid);
    load_tile_async(tb + 8192,  Al, m0, M, K, k0, kend, tid);
    load_tile_async(tb + 16384, Bh, n0, N, K, k0, kend, tid);
    load_tile_async(tb + 24576, Bl, n0, N, K, k0, kend, tid);
    CP_COMMIT();
  }

  // Per-lane ldmatrix row/segment components
  const int a_r = (lane & 15);
  const uint32_t a_koff = (lane & 16) ? 16u : 0u;
  const int b_r = ((lane & 16) ? 8 : 0) + (lane & 7);
  const uint32_t b_koff = (lane & 8) ? 16u : 0u;

  for (int c = 0; c < NC; c++) {
    if (c + 2 < NC) {
      uint32_t tb = sb + ((c + 2) % 3) * STAGE_B;
      int k0 = kbeg + (c + 2) * 32;
      load_tile_async(tb + 0,     Ah, m0, M, K, k0, kend, tid);
      load_tile_async(tb + 8192,  Al, m0, M, K, k0, kend, tid);
      load_tile_async(tb + 16384, Bh, n0, N, K, k0, kend, tid);
      load_tile_async(tb + 24576, Bl, n0, N, K, k0, kend, tid);
      CP_COMMIT();
      CP_WAIT(2);
    } else if (c + 1 < NC) {
      CP_WAIT(1);
    } else {
      CP_WAIT(0);
    }
    __syncthreads();

    const uint32_t tb = sb + (c % 3) * STAGE_B;
#pragma unroll
    for (int ks = 0; ks < 2; ks++) {
      const uint32_t kb = ks * 32;
      uint32_t bh[8], bl[8];
#pragma unroll
      for (int g2 = 0; g2 < 2; g2++) {
        uint32_t sw = sw64(((uint32_t)(warp_n * 32 + g2 * 16 + b_r) << 6) + kb + b_koff);
        ldsm4(bh + g2 * 4, tb + 16384 + sw);
        ldsm4(bl + g2 * 4, tb + 24576 + sw);
      }
#pragma unroll
      for (int mt = 0; mt < 4; mt++) {
        uint32_t ah[4], al[4];
        uint32_t sw = sw64(((uint32_t)(warp_m * 64 + mt * 16 + a_r) << 6) + kb + a_koff);
        ldsm4(ah, tb + sw);
        ldsm4(al, tb + 8192 + sw);
#pragma unroll
        for (int nt = 0; nt < 4; nt++) {
          mma16816(acc[mt][nt], ah, bh + nt * 2);
          mma16816(acc[mt][nt], al, bh + nt * 2);
          mma16816(acc[mt][nt], ah, bl + nt * 2);
        }
      }
    }
    __syncthreads();
  }

  // Epilogue
#pragma unroll
  for (int mt = 0; mt < 4; mt++) {
#pragma unroll
    for (int nt = 0; nt < 4; nt++) {
      const int col = n0 + warp_n * 32 + nt * 8 + ((lane & 3) << 1);
      const int r0 = m0 + warp_m * 64 + mt * 16 + (lane >> 2);
#pragma unroll
      for (int h = 0; h < 2; h++) {  // h: row-half (i&2)
        const int row = r0 + h * 8;
        float v0 = acc[mt][nt][h * 2 + 0];
        float v1 = acc[mt][nt][h * 2 + 1];
        if (MODE == 0) {
          v0 += bias[col];
          v1 += bias[col + 1];
          v0 = (v0 > 0.f) ? v0 : 0.1f * v0;
          v1 = (v1 > 0.f) ? v1 : 0.1f * v1;
          __nv_bfloat16 h0 = __float2bfloat16_rn(v0), h1 = __float2bfloat16_rn(v1);
          __nv_bfloat16 l0 = __float2bfloat16_rn(v0 - __bfloat162float(h0));
          __nv_bfloat16 l1 = __float2bfloat16_rn(v1 - __bfloat162float(h1));
          uint32_t ph = ((uint32_t)__bfloat16_as_ushort(h1) << 16) | __bfloat16_as_ushort(h0);
          uint32_t pl = ((uint32_t)__bfloat16_as_ushort(l1) << 16) | __bfloat16_as_ushort(l0);
          *reinterpret_cast<uint32_t*>(Ch + (size_t)row * N + col) = ph;
          *reinterpret_cast<uint32_t*>(Cl + (size_t)row * N + col) = pl;
        } else {
          float* dst = Pf + (size_t)blockIdx.z * BDIM * PSTRIDE + (size_t)row * PSTRIDE + col;
          *reinterpret_cast<float2*>(dst) = make_float2(v0, v1);
        }
      }
    }
  }
}

// ---------------------------------------------------------------------------
// Reduce split-K partials + bias -> cost [1024, 500]
// ---------------------------------------------------------------------------
__global__ void reduce_cost(const float* __restrict__ Pf, const float* __restrict__ bias,
                            float* __restrict__ cost) {
  int i = blockIdx.x * 256 + threadIdx.x;
  if (i >= BDIM * RDIM) return;
  int r = i / RDIM, n = i % RDIM;
  float s = bias[n];
#pragma unroll
  for (int z = 0; z < KSPLIT; z++)
    s += Pf[(size_t)z * BDIM * PSTRIDE + (size_t)r * PSTRIDE + n];
  cost[i] = s;
}

// ---------------------------------------------------------------------------
// Setup: S = I + 0.5 * W W^T (30x30), invert via Gauss-Jordan.
// ---------------------------------------------------------------------------
__global__ void setup_sinv(const float* __restrict__ W, float* __restrict__ Sinv) {
  __shared__ float aug[KDIM][64];
  __shared__ float fac[KDIM];
  __shared__ float pivinv;
  const int tid = threadIdx.x;  // 256 threads

  for (int idx = tid; idx < KDIM * KDIM; idx += 256) {
    int a = idx / KDIM, b = idx % KDIM;
    float s = 0.f;
    for (int j = 0; j < RDIM; j++) s += W[a * RDIM + j] * W[b * RDIM + j];
    aug[a][b] = 0.5f * s + (a == b ? 1.f : 0.f);
  }
  for (int idx = tid; idx < KDIM * 34; idx += 256) {
    int a = idx / 34, c = 30 + idx % 34;
    aug[a][c] = (c - 30 == a) ? 1.f : 0.f;
  }
  __syncthreads();

  for (int i = 0; i < KDIM; i++) {
    if (tid == 0) pivinv = 1.f / aug[i][i];
    __syncthreads();
    if (tid < 64) aug[i][tid] *= pivinv;
    __syncthreads();
    if (tid < KDIM) fac[tid] = aug[tid][i];
    __syncthreads();
    for (int idx = tid; idx < KDIM * 64; idx += 256) {
      int r = idx / 64, c = idx % 64;
      if (r != i) aug[r][c] -= fac[r] * aug[i][c];
    }
    __syncthreads();
  }
  for (int idx = tid; idx < KDIM * KDIM; idx += 256)
    Sinv[idx] = aug[idx / KDIM][30 + idx % KDIM];
}

// ---------------------------------------------------------------------------
// Persistent ADMM kernel (unchanged from R5 passing version).
// ---------------------------------------------------------------------------
#define AROWS 4
#define PADR 512

__global__ __launch_bounds__(256, 2)
void admm_kernel(const float* __restrict__ cost, const float* __restrict__ W,
                 const float* __restrict__ cap, const float* __restrict__ SinvG,
                 float* __restrict__ out) {
  extern __shared__ float sm[];
  float* Ws   = sm;
  float* cst  = Ws + KDIM * PADR;
  float* vr   = cst + AROWS * PADR;
  float* rh   = vr + AROWS * PADR;
  float* pr   = rh + AROWS * PADR;
  float* ps   = pr + AROWS * PADR;
  float* pk   = ps + AROWS * PADR;
  float* gk   = pk + AROWS * 32;
  float* ck   = gk + AROWS * 32;
  float* y1s  = ck + AROWS * 32;
  float* ts   = y1s + AROWS * 32;
  float* Ssm  = ts + AROWS * 32;
  float* cap2 = Ssm + KDIM * 33;

  const int tid = threadIdx.x;
  const int lane = tid & 31;
  const int wid = tid >> 5;
  const int row0 = blockIdx.x * AROWS;

  for (int idx = tid; idx < KDIM * PADR; idx += 256) {
    int k = idx >> 9, j = idx & (PADR - 1);
    Ws[idx] = (j < RDIM) ? W[k * RDIM + j] : 0.f;
  }
  for (int idx = tid; idx < AROWS * PADR; idx += 256) {
    int r = idx >> 9, j = idx & (PADR - 1);
    cst[idx] = (j < RDIM) ? cost[(size_t)(row0 + r) * RDIM + j] : 0.f;
    vr[idx] = 0.f; rh[idx] = 0.f; pr[idx] = 0.f; ps[idx] = 0.f;
  }
  if (tid < 32) cap2[tid] = (tid < KDIM) ? 2.f * cap[tid] : 0.f;
  for (int idx = tid; idx < KDIM * 33; idx += 256) {
    int k = idx / 33, m = idx % 33;
    Ssm[idx] = (m < KDIM) ? SinvG[k * KDIM + m] : 0.f;
  }
  if (tid < AROWS * 32) { pk[tid] = 0.f; gk[tid] = 0.f; ck[tid] = 0.f; y1s[tid] = 0.f; ts[tid] = 0.f; }
  __syncthreads();

  const int j0 = tid;
  const int j1 = tid + 256;
  float Wr0[KDIM], Wr1[KDIM];
#pragma unroll
  for (int k = 0; k < KDIM; k++) {
    Wr0[k] = Ws[k * PADR + j0];
    Wr1[k] = Ws[k * PADR + j1];
  }

  const int r_w = wid & 3;
  const int half = wid >> 2;

  for (int it = 0; it < NITER; it++) {
#pragma unroll
    for (int r = 0; r < AROWS; r++) {
      {
        float prv = pr[r * PADR + j0], psv = ps[r * PADR + j0];
        float v = cst[r * PADR + j0] + fabsf(prv);
        vr[r * PADR + j0] = v;
        rh[r * PADR + j0] = v + fabsf(psv) - 2.f;
      }
      if (j1 < RDIM) {
        float prv = pr[r * PADR + j1], psv = ps[r * PADR + j1];
        float v = cst[r * PADR + j1] + fabsf(prv);
        vr[r * PADR + j1] = v;
        rh[r * PADR + j1] = v + fabsf(psv) - 2.f;
      }
    }
    __syncthreads();

    {
      float vreg[16], rreg[16];
#pragma unroll
      for (int m = 0; m < 16; m++) {
        vreg[m] = vr[r_w * PADR + lane + 32 * m];
        rreg[m] = rh[r_w * PADR + lane + 32 * m];
      }
      for (int kk = 0; kk < 15; kk++) {
        int k = half * 15 + kk;
        float ag = 0.f, ac = 0.f;
#pragma unroll
        for (int m = 0; m < 16; m++) {
          float w = Ws[k * PADR + lane + 32 * m];
          ag += w * vreg[m];
          ac += w * rreg[m];
        }
#pragma unroll
        for (int o = 16; o > 0; o >>= 1) {
          ag += __shfl_down_sync(0xffffffffu, ag, o);
          ac += __shfl_down_sync(0xffffffffu, ac, o);
        }
        if (lane == 0) { gk[r_w * 32 + k] = ag; ck[r_w * 32 + k] = ac; }
      }
    }
    __syncthreads();

    if (wid < AROWS) {
      const int r = wid;
      float pkv = 0.f;
      if (lane < KDIM) {
        pkv = pk[r * 32 + lane];
        float rhs1 = gk[r * 32 + lane] + fabsf(pkv) - cap2[lane];
        ts[r * 32 + lane] = rhs1 - 0.5f * ck[r * 32 + lane];
      }
      __syncwarp(0xffffffffu);
      if (lane < KDIM) {
        float y = 0.f;
#pragma unroll
        for (int m = 0; m < KDIM; m++) y += Ssm[lane * 33 + m] * ts[r * 32 + m];
        y1s[r * 32 + lane] = y;
        float xk = 0.5f * (fabsf(pkv) - y);
        pk[r * 32 + lane] = xk + fminf(pkv, 0.f);
        if (it == NITER - 1)
          out[(size_t)(row0 + r) * N2_DIM + RDIM + lane] = xk;
      }
    }
    __syncthreads();

#pragma unroll
    for (int r = 0; r < AROWS; r++) {
      float wt0 = 0.f, wt1 = 0.f;
#pragma unroll
      for (int k = 0; k < KDIM; k++) {
        float y = y1s[r * 32 + k];
        wt0 += Wr0[k] * y;
        wt1 += Wr1[k] * y;
      }
      {
        float v = vr[r * PADR + j0], rr = rh[r * PADR + j0];
        float prv = pr[r * PADR + j0], psv = ps[r * PADR + j0];
        float xr = 0.5f * v - 0.25f * (wt0 + rr);
        float xs = 0.5f * fabsf(psv) + 0.25f * (wt0 - rr);
        pr[r * PADR + j0] = xr + fminf(prv, 0.f);
        ps[r * PADR + j0] = xs + fminf(psv, 0.f);
        if (it == NITER - 1) {
          out[(size_t)(row0 + r) * N2_DIM + j0] = xr;
          out[(size_t)(row0 + r) * N2_DIM + RDIM + KDIM + j0] = xs;
        }
      }
      if (j1 < RDIM) {
        float v = vr[r * PADR + j1], rr = rh[r * PADR + j1];
        float prv = pr[r * PADR + j1], psv = ps[r * PADR + j1];
        float xr = 0.5f * v - 0.25f * (wt1 + rr);
        float xs = 0.5f * fabsf(psv) + 0.25f * (wt1 - rr);
        pr[r * PADR + j1] = xr + fminf(prv, 0.f);
        ps[r * PADR + j1] = xs + fminf(psv, 0.f);
        if (it == NITER - 1) {
          out[(size_t)(row0 + r) * N2_DIM + j1] = xr;
          out[(size_t)(row0 + r) * N2_DIM + RDIM + KDIM + j1] = xs;
        }
      }
    }
    __syncthreads();
  }
}

// ---------------------------------------------------------------------------
extern "C" void kernel_launch(void* const* d_in, const int* in_sizes, int n_in,
                              void* d_out, int out_size) {
  const float* d   = (const float*)d_in[0];  // [1024,32]
  const float* W1  = (const float*)d_in[1];  // [3200,32]
  const float* b1  = (const float*)d_in[2];  // [3200]
  const float* W2  = (const float*)d_in[3];  // [3200,3200]
  const float* b2  = (const float*)d_in[4];  // [3200]
  const float* W3  = (const float*)d_in[5];  // [500,3200]
  const float* b3  = (const float*)d_in[6];  // [500]
  const float* Wm  = (const float*)d_in[7];  // [30,500]
  const float* cap = (const float*)d_in[8];  // [30]
  float* out = (float*)d_out;                // [1024,1030]

  __nv_bfloat16 *dh, *dl, *w1h, *w1l, *w2h, *w2l, *w3h, *w3l, *h1h, *h1l, *h2h, *h2l;
  float *cost, *costP, *sinv;
  cudaGetSymbolAddress((void**)&dh, g_dh);   cudaGetSymbolAddress((void**)&dl, g_dl);
  cudaGetSymbolAddress((void**)&w1h, g_W1h); cudaGetSymbolAddress((void**)&w1l, g_W1l);
  cudaGetSymbolAddress((void**)&w2h, g_W2h); cudaGetSymbolAddress((void**)&w2l, g_W2l);
  cudaGetSymbolAddress((void**)&w3h, g_W3h); cudaGetSymbolAddress((void**)&w3l, g_W3l);
  cudaGetSymbolAddress((void**)&h1h, g_h1h); cudaGetSymbolAddress((void**)&h1l, g_h1l);
  cudaGetSymbolAddress((void**)&h2h, g_h2h); cudaGetSymbolAddress((void**)&h2l, g_h2l);
  cudaGetSymbolAddress((void**)&cost, g_cost);
  cudaGetSymbolAddress((void**)&costP, g_costP);
  cudaGetSymbolAddress((void**)&sinv, g_Sinv);

  // Split inputs into bf16 hi/lo
  cvt_split4<<<(BDIM * CDIM / 4 + 255) / 256, 256>>>(d, dh, dl, BDIM * CDIM / 4);
  cvt_split4<<<(HDIM * CDIM / 4 + 255) / 256, 256>>>(W1, w1h, w1l, HDIM * CDIM / 4);
  cvt_split4<<<(HDIM * HDIM / 4 + 255) / 256, 256>>>(W2, w2h, w2l, HDIM * HDIM / 4);
  cvt_split4<<<(RDIM * HDIM / 4 + 255) / 256, 256>>>(W3, w3h, w3l, RDIM * HDIM / 4);

  setup_sinv<<<1, 256>>>(Wm, sinv);

  const int gemm_smem = 3 * STAGE_B;  // 98304 B
  cudaFuncSetAttribute(mma_gemm<0>, cudaFuncAttributeMaxDynamicSharedMemorySize, gemm_smem);
  cudaFuncSetAttribute(mma_gemm<1>, cudaFuncAttributeMaxDynamicSharedMemorySize, gemm_smem);

  // MLP on tensor cores (bf16x3 split via mma.sync)
  mma_gemm<0><<<dim3(HDIM / 128, BDIM / 128), 256, gemm_smem>>>(
      dh, dl, w1h, w1l, b1, nullptr, h1h, h1l, BDIM, HDIM, CDIM, CDIM);
  mma_gemm<0><<<dim3(HDIM / 128, BDIM / 128), 256, gemm_smem>>>(
      h1h, h1l, w2h, w2l, b2, nullptr, h2h, h2l, BDIM, HDIM, HDIM, HDIM);
  // GEMM3 split-K x4 (deterministic partials), then reduce + bias
  mma_gemm<1><<<dim3((RDIM + 127) / 128, BDIM / 128, KSPLIT), 256, gemm_smem>>>(
      h2h, h2l, w3h, w3l, nullptr, costP, nullptr, nullptr, BDIM, RDIM, HDIM, HDIM / KSPLIT);
  reduce_cost<<<(BDIM * RDIM + 255) / 256, 256>>>(costP, b3, cost);

  // ADMM (persistent, 4 rows/block)
  const int admm_smem = (KDIM * PADR + 5 * AROWS * PADR + 5 * AROWS * 32 + KDIM * 33 + 32) * (int)sizeof(float);
  cudaFuncSetAttribute(admm_kernel, cudaFuncAttributeMaxDynamicSharedMemorySize, admm_smem);
  admm_kernel<<<BDIM / AROWS, 256, admm_smem>>>(cost, Wm, cap, sinv, out);
}

// round 7
// speedup vs baseline: 2.1087x; 1.1211x over previous
#include <cuda_runtime.h>
#include <cuda_bf16.h>
#include <cstdint>

// Problem constants
#define CDIM 32
#define HDIM 3200
#define BDIM 1024
#define RDIM 500
#define KDIM 30
#define N2_DIM 1030
#define NITER 200
#define KSPLIT 4
#define PSTRIDE 512

// ---------------------------------------------------------------------------
// Device-global scratch (no allocation allowed)
// ---------------------------------------------------------------------------
__device__ __nv_bfloat16 g_dh[BDIM * CDIM],  g_dl[BDIM * CDIM];
__device__ __nv_bfloat16 g_W1h[HDIM * CDIM], g_W1l[HDIM * CDIM];
__device__ __nv_bfloat16 g_W2h[HDIM * HDIM], g_W2l[HDIM * HDIM];
__device__ __nv_bfloat16 g_W3h[RDIM * HDIM], g_W3l[RDIM * HDIM];
__device__ __nv_bfloat16 g_h1h[BDIM * HDIM], g_h1l[BDIM * HDIM];
__device__ __nv_bfloat16 g_h2h[BDIM * HDIM], g_h2l[BDIM * HDIM];
__device__ float g_costP[KSPLIT * BDIM * PSTRIDE];
__device__ float g_cost[BDIM * RDIM];
__device__ float g_Sinv[KDIM * KDIM];

// ---------------------------------------------------------------------------
// PTX helpers (plain sm_80+/sm_100 base features — no arch-'a' gated instrs)
// ---------------------------------------------------------------------------
__device__ __forceinline__ uint32_t smem_u32(const void* p) {
  uint32_t a;
  asm("{ .reg .u64 t; cvta.to.shared.u64 t, %1; cvt.u32.u64 %0, t; }" : "=r"(a) : "l"(p));
  return a;
}
__device__ __forceinline__ void ldsm4(uint32_t* r, uint32_t a) {
  asm volatile("ldmatrix.sync.aligned.m8n8.x4.shared.b16 {%0,%1,%2,%3}, [%4];"
               : "=r"(r[0]), "=r"(r[1]), "=r"(r[2]), "=r"(r[3]) : "r"(a));
}
__device__ __forceinline__ void mma16816(float* c, const uint32_t* a, const uint32_t* b) {
  asm volatile(
      "mma.sync.aligned.m16n8k16.row.col.f32.bf16.bf16.f32 "
      "{%0,%1,%2,%3}, {%4,%5,%6,%7}, {%8,%9}, {%0,%1,%2,%3};"
      : "+f"(c[0]), "+f"(c[1]), "+f"(c[2]), "+f"(c[3])
      : "r"(a[0]), "r"(a[1]), "r"(a[2]), "r"(a[3]), "r"(b[0]), "r"(b[1]));
}
#define CP_COMMIT() asm volatile("cp.async.commit_group;" ::: "memory")
#define CP_WAIT(n)  asm volatile("cp.async.wait_group %0;" :: "n"(n) : "memory")

// Packed fp32x2 (Blackwell FFMA2 path; base PTX, sm_100+)
__device__ __forceinline__ unsigned long long ffma2(unsigned long long a, unsigned long long b,
                                                    unsigned long long c) {
  unsigned long long d;
  asm("fma.rn.f32x2 %0, %1, %2, %3;" : "=l"(d) : "l"(a), "l"(b), "l"(c));
  return d;
}
__device__ __forceinline__ unsigned long long fadd2(unsigned long long a, unsigned long long b) {
  unsigned long long d;
  asm("add.rn.f32x2 %0, %1, %2;" : "=l"(d) : "l"(a), "l"(b));
  return d;
}
__device__ __forceinline__ void lds_v2b64(unsigned long long& a, unsigned long long& b, uint32_t addr) {
  asm volatile("ld.shared.v2.b64 {%0,%1}, [%2];" : "=l"(a), "=l"(b) : "r"(addr));
}
__device__ __forceinline__ float2 unpack2(unsigned long long v) {
  float2 f;
  asm("mov.b64 {%0,%1}, %2;" : "=f"(f.x), "=f"(f.y) : "l"(v));
  return f;
}
__device__ __forceinline__ unsigned long long pack2(float x, float y) {
  unsigned long long v;
  asm("mov.b64 %0, {%1,%2};" : "=l"(v) : "f"(x), "f"(y));
  return v;
}

// SW64 swizzle for 64-byte rows (conflict-free ldmatrix over 8-row atoms)
__device__ __forceinline__ uint32_t sw64(uint32_t bo) { return bo ^ ((bo >> 3) & 0x30); }

// ---------------------------------------------------------------------------
// fp32 -> (bf16 hi, bf16 lo) split, 4-wide
// ---------------------------------------------------------------------------
__global__ void cvt_split4(const float* __restrict__ in, __nv_bfloat16* __restrict__ hi,
                           __nv_bfloat16* __restrict__ lo, int n4) {
  int i = blockIdx.x * 256 + threadIdx.x;
  if (i >= n4) return;
  float4 v = reinterpret_cast<const float4*>(in)[i];
  __nv_bfloat16 h0 = __float2bfloat16_rn(v.x), h1 = __float2bfloat16_rn(v.y);
  __nv_bfloat16 h2 = __float2bfloat16_rn(v.z), h3 = __float2bfloat16_rn(v.w);
  __nv_bfloat16 l0 = __float2bfloat16_rn(v.x - __bfloat162float(h0));
  __nv_bfloat16 l1 = __float2bfloat16_rn(v.y - __bfloat162float(h1));
  __nv_bfloat16 l2 = __float2bfloat16_rn(v.z - __bfloat162float(h2));
  __nv_bfloat16 l3 = __float2bfloat16_rn(v.w - __bfloat162float(h3));
  uint2 ph, pl;
  ph.x = ((uint32_t)__bfloat16_as_ushort(h1) << 16) | __bfloat16_as_ushort(h0);
  ph.y = ((uint32_t)__bfloat16_as_ushort(h3) << 16) | __bfloat16_as_ushort(h2);
  pl.x = ((uint32_t)__bfloat16_as_ushort(l1) << 16) | __bfloat16_as_ushort(l0);
  pl.y = ((uint32_t)__bfloat16_as_ushort(l3) << 16) | __bfloat16_as_ushort(l2);
  reinterpret_cast<uint2*>(hi)[i] = ph;
  reinterpret_cast<uint2*>(lo)[i] = pl;
}

// ---------------------------------------------------------------------------
// Async tile loader: 128 rows x 32 bf16 (64 B/row), SW64 swizzle, cp.async 16B
// ---------------------------------------------------------------------------
__device__ __forceinline__ void load_tile_async(uint32_t tile, const __nv_bfloat16* __restrict__ g,
                                                int row0, int rmax, int ldk, int k0, int kend,
                                                int tid) {
#pragma unroll
  for (int t = 0; t < 2; t++) {
    int v = tid + t * 256;          // 0..511
    int r = v >> 2;                 // tile row 0..127
    int cs = v & 3;                 // 16B segment (4 per 64B row)
    int gr = row0 + r;
    int gk = k0 + cs * 8;
    uint32_t dst = tile + sw64(((uint32_t)r << 6) + ((uint32_t)cs << 4));
    if (gr < rmax && gk < kend) {
      const void* src = g + (size_t)gr * ldk + gk;
      asm volatile("cp.async.cg.shared.global [%0], [%1], 16;" :: "r"(dst), "l"(src));
    } else {
      asm volatile("st.shared.v4.b32 [%0], {%1,%1,%1,%1};" :: "r"(dst), "r"(0u));
    }
  }
}

// ---------------------------------------------------------------------------
// bf16x3 split GEMM via mma.sync m16n8k16 (unchanged from R6 passing version)
// ---------------------------------------------------------------------------
#define STAGE_B 32768  // 4 arrays x 8KB

template <int MODE>
__global__ __launch_bounds__(256, 2)
void mma_gemm(const __nv_bfloat16* __restrict__ Ah, const __nv_bfloat16* __restrict__ Al,
              const __nv_bfloat16* __restrict__ Bh, const __nv_bfloat16* __restrict__ Bl,
              const float* __restrict__ bias, float* __restrict__ Pf,
              __nv_bfloat16* __restrict__ Ch, __nv_bfloat16* __restrict__ Cl,
              int M, int N, int K, int kchunk) {
  extern __shared__ char smem[];
  const uint32_t sb = smem_u32(smem);
  const int tid = threadIdx.x, wid = tid >> 5, lane = tid & 31;
  const int m0 = blockIdx.y * 128, n0 = blockIdx.x * 128;
  const int warp_m = wid & 1;
  const int warp_n = wid >> 1;

  const int kbeg = (MODE == 1) ? blockIdx.z * kchunk : 0;
  const int kend = (kbeg + kchunk < K) ? (kbeg + kchunk) : K;
  const int NC = (kend - kbeg + 31) / 32;

  float acc[4][4][4];
#pragma unroll
  for (int mt = 0; mt < 4; mt++)
#pragma unroll
    for (int nt = 0; nt < 4; nt++)
#pragma unroll
      for (int i = 0; i < 4; i++) acc[mt][nt][i] = 0.f;

#pragma unroll
  for (int s = 0; s < 2; s++) {
    uint32_t tb = sb + s * STAGE_B;
    int k0 = kbeg + s * 32;
    load_tile_async(tb + 0,     Ah, m0, M, K, k0, kend, tid);
    load_tile_async(tb + 8192,  Al, m0, M, K, k0, kend, tid);
    load_tile_async(tb + 16384, Bh, n0, N, K, k0, kend, tid);
    load_tile_async(tb + 24576, Bl, n0, N, K, k0, kend, tid);
    CP_COMMIT();
  }

  const int a_r = (lane & 15);
  const uint32_t a_koff = (lane & 16) ? 16u : 0u;
  const int b_r = ((lane & 16) ? 8 : 0) + (lane & 7);
  const uint32_t b_koff = (lane & 8) ? 16u : 0u;

  for (int c = 0; c < NC; c++) {
    if (c + 2 < NC) {
      uint32_t tb = sb + ((c + 2) % 3) * STAGE_B;
      int k0 = kbeg + (c + 2) * 32;
      load_tile_async(tb + 0,     Ah, m0, M, K, k0, kend, tid);
      load_tile_async(tb + 8192,  Al, m0, M, K, k0, kend, tid);
      load_tile_async(tb + 16384, Bh, n0, N, K, k0, kend, tid);
      load_tile_async(tb + 24576, Bl, n0, N, K, k0, kend, tid);
      CP_COMMIT();
      CP_WAIT(2);
    } else if (c + 1 < NC) {
      CP_WAIT(1);
    } else {
      CP_WAIT(0);
    }
    __syncthreads();

    const uint32_t tb = sb + (c % 3) * STAGE_B;
#pragma unroll
    for (int ks = 0; ks < 2; ks++) {
      const uint32_t kb = ks * 32;
      uint32_t bh[8], bl[8];
#pragma unroll
      for (int g2 = 0; g2 < 2; g2++) {
        uint32_t sw = sw64(((uint32_t)(warp_n * 32 + g2 * 16 + b_r) << 6) + kb + b_koff);
        ldsm4(bh + g2 * 4, tb + 16384 + sw);
        ldsm4(bl + g2 * 4, tb + 24576 + sw);
      }
#pragma unroll
      for (int mt = 0; mt < 4; mt++) {
        uint32_t ah[4], al[4];
        uint32_t sw = sw64(((uint32_t)(warp_m * 64 + mt * 16 + a_r) << 6) + kb + a_koff);
        ldsm4(ah, tb + sw);
        ldsm4(al, tb + 8192 + sw);
#pragma unroll
        for (int nt = 0; nt < 4; nt++) {
          mma16816(acc[mt][nt], ah, bh + nt * 2);
          mma16816(acc[mt][nt], al, bh + nt * 2);
          mma16816(acc[mt][nt], ah, bl + nt * 2);
        }
      }
    }
    __syncthreads();
  }

#pragma unroll
  for (int mt = 0; mt < 4; mt++) {
#pragma unroll
    for (int nt = 0; nt < 4; nt++) {
      const int col = n0 + warp_n * 32 + nt * 8 + ((lane & 3) << 1);
      const int r0 = m0 + warp_m * 64 + mt * 16 + (lane >> 2);
#pragma unroll
      for (int h = 0; h < 2; h++) {
        const int row = r0 + h * 8;
        float v0 = acc[mt][nt][h * 2 + 0];
        float v1 = acc[mt][nt][h * 2 + 1];
        if (MODE == 0) {
          v0 += bias[col];
          v1 += bias[col + 1];
          v0 = (v0 > 0.f) ? v0 : 0.1f * v0;
          v1 = (v1 > 0.f) ? v1 : 0.1f * v1;
          __nv_bfloat16 h0 = __float2bfloat16_rn(v0), h1 = __float2bfloat16_rn(v1);
          __nv_bfloat16 l0 = __float2bfloat16_rn(v0 - __bfloat162float(h0));
          __nv_bfloat16 l1 = __float2bfloat16_rn(v1 - __bfloat162float(h1));
          uint32_t ph = ((uint32_t)__bfloat16_as_ushort(h1) << 16) | __bfloat16_as_ushort(h0);
          uint32_t pl = ((uint32_t)__bfloat16_as_ushort(l1) << 16) | __bfloat16_as_ushort(l0);
          *reinterpret_cast<uint32_t*>(Ch + (size_t)row * N + col) = ph;
          *reinterpret_cast<uint32_t*>(Cl + (size_t)row * N + col) = pl;
        } else {
          float* dst = Pf + (size_t)blockIdx.z * BDIM * PSTRIDE + (size_t)row * PSTRIDE + col;
          *reinterpret_cast<float2*>(dst) = make_float2(v0, v1);
        }
      }
    }
  }
}

// ---------------------------------------------------------------------------
// Reduce split-K partials + bias -> cost [1024, 500]
// ---------------------------------------------------------------------------
__global__ void reduce_cost(const float* __restrict__ Pf, const float* __restrict__ bias,
                            float* __restrict__ cost) {
  int i = blockIdx.x * 256 + threadIdx.x;
  if (i >= BDIM * RDIM) return;
  int r = i / RDIM, n = i % RDIM;
  float s = bias[n];
#pragma unroll
  for (int z = 0; z < KSPLIT; z++)
    s += Pf[(size_t)z * BDIM * PSTRIDE + (size_t)r * PSTRIDE + n];
  cost[i] = s;
}

// ---------------------------------------------------------------------------
// Setup: S = I + 0.5 * W W^T (30x30), invert via Gauss-Jordan.
// ---------------------------------------------------------------------------
__global__ void setup_sinv(const float* __restrict__ W, float* __restrict__ Sinv) {
  __shared__ float aug[KDIM][64];
  __shared__ float fac[KDIM];
  __shared__ float pivinv;
  const int tid = threadIdx.x;  // 256 threads

  for (int idx = tid; idx < KDIM * KDIM; idx += 256) {
    int a = idx / KDIM, b = idx % KDIM;
    float s = 0.f;
    for (int j = 0; j < RDIM; j++) s += W[a * RDIM + j] * W[b * RDIM + j];
    aug[a][b] = 0.5f * s + (a == b ? 1.f : 0.f);
  }
  for (int idx = tid; idx < KDIM * 34; idx += 256) {
    int a = idx / 34, c = 30 + idx % 34;
    aug[a][c] = (c - 30 == a) ? 1.f : 0.f;
  }
  __syncthreads();

  for (int i = 0; i < KDIM; i++) {
    if (tid == 0) pivinv = 1.f / aug[i][i];
    __syncthreads();
    if (tid < 64) aug[i][tid] *= pivinv;
    __syncthreads();
    if (tid < KDIM) fac[tid] = aug[tid][i];
    __syncthreads();
    for (int idx = tid; idx < KDIM * 64; idx += 256) {
      int r = idx / 64, c = idx % 64;
      if (r != i) aug[r][c] -= fac[r] * aug[i][c];
    }
    __syncthreads();
  }
  for (int idx = tid; idx < KDIM * KDIM; idx += 256)
    Sinv[idx] = aug[idx / KDIM][30 + idx % KDIM];
}

// ---------------------------------------------------------------------------
// Persistent ADMM kernel — rewritten:
//  * single forward matvec:  t = 0.5*W*e + wsum + |p_k| - 2cap,  e = v_r - |p_s|
//  * x_r = 0.25*(e - wt) + 0.5,  x_s = 1 - x_r,  x_k = 0.5*(|p_k| - y1)
//  * packed fma.rn.f32x2 in both matvecs; ld.shared.v2.b64 vector loads
//  * E fused into M2 (3 barriers/iter)
// ---------------------------------------------------------------------------
#define AROWS 4
#define PADR 512

__global__ __launch_bounds__(256, 2)
void admm_kernel(const float* __restrict__ cost, const float* __restrict__ W,
                 const float* __restrict__ cap, const float* __restrict__ SinvG,
                 float* __restrict__ out) {
  extern __shared__ float sm[];
  float* Ws   = sm;                     // [30][512]
  float* cst  = Ws + KDIM * PADR;       // [4][512]
  float* ev   = cst + AROWS * PADR;     // [4][512]  e = v_r - |p_s|
  float* pr   = ev + AROWS * PADR;      // [4][512]
  float* ps   = pr + AROWS * PADR;      // [4][512]
  float* pk   = ps + AROWS * PADR;      // [4][32]
  float* gk   = pk + AROWS * 32;        // [4][32]
  float* ts   = gk + AROWS * 32;        // [4][32]
  float* y1d  = ts + AROWS * 32;        // [4][32] float2 (duplicated y1)
  float* tcap = y1d + AROWS * 64;       // [32]
  float* Ssm  = tcap + 32;              // [30][33]

  const int tid = threadIdx.x;
  const int lane = tid & 31;
  const int wid = tid >> 5;
  const int row0 = blockIdx.x * AROWS;

  // ---- init ----
  for (int idx = tid; idx < KDIM * PADR; idx += 256) {
    int k = idx >> 9, j = idx & (PADR - 1);
    Ws[idx] = (j < RDIM) ? W[k * RDIM + j] : 0.f;
  }
  for (int idx = tid; idx < AROWS * PADR; idx += 256) {
    int r = idx >> 9, j = idx & (PADR - 1);
    float cv = (j < RDIM) ? cost[(size_t)(row0 + r) * RDIM + j] : 0.f;
    cst[idx] = cv;
    ev[idx] = cv;         // p = 0 -> e = cost
    pr[idx] = 0.f; ps[idx] = 0.f;
  }
  for (int idx = tid; idx < KDIM * 33; idx += 256) {
    int k = idx / 33, m = idx % 33;
    Ssm[idx] = (m < KDIM) ? SinvG[k * KDIM + m] : 0.f;
  }
  if (tid < AROWS * 32) pk[tid] = 0.f;
  __syncthreads();

  // wsum_k = sum_j Ws[k][j]; tcap_k = wsum_k - 2*cap_k
  {
#pragma unroll
    for (int q = 0; q < 4; q++) {
      int k = wid * 4 + q;
      if (k < KDIM) {
        float s = 0.f;
#pragma unroll
        for (int m = 0; m < 16; m++) s += Ws[k * PADR + lane + 32 * m];
#pragma unroll
        for (int o = 16; o > 0; o >>= 1) s += __shfl_down_sync(0xffffffffu, s, o);
        if (lane == 0) tcap[k] = s;
      }
    }
  }
  __syncthreads();
  if (tid < 32) tcap[tid] = (tid < KDIM) ? tcap[tid] - 2.f * cap[tid] : 0.f;
  __syncthreads();

  // Wr2[k] = (Ws[k][j0], Ws[k][j1]) packed (for the transpose matvec)
  const int j0 = tid;
  const int j1 = tid + 256;
  unsigned long long Wr2[KDIM];
#pragma unroll
  for (int k = 0; k < KDIM; k++)
    Wr2[k] = pack2(Ws[k * PADR + j0], Ws[k * PADR + j1]);

  const int r_w = wid & 3;      // row for M1
  const int half = wid >> 2;    // k-half (0: 0..14, 1: 15..29)
  const uint32_t ws_a = smem_u32(Ws);
  const uint32_t ev_a = smem_u32(ev);
  const uint32_t yd_a = smem_u32(y1d);

  for (int it = 0; it < NITER; it++) {
    // ---- M1: gk = W e (f32x2 packed, v2.b64 loads) ----
    {
      unsigned long long er[8];
      const uint32_t eb = ev_a + ((uint32_t)(r_w * PADR + lane * 4) << 2);
#pragma unroll
      for (int s = 0; s < 4; s++) lds_v2b64(er[2 * s], er[2 * s + 1], eb + 512 * s);
#pragma unroll
      for (int kk = 0; kk < 15; kk++) {
        const int k = half * 15 + kk;
        const uint32_t wb = ws_a + ((uint32_t)(k * PADR + lane * 4) << 2);
        unsigned long long a0 = 0ull, a1 = 0ull, w0, w1;
#pragma unroll
        for (int s = 0; s < 4; s++) {
          lds_v2b64(w0, w1, wb + 512 * s);
          a0 = ffma2(w0, er[2 * s], a0);
          a1 = ffma2(w1, er[2 * s + 1], a1);
        }
        float2 f = unpack2(fadd2(a0, a1));
        float v = f.x + f.y;
#pragma unroll
        for (int o = 16; o > 0; o >>= 1) v += __shfl_down_sync(0xffffffffu, v, o);
        if (lane == 0) gk[r_w * 32 + k] = v;
      }
    }
    __syncthreads();

    // ---- Solve: y1 = Sinv(0.5*gk + |p_k| + tcap); p_k update ----
    if (wid < AROWS) {
      const int r = wid;
      float pkv = 0.f;
      if (lane < KDIM) {
        pkv = pk[r * 32 + lane];
        ts[r * 32 + lane] = 0.5f * gk[r * 32 + lane] + fabsf(pkv) + tcap[lane];
      }
      __syncwarp(0xffffffffu);
      if (lane < KDIM) {
        float y = 0.f;
#pragma unroll
        for (int m = 0; m < KDIM; m++) y += Ssm[lane * 33 + m] * ts[r * 32 + m];
        reinterpret_cast<float2*>(y1d)[r * 32 + lane] = make_float2(y, y);
        float xk = 0.5f * (fabsf(pkv) - y);
        pk[r * 32 + lane] = xk + fminf(pkv, 0.f);
        if (it == NITER - 1)
          out[(size_t)(row0 + r) * N2_DIM + RDIM + lane] = xk;
      } else if (lane < 32) {
        reinterpret_cast<float2*>(y1d)[r * 32 + lane] = make_float2(0.f, 0.f);
      }
    }
    __syncthreads();

    // ---- M2+E: wt = W^T y1; update p_r/p_s; recompute e ----
#pragma unroll
    for (int r = 0; r < AROWS; r++) {
      unsigned long long a0 = 0ull, a1 = 0ull, y0, y1v;
      const uint32_t yb = yd_a + (uint32_t)(r * 256);
#pragma unroll
      for (int kk = 0; kk < 15; kk++) {
        lds_v2b64(y0, y1v, yb + kk * 16);
        a0 = ffma2(Wr2[2 * kk], y0, a0);
        a1 = ffma2(Wr2[2 * kk + 1], y1v, a1);
      }
      float2 wt = unpack2(fadd2(a0, a1));  // (wt_j0, wt_j1)
      {
        float e0 = ev[r * PADR + j0];
        float xr = 0.25f * (e0 - wt.x) + 0.5f;
        float xs = 1.f - xr;
        float p0 = pr[r * PADR + j0], s0 = ps[r * PADR + j0];
        float np = xr + fminf(p0, 0.f);
        float nssv = xs + fminf(s0, 0.f);
        pr[r * PADR + j0] = np;
        ps[r * PADR + j0] = nssv;
        ev[r * PADR + j0] = cst[r * PADR + j0] + fabsf(np) - fabsf(nssv);
        if (it == NITER - 1) {
          out[(size_t)(row0 + r) * N2_DIM + j0] = xr;
          out[(size_t)(row0 + r) * N2_DIM + RDIM + KDIM + j0] = xs;
        }
      }
      if (j1 < RDIM) {
        float e1 = ev[r * PADR + j1];
        float xr = 0.25f * (e1 - wt.y) + 0.5f;
        float xs = 1.f - xr;
        float p1 = pr[r * PADR + j1], s1 = ps[r * PADR + j1];
        float np = xr + fminf(p1, 0.f);
        float nssv = xs + fminf(s1, 0.f);
        pr[r * PADR + j1] = np;
        ps[r * PADR + j1] = nssv;
        ev[r * PADR + j1] = cst[r * PADR + j1] + fabsf(np) - fabsf(nssv);
        if (it == NITER - 1) {
          out[(size_t)(row0 + r) * N2_DIM + j1] = xr;
          out[(size_t)(row0 + r) * N2_DIM + RDIM + KDIM + j1] = xs;
        }
      }
    }
    __syncthreads();
  }
}

// ---------------------------------------------------------------------------
extern "C" void kernel_launch(void* const* d_in, const int* in_sizes, int n_in,
                              void* d_out, int out_size) {
  const float* d   = (const float*)d_in[0];  // [1024,32]
  const float* W1  = (const float*)d_in[1];  // [3200,32]
  const float* b1  = (const float*)d_in[2];  // [3200]
  const float* W2  = (const float*)d_in[3];  // [3200,3200]
  const float* b2  = (const float*)d_in[4];  // [3200]
  const float* W3  = (const float*)d_in[5];  // [500,3200]
  const float* b3  = (const float*)d_in[6];  // [500]
  const float* Wm  = (const float*)d_in[7];  // [30,500]
  const float* cap = (const float*)d_in[8];  // [30]
  float* out = (float*)d_out;                // [1024,1030]

  __nv_bfloat16 *dh, *dl, *w1h, *w1l, *w2h, *w2l, *w3h, *w3l, *h1h, *h1l, *h2h, *h2l;
  float *cost, *costP, *sinv;
  cudaGetSymbolAddress((void**)&dh, g_dh);   cudaGetSymbolAddress((void**)&dl, g_dl);
  cudaGetSymbolAddress((void**)&w1h, g_W1h); cudaGetSymbolAddress((void**)&w1l, g_W1l);
  cudaGetSymbolAddress((void**)&w2h, g_W2h); cudaGetSymbolAddress((void**)&w2l, g_W2l);
  cudaGetSymbolAddress((void**)&w3h, g_W3h); cudaGetSymbolAddress((void**)&w3l, g_W3l);
  cudaGetSymbolAddress((void**)&h1h, g_h1h); cudaGetSymbolAddress((void**)&h1l, g_h1l);
  cudaGetSymbolAddress((void**)&h2h, g_h2h); cudaGetSymbolAddress((void**)&h2l, g_h2l);
  cudaGetSymbolAddress((void**)&cost, g_cost);
  cudaGetSymbolAddress((void**)&costP, g_costP);
  cudaGetSymbolAddress((void**)&sinv, g_Sinv);

  // Split inputs into bf16 hi/lo
  cvt_split4<<<(BDIM * CDIM / 4 + 255) / 256, 256>>>(d, dh, dl, BDIM * CDIM / 4);
  cvt_split4<<<(HDIM * CDIM / 4 + 255) / 256, 256>>>(W1, w1h, w1l, HDIM * CDIM / 4);
  cvt_split4<<<(HDIM * HDIM / 4 + 255) / 256, 256>>>(W2, w2h, w2l, HDIM * HDIM / 4);
  cvt_split4<<<(RDIM * HDIM / 4 + 255) / 256, 256>>>(W3, w3h, w3l, RDIM * HDIM / 4);

  setup_sinv<<<1, 256>>>(Wm, sinv);

  const int gemm_smem = 3 * STAGE_B;  // 98304 B
  cudaFuncSetAttribute(mma_gemm<0>, cudaFuncAttributeMaxDynamicSharedMemorySize, gemm_smem);
  cudaFuncSetAttribute(mma_gemm<1>, cudaFuncAttributeMaxDynamicSharedMemorySize, gemm_smem);

  // MLP on tensor cores (bf16x3 split via mma.sync)
  mma_gemm<0><<<dim3(HDIM / 128, BDIM / 128), 256, gemm_smem>>>(
      dh, dl, w1h, w1l, b1, nullptr, h1h, h1l, BDIM, HDIM, CDIM, CDIM);
  mma_gemm<0><<<dim3(HDIM / 128, BDIM / 128), 256, gemm_smem>>>(
      h1h, h1l, w2h, w2l, b2, nullptr, h2h, h2l, BDIM, HDIM, HDIM, HDIM);
  mma_gemm<1><<<dim3((RDIM + 127) / 128, BDIM / 128, KSPLIT), 256, gemm_smem>>>(
      h2h, h2l, w3h, w3l, nullptr, costP, nullptr, nullptr, BDIM, RDIM, HDIM, HDIM / KSPLIT);
  reduce_cost<<<(BDIM * RDIM + 255) / 256, 256>>>(costP, b3, cost);

  // ADMM (persistent, 4 rows/block, f32x2 matvecs)
  const int admm_smem = (KDIM * PADR + 4 * AROWS * PADR + 3 * AROWS * 32 + AROWS * 64 + 32 + KDIM * 33) * (int)sizeof(float);
  cudaFuncSetAttribute(admm_kernel, cudaFuncAttributeMaxDynamicSharedMemorySize, admm_smem);
  admm_kernel<<<BDIM / AROWS, 256, admm_smem>>>(cost, Wm, cap, sinv, out);
}

// round 8
// speedup vs baseline: 2.2600x; 1.0718x over previous
#include <cuda_runtime.h>
#include <cuda_bf16.h>
#include <cstdint>

// Problem constants
#define CDIM 32
#define HDIM 3200
#define BDIM 1024
#define RDIM 500
#define KDIM 30
#define N2_DIM 1030
#define NITER 200
#define KSPLIT 4
#define PSTRIDE 512

// ---------------------------------------------------------------------------
// Device-global scratch (no allocation allowed)
// ---------------------------------------------------------------------------
__device__ __nv_bfloat16 g_dh[BDIM * CDIM],  g_dl[BDIM * CDIM];
__device__ __nv_bfloat16 g_W1h[HDIM * CDIM], g_W1l[HDIM * CDIM];
__device__ __nv_bfloat16 g_W2h[HDIM * HDIM], g_W2l[HDIM * HDIM];
__device__ __nv_bfloat16 g_W3h[RDIM * HDIM], g_W3l[RDIM * HDIM];
__device__ __nv_bfloat16 g_h1h[BDIM * HDIM], g_h1l[BDIM * HDIM];
__device__ __nv_bfloat16 g_h2h[BDIM * HDIM], g_h2l[BDIM * HDIM];
__device__ float g_costP[KSPLIT * BDIM * PSTRIDE];
__device__ float g_Sinv[KDIM * KDIM];

// ---------------------------------------------------------------------------
// PTX helpers (plain sm_80+/sm_100 base features — no arch-'a' gated instrs)
// ---------------------------------------------------------------------------
__device__ __forceinline__ uint32_t smem_u32(const void* p) {
  uint32_t a;
  asm("{ .reg .u64 t; cvta.to.shared.u64 t, %1; cvt.u32.u64 %0, t; }" : "=r"(a) : "l"(p));
  return a;
}
__device__ __forceinline__ void ldsm4(uint32_t* r, uint32_t a) {
  asm volatile("ldmatrix.sync.aligned.m8n8.x4.shared.b16 {%0,%1,%2,%3}, [%4];"
               : "=r"(r[0]), "=r"(r[1]), "=r"(r[2]), "=r"(r[3]) : "r"(a));
}
__device__ __forceinline__ void mma16816(float* c, const uint32_t* a, const uint32_t* b) {
  asm volatile(
      "mma.sync.aligned.m16n8k16.row.col.f32.bf16.bf16.f32 "
      "{%0,%1,%2,%3}, {%4,%5,%6,%7}, {%8,%9}, {%0,%1,%2,%3};"
      : "+f"(c[0]), "+f"(c[1]), "+f"(c[2]), "+f"(c[3])
      : "r"(a[0]), "r"(a[1]), "r"(a[2]), "r"(a[3]), "r"(b[0]), "r"(b[1]));
}
#define CP_COMMIT() asm volatile("cp.async.commit_group;" ::: "memory")
#define CP_WAIT(n)  asm volatile("cp.async.wait_group %0;" :: "n"(n) : "memory")

// Packed fp32x2 (Blackwell FFMA2 path; base PTX, sm_100+)
__device__ __forceinline__ unsigned long long ffma2(unsigned long long a, unsigned long long b,
                                                    unsigned long long c) {
  unsigned long long d;
  asm("fma.rn.f32x2 %0, %1, %2, %3;" : "=l"(d) : "l"(a), "l"(b), "l"(c));
  return d;
}
__device__ __forceinline__ unsigned long long fadd2(unsigned long long a, unsigned long long b) {
  unsigned long long d;
  asm("add.rn.f32x2 %0, %1, %2;" : "=l"(d) : "l"(a), "l"(b));
  return d;
}
__device__ __forceinline__ void lds_v2b64(unsigned long long& a, unsigned long long& b, uint32_t addr) {
  asm volatile("ld.shared.v2.b64 {%0,%1}, [%2];" : "=l"(a), "=l"(b) : "r"(addr));
}
__device__ __forceinline__ float2 unpack2(unsigned long long v) {
  float2 f;
  asm("mov.b64 {%0,%1}, %2;" : "=f"(f.x), "=f"(f.y) : "l"(v));
  return f;
}
__device__ __forceinline__ unsigned long long pack2(float x, float y) {
  unsigned long long v;
  asm("mov.b64 %0, {%1,%2};" : "=l"(v) : "f"(x), "f"(y));
  return v;
}

// SW64 swizzle for 64-byte rows (conflict-free ldmatrix over 8-row atoms)
__device__ __forceinline__ uint32_t sw64(uint32_t bo) { return bo ^ ((bo >> 3) & 0x30); }

// ---------------------------------------------------------------------------
// Fused fp32 -> (bf16 hi, bf16 lo) split for all four input tensors.
// Sizes (float4): d 8192 | W1 25600 | W2 2,560,000 | W3 400,000; total 2,993,792.
// ---------------------------------------------------------------------------
#define CVT_N4_D   8192
#define CVT_N4_W1  25600
#define CVT_N4_W2  2560000
#define CVT_N4_W3  400000
#define CVT_C1 (CVT_N4_D)
#define CVT_C2 (CVT_C1 + CVT_N4_W1)
#define CVT_C3 (CVT_C2 + CVT_N4_W2)
#define CVT_C4 (CVT_C3 + CVT_N4_W3)

__global__ void cvt_all(const float* __restrict__ d, const float* __restrict__ W1,
                        const float* __restrict__ W2, const float* __restrict__ W3,
                        __nv_bfloat16* dh, __nv_bfloat16* dl,
                        __nv_bfloat16* w1h, __nv_bfloat16* w1l,
                        __nv_bfloat16* w2h, __nv_bfloat16* w2l,
                        __nv_bfloat16* w3h, __nv_bfloat16* w3l) {
  int i = blockIdx.x * 256 + threadIdx.x;
  const float* src;
  __nv_bfloat16 *ph, *pl;
  int off;
  if (i < CVT_C1)      { src = d;  ph = dh;  pl = dl;  off = i; }
  else if (i < CVT_C2) { src = W1; ph = w1h; pl = w1l; off = i - CVT_C1; }
  else if (i < CVT_C3) { src = W2; ph = w2h; pl = w2l; off = i - CVT_C2; }
  else if (i < CVT_C4) { src = W3; ph = w3h; pl = w3l; off = i - CVT_C3; }
  else return;
  float4 v = reinterpret_cast<const float4*>(src)[off];
  __nv_bfloat16 h0 = __float2bfloat16_rn(v.x), h1 = __float2bfloat16_rn(v.y);
  __nv_bfloat16 h2 = __float2bfloat16_rn(v.z), h3 = __float2bfloat16_rn(v.w);
  __nv_bfloat16 l0 = __float2bfloat16_rn(v.x - __bfloat162float(h0));
  __nv_bfloat16 l1 = __float2bfloat16_rn(v.y - __bfloat162float(h1));
  __nv_bfloat16 l2 = __float2bfloat16_rn(v.z - __bfloat162float(h2));
  __nv_bfloat16 l3 = __float2bfloat16_rn(v.w - __bfloat162float(h3));
  uint2 phv, plv;
  phv.x = ((uint32_t)__bfloat16_as_ushort(h1) << 16) | __bfloat16_as_ushort(h0);
  phv.y = ((uint32_t)__bfloat16_as_ushort(h3) << 16) | __bfloat16_as_ushort(h2);
  plv.x = ((uint32_t)__bfloat16_as_ushort(l1) << 16) | __bfloat16_as_ushort(l0);
  plv.y = ((uint32_t)__bfloat16_as_ushort(l3) << 16) | __bfloat16_as_ushort(l2);
  reinterpret_cast<uint2*>(ph)[off] = phv;
  reinterpret_cast<uint2*>(pl)[off] = plv;
}

// ---------------------------------------------------------------------------
// Async tile loader: 128 rows x 32 bf16 (64 B/row), SW64 swizzle, cp.async 16B
// ---------------------------------------------------------------------------
__device__ __forceinline__ void load_tile_async(uint32_t tile, const __nv_bfloat16* __restrict__ g,
                                                int row0, int rmax, int ldk, int k0, int kend,
                                                int tid) {
#pragma unroll
  for (int t = 0; t < 2; t++) {
    int v = tid + t * 256;          // 0..511
    int r = v >> 2;                 // tile row 0..127
    int cs = v & 3;                 // 16B segment (4 per 64B row)
    int gr = row0 + r;
    int gk = k0 + cs * 8;
    uint32_t dst = tile + sw64(((uint32_t)r << 6) + ((uint32_t)cs << 4));
    if (gr < rmax && gk < kend) {
      const void* src = g + (size_t)gr * ldk + gk;
      asm volatile("cp.async.cg.shared.global [%0], [%1], 16;" :: "r"(dst), "l"(src));
    } else {
      asm volatile("st.shared.v4.b32 [%0], {%1,%1,%1,%1};" :: "r"(dst), "r"(0u));
    }
  }
}

// ---------------------------------------------------------------------------
// bf16x3 split GEMM via mma.sync m16n8k16 (unchanged from R7 passing version)
// ---------------------------------------------------------------------------
#define STAGE_B 32768  // 4 arrays x 8KB

template <int MODE>
__global__ __launch_bounds__(256, 2)
void mma_gemm(const __nv_bfloat16* __restrict__ Ah, const __nv_bfloat16* __restrict__ Al,
              const __nv_bfloat16* __restrict__ Bh, const __nv_bfloat16* __restrict__ Bl,
              const float* __restrict__ bias, float* __restrict__ Pf,
              __nv_bfloat16* __restrict__ Ch, __nv_bfloat16* __restrict__ Cl,
              int M, int N, int K, int kchunk) {
  extern __shared__ char smem[];
  const uint32_t sb = smem_u32(smem);
  const int tid = threadIdx.x, wid = tid >> 5, lane = tid & 31;
  const int m0 = blockIdx.y * 128, n0 = blockIdx.x * 128;
  const int warp_m = wid & 1;
  const int warp_n = wid >> 1;

  const int kbeg = (MODE == 1) ? blockIdx.z * kchunk : 0;
  const int kend = (kbeg + kchunk < K) ? (kbeg + kchunk) : K;
  const int NC = (kend - kbeg + 31) / 32;

  float acc[4][4][4];
#pragma unroll
  for (int mt = 0; mt < 4; mt++)
#pragma unroll
    for (int nt = 0; nt < 4; nt++)
#pragma unroll
      for (int i = 0; i < 4; i++) acc[mt][nt][i] = 0.f;

#pragma unroll
  for (int s = 0; s < 2; s++) {
    uint32_t tb = sb + s * STAGE_B;
    int k0 = kbeg + s * 32;
    load_tile_async(tb + 0,     Ah, m0, M, K, k0, kend, tid);
    load_tile_async(tb + 8192,  Al, m0, M, K, k0, kend, tid);
    load_tile_async(tb + 16384, Bh, n0, N, K, k0, kend, tid);
    load_tile_async(tb + 24576, Bl, n0, N, K, k0, kend, tid);
    CP_COMMIT();
  }

  const int a_r = (lane & 15);
  const uint32_t a_koff = (lane & 16) ? 16u : 0u;
  const int b_r = ((lane & 16) ? 8 : 0) + (lane & 7);
  const uint32_t b_koff = (lane & 8) ? 16u : 0u;

  for (int c = 0; c < NC; c++) {
    if (c + 2 < NC) {
      uint32_t tb = sb + ((c + 2) % 3) * STAGE_B;
      int k0 = kbeg + (c + 2) * 32;
      load_tile_async(tb + 0,     Ah, m0, M, K, k0, kend, tid);
      load_tile_async(tb + 8192,  Al, m0, M, K, k0, kend, tid);
      load_tile_async(tb + 16384, Bh, n0, N, K, k0, kend, tid);
      load_tile_async(tb + 24576, Bl, n0, N, K, k0, kend, tid);
      CP_COMMIT();
      CP_WAIT(2);
    } else if (c + 1 < NC) {
      CP_WAIT(1);
    } else {
      CP_WAIT(0);
    }
    __syncthreads();

    const uint32_t tb = sb + (c % 3) * STAGE_B;
#pragma unroll
    for (int ks = 0; ks < 2; ks++) {
      const uint32_t kb = ks * 32;
      uint32_t bh[8], bl[8];
#pragma unroll
      for (int g2 = 0; g2 < 2; g2++) {
        uint32_t sw = sw64(((uint32_t)(warp_n * 32 + g2 * 16 + b_r) << 6) + kb + b_koff);
        ldsm4(bh + g2 * 4, tb + 16384 + sw);
        ldsm4(bl + g2 * 4, tb + 24576 + sw);
      }
#pragma unroll
      for (int mt = 0; mt < 4; mt++) {
        uint32_t ah[4], al[4];
        uint32_t sw = sw64(((uint32_t)(warp_m * 64 + mt * 16 + a_r) << 6) + kb + a_koff);
        ldsm4(ah, tb + sw);
        ldsm4(al, tb + 8192 + sw);
#pragma unroll
        for (int nt = 0; nt < 4; nt++) {
          mma16816(acc[mt][nt], ah, bh + nt * 2);
          mma16816(acc[mt][nt], al, bh + nt * 2);
          mma16816(acc[mt][nt], ah, bl + nt * 2);
        }
      }
    }
    __syncthreads();
  }

#pragma unroll
  for (int mt = 0; mt < 4; mt++) {
#pragma unroll
    for (int nt = 0; nt < 4; nt++) {
      const int col = n0 + warp_n * 32 + nt * 8 + ((lane & 3) << 1);
      const int r0 = m0 + warp_m * 64 + mt * 16 + (lane >> 2);
#pragma unroll
      for (int h = 0; h < 2; h++) {
        const int row = r0 + h * 8;
        float v0 = acc[mt][nt][h * 2 + 0];
        float v1 = acc[mt][nt][h * 2 + 1];
        if (MODE == 0) {
          v0 += bias[col];
          v1 += bias[col + 1];
          v0 = (v0 > 0.f) ? v0 : 0.1f * v0;
          v1 = (v1 > 0.f) ? v1 : 0.1f * v1;
          __nv_bfloat16 h0 = __float2bfloat16_rn(v0), h1 = __float2bfloat16_rn(v1);
          __nv_bfloat16 l0 = __float2bfloat16_rn(v0 - __bfloat162float(h0));
          __nv_bfloat16 l1 = __float2bfloat16_rn(v1 - __bfloat162float(h1));
          uint32_t ph = ((uint32_t)__bfloat16_as_ushort(h1) << 16) | __bfloat16_as_ushort(h0);
          uint32_t pl = ((uint32_t)__bfloat16_as_ushort(l1) << 16) | __bfloat16_as_ushort(l0);
          *reinterpret_cast<uint32_t*>(Ch + (size_t)row * N + col) = ph;
          *reinterpret_cast<uint32_t*>(Cl + (size_t)row * N + col) = pl;
        } else {
          float* dst = Pf + (size_t)blockIdx.z * BDIM * PSTRIDE + (size_t)row * PSTRIDE + col;
          *reinterpret_cast<float2*>(dst) = make_float2(v0, v1);
        }
      }
    }
  }
}

// ---------------------------------------------------------------------------
// Setup: S = I + 0.5 * W W^T (30x30), invert via Gauss-Jordan. 1024 threads.
// ---------------------------------------------------------------------------
__global__ void setup_sinv(const float* __restrict__ W, float* __restrict__ Sinv) {
  __shared__ float aug[KDIM][64];
  __shared__ float fac[KDIM];
  __shared__ float pivinv;
  const int tid = threadIdx.x;  // 1024 threads

  if (tid < KDIM * KDIM) {
    int a = tid / KDIM, b = tid % KDIM;
    float s = 0.f;
    for (int j = 0; j < RDIM; j++) s += W[a * RDIM + j] * W[b * RDIM + j];
    aug[a][b] = 0.5f * s + (a == b ? 1.f : 0.f);
  }
  for (int idx = tid; idx < KDIM * 34; idx += 1024) {
    int a = idx / 34, c = 30 + idx % 34;
    aug[a][c] = (c - 30 == a) ? 1.f : 0.f;
  }
  __syncthreads();

  for (int i = 0; i < KDIM; i++) {
    if (tid == 0) pivinv = 1.f / aug[i][i];
    __syncthreads();
    if (tid < 64) aug[i][tid] *= pivinv;
    __syncthreads();
    if (tid < KDIM) fac[tid] = aug[tid][i];
    __syncthreads();
    for (int idx = tid; idx < KDIM * 64; idx += 1024) {
      int r = idx / 64, c = idx % 64;
      if (r != i) aug[r][c] -= fac[r] * aug[i][c];
    }
    __syncthreads();
  }
  for (int idx = tid; idx < KDIM * KDIM; idx += 1024)
    Sinv[idx] = aug[idx / KDIM][30 + idx % KDIM];
}

// ---------------------------------------------------------------------------
// Persistent ADMM kernel — 512 threads, 7 rows/block, 147 blocks (1 CTA/SM).
//  * cost-reduce (split-K partials + bias) folded into init
//  * single forward matvec + FFMA2 everywhere; W zero-padded to 32 k-rows
//  * per-thread j (512 j-slots), M2 k-pairs in 16 packed W registers
// ---------------------------------------------------------------------------
#define AROWS 7

__global__ __launch_bounds__(512, 1)
void admm_kernel(const float* __restrict__ costP, const float* __restrict__ b3,
                 const float* __restrict__ W, const float* __restrict__ cap,
                 const float* __restrict__ SinvG, float* __restrict__ out) {
  extern __shared__ float sm[];
  float* Ws   = sm;                     // [32][512] (rows 30,31 zero)
  float* cst  = Ws + 32 * 512;          // [7][512]
  float* ev   = cst + AROWS * 512;      // [7][512]
  float* pr   = ev + AROWS * 512;       // [7][512]
  float* ps   = pr + AROWS * 512;       // [7][512]
  float* pk   = ps + AROWS * 512;       // [7][32]
  float* gk   = pk + AROWS * 32;        // [7][32]
  float* ts   = gk + AROWS * 32;        // [7][32]
  float* y1s  = ts + AROWS * 32;        // [7][32] (lanes 30,31 stay zero)
  float* tcap = y1s + AROWS * 32;       // [32]
  float* Ssm  = tcap + 32;              // [30][33]

  const int tid = threadIdx.x;          // 0..511
  const int lane = tid & 31;
  const int wid = tid >> 5;             // 0..15
  const int row0 = blockIdx.x * AROWS;

  // ---- init ----
  for (int idx = tid; idx < 32 * 512; idx += 512) {
    int k = idx >> 9, j = idx & 511;
    Ws[idx] = (k < KDIM && j < RDIM) ? W[k * RDIM + j] : 0.f;
  }
#pragma unroll
  for (int r = 0; r < AROWS; r++) {
    int j = tid;
    int row_g = row0 + r; if (row_g > BDIM - 1) row_g = BDIM - 1;
    float cv = 0.f;
    if (j < RDIM) {
      cv = b3[j];
#pragma unroll
      for (int z = 0; z < KSPLIT; z++)
        cv += costP[(size_t)z * BDIM * PSTRIDE + (size_t)row_g * PSTRIDE + j];
    }
    cst[r * 512 + j] = cv;
    ev[r * 512 + j] = cv;   // p = 0 -> e = cost
    pr[r * 512 + j] = 0.f;
    ps[r * 512 + j] = 0.f;
  }
  for (int idx = tid; idx < KDIM * 33; idx += 512) {
    int k = idx / 33, m = idx % 33;
    Ssm[idx] = (m < KDIM) ? SinvG[k * KDIM + m] : 0.f;
  }
  if (tid < AROWS * 32) { pk[tid] = 0.f; y1s[tid] = 0.f; gk[tid] = 0.f; ts[tid] = 0.f; }
  __syncthreads();

  // tcap_k = (sum_j W[k][j]) - 2*cap_k   (warps 0..14 handle 2 k's each)
  {
    int k = wid * 2;
#pragma unroll
    for (int q = 0; q < 2; q++, k++) {
      if (k < KDIM) {
        float s = 0.f;
#pragma unroll
        for (int m = 0; m < 16; m++) s += Ws[k * 512 + lane + 32 * m];
#pragma unroll
        for (int o = 16; o > 0; o >>= 1) s += __shfl_down_sync(0xffffffffu, s, o);
        if (lane == 0) tcap[k] = s - 2.f * cap[k];
      }
    }
  }
  __syncthreads();

  // M2 weights: Wr2[kk] = (Ws[2kk][j], Ws[2kk+1][j]) for kk = 0..15 (k up to 31, zero-padded)
  const int j = tid;
  unsigned long long Wr2[16];
#pragma unroll
  for (int kk = 0; kk < 16; kk++)
    Wr2[kk] = pack2(Ws[(2 * kk) * 512 + j], Ws[(2 * kk + 1) * 512 + j]);

  const int r_w = wid >> 1;    // row for M1 (warps 0..13)
  const int half = wid & 1;    // k-half (0: 0..14, 1: 15..29)
  const uint32_t ws_a = smem_u32(Ws);
  const uint32_t ev_a = smem_u32(ev);
  const uint32_t y_a  = smem_u32(y1s);

  for (int it = 0; it < NITER; it++) {
    // ---- M1: gk = W e (f32x2, v2.b64 loads; warps 0..13) ----
    if (wid < 14) {
      unsigned long long er[8];
      const uint32_t eb = ev_a + ((uint32_t)(r_w * 512 + lane * 4) << 2);
#pragma unroll
      for (int s = 0; s < 4; s++) lds_v2b64(er[2 * s], er[2 * s + 1], eb + 512 * s);
#pragma unroll
      for (int kk = 0; kk < 15; kk++) {
        const int k = half * 15 + kk;
        const uint32_t wb = ws_a + ((uint32_t)(k * 512 + lane * 4) << 2);
        unsigned long long a0 = 0ull, a1 = 0ull, w0, w1;
#pragma unroll
        for (int s = 0; s < 4; s++) {
          lds_v2b64(w0, w1, wb + 512 * s);
          a0 = ffma2(w0, er[2 * s], a0);
          a1 = ffma2(w1, er[2 * s + 1], a1);
        }
        float2 f = unpack2(fadd2(a0, a1));
        float v = f.x + f.y;
#pragma unroll
        for (int o = 16; o > 0; o >>= 1) v += __shfl_down_sync(0xffffffffu, v, o);
        if (lane == 0) gk[r_w * 32 + k] = v;
      }
    }
    __syncthreads();

    // ---- Solve: y1 = Sinv(0.5*gk + |p_k| + tcap); p_k update (warps 0..6) ----
    if (wid < AROWS) {
      const int r = wid;
      float pkv = 0.f;
      if (lane < KDIM) {
        pkv = pk[r * 32 + lane];
        ts[r * 32 + lane] = 0.5f * gk[r * 32 + lane] + fabsf(pkv) + tcap[lane];
      }
      __syncwarp(0xffffffffu);
      if (lane < KDIM) {
        float y = 0.f;
#pragma unroll
        for (int m = 0; m < KDIM; m++) y += Ssm[lane * 33 + m] * ts[r * 32 + m];
        y1s[r * 32 + lane] = y;
        float xk = 0.5f * (fabsf(pkv) - y);
        pk[r * 32 + lane] = xk + fminf(pkv, 0.f);
        if (it == NITER - 1) {
          int row_g = row0 + r; if (row_g > BDIM - 1) row_g = BDIM - 1;
          out[(size_t)row_g * N2_DIM + RDIM + lane] = xk;
        }
      }
    }
    __syncthreads();

    // ---- M2+E: wt_j = (W^T y1)_j; update p_r/p_s; recompute e ----
#pragma unroll
    for (int r = 0; r < AROWS; r++) {
      unsigned long long a0 = 0ull, a1 = 0ull, y0, y1v;
      const uint32_t yb = y_a + (uint32_t)(r * 128);
#pragma unroll
      for (int kk8 = 0; kk8 < 8; kk8++) {
        lds_v2b64(y0, y1v, yb + kk8 * 16);
        a0 = ffma2(Wr2[2 * kk8], y0, a0);
        a1 = ffma2(Wr2[2 * kk8 + 1], y1v, a1);
      }
      float2 f = unpack2(fadd2(a0, a1));
      float wt = f.x + f.y;

      float e0 = ev[r * 512 + j];
      float xr = 0.25f * (e0 - wt) + 0.5f;
      float xs = 1.f - xr;
      float p0 = pr[r * 512 + j], s0 = ps[r * 512 + j];
      float np = xr + fminf(p0, 0.f);
      float ns = xs + fminf(s0, 0.f);
      pr[r * 512 + j] = np;
      ps[r * 512 + j] = ns;
      ev[r * 512 + j] = cst[r * 512 + j] + fabsf(np) - fabsf(ns);
      if (it == NITER - 1 && j < RDIM) {
        int row_g = row0 + r; if (row_g > BDIM - 1) row_g = BDIM - 1;
        out[(size_t)row_g * N2_DIM + j] = xr;
        out[(size_t)row_g * N2_DIM + RDIM + KDIM + j] = xs;
      }
    }
    __syncthreads();
  }
}

// ---------------------------------------------------------------------------
extern "C" void kernel_launch(void* const* d_in, const int* in_sizes, int n_in,
                              void* d_out, int out_size) {
  const float* d   = (const float*)d_in[0];  // [1024,32]
  const float* W1  = (const float*)d_in[1];  // [3200,32]
  const float* b1  = (const float*)d_in[2];  // [3200]
  const float* W2  = (const float*)d_in[3];  // [3200,3200]
  const float* b2  = (const float*)d_in[4];  // [3200]
  const float* W3  = (const float*)d_in[5];  // [500,3200]
  const float* b3  = (const float*)d_in[6];  // [500]
  const float* Wm  = (const float*)d_in[7];  // [30,500]
  const float* cap = (const float*)d_in[8];  // [30]
  float* out = (float*)d_out;                // [1024,1030]

  __nv_bfloat16 *dh, *dl, *w1h, *w1l, *w2h, *w2l, *w3h, *w3l, *h1h, *h1l, *h2h, *h2l;
  float *costP, *sinv;
  cudaGetSymbolAddress((void**)&dh, g_dh);   cudaGetSymbolAddress((void**)&dl, g_dl);
  cudaGetSymbolAddress((void**)&w1h, g_W1h); cudaGetSymbolAddress((void**)&w1l, g_W1l);
  cudaGetSymbolAddress((void**)&w2h, g_W2h); cudaGetSymbolAddress((void**)&w2l, g_W2l);
  cudaGetSymbolAddress((void**)&w3h, g_W3h); cudaGetSymbolAddress((void**)&w3l, g_W3l);
  cudaGetSymbolAddress((void**)&h1h, g_h1h); cudaGetSymbolAddress((void**)&h1l, g_h1l);
  cudaGetSymbolAddress((void**)&h2h, g_h2h); cudaGetSymbolAddress((void**)&h2l, g_h2l);
  cudaGetSymbolAddress((void**)&costP, g_costP);
  cudaGetSymbolAddress((void**)&sinv, g_Sinv);

  // 1) Fused hi/lo bf16 splits of all inputs
  cvt_all<<<(CVT_C4 + 255) / 256, 256>>>(d, W1, W2, W3, dh, dl, w1h, w1l, w2h, w2l, w3h, w3l);

  // 2) Sinv = (I + 0.5 W W^T)^-1
  setup_sinv<<<1, 1024>>>(Wm, sinv);

  const int gemm_smem = 3 * STAGE_B;  // 98304 B
  cudaFuncSetAttribute(mma_gemm<0>, cudaFuncAttributeMaxDynamicSharedMemorySize, gemm_smem);
  cudaFuncSetAttribute(mma_gemm<1>, cudaFuncAttributeMaxDynamicSharedMemorySize, gemm_smem);

  // 3-5) MLP on tensor cores (bf16x3 split via mma.sync)
  mma_gemm<0><<<dim3(HDIM / 128, BDIM / 128), 256, gemm_smem>>>(
      dh, dl, w1h, w1l, b1, nullptr, h1h, h1l, BDIM, HDIM, CDIM, CDIM);
  mma_gemm<0><<<dim3(HDIM / 128, BDIM / 128), 256, gemm_smem>>>(
      h1h, h1l, w2h, w2l, b2, nullptr, h2h, h2l, BDIM, HDIM, HDIM, HDIM);
  mma_gemm<1><<<dim3((RDIM + 127) / 128, BDIM / 128, KSPLIT), 256, gemm_smem>>>(
      h2h, h2l, w3h, w3l, nullptr, costP, nullptr, nullptr, BDIM, RDIM, HDIM, HDIM / KSPLIT);

  // 6) ADMM (persistent; cost-reduce folded into init)
  const int admm_smem = (32 * 512 + 4 * AROWS * 512 + 4 * AROWS * 32 + 32 + KDIM * 33) * (int)sizeof(float);
  cudaFuncSetAttribute(admm_kernel, cudaFuncAttributeMaxDynamicSharedMemorySize, admm_smem);
  admm_kernel<<<(BDIM + AROWS - 1) / AROWS, 512, admm_smem>>>(costP, b3, Wm, cap, sinv, out);
}

// round 9
// speedup vs baseline: 2.5159x; 1.1132x over previous
#include <cuda_runtime.h>
#include <cuda_bf16.h>
#include <cstdint>

// Problem constants
#define CDIM 32
#define HDIM 3200
#define BDIM 1024
#define RDIM 500
#define KDIM 30
#define N2_DIM 1030
#define NITER 200
#define KSPLIT 4
#define PSTRIDE 512

// ---------------------------------------------------------------------------
// Device-global scratch (no allocation allowed)
// ---------------------------------------------------------------------------
__device__ __nv_bfloat16 g_dh[BDIM * CDIM],  g_dl[BDIM * CDIM];
__device__ __nv_bfloat16 g_W1h[HDIM * CDIM], g_W1l[HDIM * CDIM];
__device__ __nv_bfloat16 g_W2h[HDIM * HDIM], g_W2l[HDIM * HDIM];
__device__ __nv_bfloat16 g_W3h[RDIM * HDIM], g_W3l[RDIM * HDIM];
__device__ __nv_bfloat16 g_h1h[BDIM * HDIM], g_h1l[BDIM * HDIM];
__device__ __nv_bfloat16 g_h2h[BDIM * HDIM], g_h2l[BDIM * HDIM];
__device__ float g_costP[KSPLIT * BDIM * PSTRIDE];
__device__ float g_Sinv[KDIM * KDIM];

// ---------------------------------------------------------------------------
// PTX helpers (plain sm_80+/sm_100 base features — no arch-'a' gated instrs)
// ---------------------------------------------------------------------------
__device__ __forceinline__ uint32_t smem_u32(const void* p) {
  uint32_t a;
  asm("{ .reg .u64 t; cvta.to.shared.u64 t, %1; cvt.u32.u64 %0, t; }" : "=r"(a) : "l"(p));
  return a;
}
__device__ __forceinline__ void ldsm4(uint32_t* r, uint32_t a) {
  asm volatile("ldmatrix.sync.aligned.m8n8.x4.shared.b16 {%0,%1,%2,%3}, [%4];"
               : "=r"(r[0]), "=r"(r[1]), "=r"(r[2]), "=r"(r[3]) : "r"(a));
}
__device__ __forceinline__ void mma16816(float* c, const uint32_t* a, const uint32_t* b) {
  asm volatile(
      "mma.sync.aligned.m16n8k16.row.col.f32.bf16.bf16.f32 "
      "{%0,%1,%2,%3}, {%4,%5,%6,%7}, {%8,%9}, {%0,%1,%2,%3};"
      : "+f"(c[0]), "+f"(c[1]), "+f"(c[2]), "+f"(c[3])
      : "r"(a[0]), "r"(a[1]), "r"(a[2]), "r"(a[3]), "r"(b[0]), "r"(b[1]));
}
#define CP_COMMIT() asm volatile("cp.async.commit_group;" ::: "memory")
#define CP_WAIT(n)  asm volatile("cp.async.wait_group %0;" :: "n"(n) : "memory")

// Packed fp32x2 (Blackwell FFMA2 path; base PTX, sm_100+)
__device__ __forceinline__ unsigned long long ffma2(unsigned long long a, unsigned long long b,
                                                    unsigned long long c) {
  unsigned long long d;
  asm("fma.rn.f32x2 %0, %1, %2, %3;" : "=l"(d) : "l"(a), "l"(b), "l"(c));
  return d;
}
__device__ __forceinline__ unsigned long long fadd2(unsigned long long a, unsigned long long b) {
  unsigned long long d;
  asm("add.rn.f32x2 %0, %1, %2;" : "=l"(d) : "l"(a), "l"(b));
  return d;
}
__device__ __forceinline__ void lds_v2b64(unsigned long long& a, unsigned long long& b, uint32_t addr) {
  asm volatile("ld.shared.v2.b64 {%0,%1}, [%2];" : "=l"(a), "=l"(b) : "r"(addr));
}
__device__ __forceinline__ float2 unpack2(unsigned long long v) {
  float2 f;
  asm("mov.b64 {%0,%1}, %2;" : "=f"(f.x), "=f"(f.y) : "l"(v));
  return f;
}
__device__ __forceinline__ unsigned long long pack2(float x, float y) {
  unsigned long long v;
  asm("mov.b64 %0, {%1,%2};" : "=l"(v) : "f"(x), "f"(y));
  return v;
}

// SW64 swizzle for 64-byte rows (conflict-free ldmatrix over 8-row atoms)
__device__ __forceinline__ uint32_t sw64(uint32_t bo) { return bo ^ ((bo >> 3) & 0x30); }

// ---------------------------------------------------------------------------
// Fused fp32 -> (bf16 hi, bf16 lo) split for all four input tensors.
// ---------------------------------------------------------------------------
#define CVT_N4_D   8192
#define CVT_N4_W1  25600
#define CVT_N4_W2  2560000
#define CVT_N4_W3  400000
#define CVT_C1 (CVT_N4_D)
#define CVT_C2 (CVT_C1 + CVT_N4_W1)
#define CVT_C3 (CVT_C2 + CVT_N4_W2)
#define CVT_C4 (CVT_C3 + CVT_N4_W3)

__global__ void cvt_all(const float* __restrict__ d, const float* __restrict__ W1,
                        const float* __restrict__ W2, const float* __restrict__ W3,
                        __nv_bfloat16* dh, __nv_bfloat16* dl,
                        __nv_bfloat16* w1h, __nv_bfloat16* w1l,
                        __nv_bfloat16* w2h, __nv_bfloat16* w2l,
                        __nv_bfloat16* w3h, __nv_bfloat16* w3l) {
  int i = blockIdx.x * 256 + threadIdx.x;
  const float* src;
  __nv_bfloat16 *ph, *pl;
  int off;
  if (i < CVT_C1)      { src = d;  ph = dh;  pl = dl;  off = i; }
  else if (i < CVT_C2) { src = W1; ph = w1h; pl = w1l; off = i - CVT_C1; }
  else if (i < CVT_C3) { src = W2; ph = w2h; pl = w2l; off = i - CVT_C2; }
  else if (i < CVT_C4) { src = W3; ph = w3h; pl = w3l; off = i - CVT_C3; }
  else return;
  float4 v = reinterpret_cast<const float4*>(src)[off];
  __nv_bfloat16 h0 = __float2bfloat16_rn(v.x), h1 = __float2bfloat16_rn(v.y);
  __nv_bfloat16 h2 = __float2bfloat16_rn(v.z), h3 = __float2bfloat16_rn(v.w);
  __nv_bfloat16 l0 = __float2bfloat16_rn(v.x - __bfloat162float(h0));
  __nv_bfloat16 l1 = __float2bfloat16_rn(v.y - __bfloat162float(h1));
  __nv_bfloat16 l2 = __float2bfloat16_rn(v.z - __bfloat162float(h2));
  __nv_bfloat16 l3 = __float2bfloat16_rn(v.w - __bfloat162float(h3));
  uint2 phv, plv;
  phv.x = ((uint32_t)__bfloat16_as_ushort(h1) << 16) | __bfloat16_as_ushort(h0);
  phv.y = ((uint32_t)__bfloat16_as_ushort(h3) << 16) | __bfloat16_as_ushort(h2);
  plv.x = ((uint32_t)__bfloat16_as_ushort(l1) << 16) | __bfloat16_as_ushort(l0);
  plv.y = ((uint32_t)__bfloat16_as_ushort(l3) << 16) | __bfloat16_as_ushort(l2);
  reinterpret_cast<uint2*>(ph)[off] = phv;
  reinterpret_cast<uint2*>(pl)[off] = plv;
}

// ---------------------------------------------------------------------------
// Async tile loader: 128 rows x 32 bf16 (64 B/row), SW64 swizzle, cp.async 16B
// ---------------------------------------------------------------------------
__device__ __forceinline__ void load_tile_async(uint32_t tile, const __nv_bfloat16* __restrict__ g,
                                                int row0, int rmax, int ldk, int k0, int kend,
                                                int tid) {
#pragma unroll
  for (int t = 0; t < 2; t++) {
    int v = tid + t * 256;          // 0..511
    int r = v >> 2;                 // tile row 0..127
    int cs = v & 3;                 // 16B segment (4 per 64B row)
    int gr = row0 + r;
    int gk = k0 + cs * 8;
    uint32_t dst = tile + sw64(((uint32_t)r << 6) + ((uint32_t)cs << 4));
    if (gr < rmax && gk < kend) {
      const void* src = g + (size_t)gr * ldk + gk;
      asm volatile("cp.async.cg.shared.global [%0], [%1], 16;" :: "r"(dst), "l"(src));
    } else {
      asm volatile("st.shared.v4.b32 [%0], {%1,%1,%1,%1};" :: "r"(dst), "r"(0u));
    }
  }
}

// ---------------------------------------------------------------------------
// bf16x3 split GEMM via mma.sync m16n8k16 (unchanged from R8 passing version)
// ---------------------------------------------------------------------------
#define STAGE_B 32768  // 4 arrays x 8KB

template <int MODE>
__global__ __launch_bounds__(256, 2)
void mma_gemm(const __nv_bfloat16* __restrict__ Ah, const __nv_bfloat16* __restrict__ Al,
              const __nv_bfloat16* __restrict__ Bh, const __nv_bfloat16* __restrict__ Bl,
              const float* __restrict__ bias, float* __restrict__ Pf,
              __nv_bfloat16* __restrict__ Ch, __nv_bfloat16* __restrict__ Cl,
              int M, int N, int K, int kchunk) {
  extern __shared__ char smem[];
  const uint32_t sb = smem_u32(smem);
  const int tid = threadIdx.x, wid = tid >> 5, lane = tid & 31;
  const int m0 = blockIdx.y * 128, n0 = blockIdx.x * 128;
  const int warp_m = wid & 1;
  const int warp_n = wid >> 1;

  const int kbeg = (MODE == 1) ? blockIdx.z * kchunk : 0;
  const int kend = (kbeg + kchunk < K) ? (kbeg + kchunk) : K;
  const int NC = (kend - kbeg + 31) / 32;

  float acc[4][4][4];
#pragma unroll
  for (int mt = 0; mt < 4; mt++)
#pragma unroll
    for (int nt = 0; nt < 4; nt++)
#pragma unroll
      for (int i = 0; i < 4; i++) acc[mt][nt][i] = 0.f;

#pragma unroll
  for (int s = 0; s < 2; s++) {
    uint32_t tb = sb + s * STAGE_B;
    int k0 = kbeg + s * 32;
    load_tile_async(tb + 0,     Ah, m0, M, K, k0, kend, tid);
    load_tile_async(tb + 8192,  Al, m0, M, K, k0, kend, tid);
    load_tile_async(tb + 16384, Bh, n0, N, K, k0, kend, tid);
    load_tile_async(tb + 24576, Bl, n0, N, K, k0, kend, tid);
    CP_COMMIT();
  }

  const int a_r = (lane & 15);
  const uint32_t a_koff = (lane & 16) ? 16u : 0u;
  const int b_r = ((lane & 16) ? 8 : 0) + (lane & 7);
  const uint32_t b_koff = (lane & 8) ? 16u : 0u;

  for (int c = 0; c < NC; c++) {
    if (c + 2 < NC) {
      uint32_t tb = sb + ((c + 2) % 3) * STAGE_B;
      int k0 = kbeg + (c + 2) * 32;
      load_tile_async(tb + 0,     Ah, m0, M, K, k0, kend, tid);
      load_tile_async(tb + 8192,  Al, m0, M, K, k0, kend, tid);
      load_tile_async(tb + 16384, Bh, n0, N, K, k0, kend, tid);
      load_tile_async(tb + 24576, Bl, n0, N, K, k0, kend, tid);
      CP_COMMIT();
      CP_WAIT(2);
    } else if (c + 1 < NC) {
      CP_WAIT(1);
    } else {
      CP_WAIT(0);
    }
    __syncthreads();

    const uint32_t tb = sb + (c % 3) * STAGE_B;
#pragma unroll
    for (int ks = 0; ks < 2; ks++) {
      const uint32_t kb = ks * 32;
      uint32_t bh[8], bl[8];
#pragma unroll
      for (int g2 = 0; g2 < 2; g2++) {
        uint32_t sw = sw64(((uint32_t)(warp_n * 32 + g2 * 16 + b_r) << 6) + kb + b_koff);
        ldsm4(bh + g2 * 4, tb + 16384 + sw);
        ldsm4(bl + g2 * 4, tb + 24576 + sw);
      }
#pragma unroll
      for (int mt = 0; mt < 4; mt++) {
        uint32_t ah[4], al[4];
        uint32_t sw = sw64(((uint32_t)(warp_m * 64 + mt * 16 + a_r) << 6) + kb + a_koff);
        ldsm4(ah, tb + sw);
        ldsm4(al, tb + 8192 + sw);
#pragma unroll
        for (int nt = 0; nt < 4; nt++) {
          mma16816(acc[mt][nt], ah, bh + nt * 2);
          mma16816(acc[mt][nt], al, bh + nt * 2);
          mma16816(acc[mt][nt], ah, bl + nt * 2);
        }
      }
    }
    __syncthreads();
  }

#pragma unroll
  for (int mt = 0; mt < 4; mt++) {
#pragma unroll
    for (int nt = 0; nt < 4; nt++) {
      const int col = n0 + warp_n * 32 + nt * 8 + ((lane & 3) << 1);
      const int r0 = m0 + warp_m * 64 + mt * 16 + (lane >> 2);
#pragma unroll
      for (int h = 0; h < 2; h++) {
        const int row = r0 + h * 8;
        float v0 = acc[mt][nt][h * 2 + 0];
        float v1 = acc[mt][nt][h * 2 + 1];
        if (MODE == 0) {
          v0 += bias[col];
          v1 += bias[col + 1];
          v0 = (v0 > 0.f) ? v0 : 0.1f * v0;
          v1 = (v1 > 0.f) ? v1 : 0.1f * v1;
          __nv_bfloat16 h0 = __float2bfloat16_rn(v0), h1 = __float2bfloat16_rn(v1);
          __nv_bfloat16 l0 = __float2bfloat16_rn(v0 - __bfloat162float(h0));
          __nv_bfloat16 l1 = __float2bfloat16_rn(v1 - __bfloat162float(h1));
          uint32_t ph = ((uint32_t)__bfloat16_as_ushort(h1) << 16) | __bfloat16_as_ushort(h0);
          uint32_t pl = ((uint32_t)__bfloat16_as_ushort(l1) << 16) | __bfloat16_as_ushort(l0);
          *reinterpret_cast<uint32_t*>(Ch + (size_t)row * N + col) = ph;
          *reinterpret_cast<uint32_t*>(Cl + (size_t)row * N + col) = pl;
        } else {
          float* dst = Pf + (size_t)blockIdx.z * BDIM * PSTRIDE + (size_t)row * PSTRIDE + col;
          *reinterpret_cast<float2*>(dst) = make_float2(v0, v1);
        }
      }
    }
  }
}

// ---------------------------------------------------------------------------
// Setup: S = I + 0.5 * W W^T (30x30), invert via Gauss-Jordan. 1024 threads.
// ---------------------------------------------------------------------------
__global__ void setup_sinv(const float* __restrict__ W, float* __restrict__ Sinv) {
  __shared__ float aug[KDIM][64];
  __shared__ float fac[KDIM];
  __shared__ float pivinv;
  const int tid = threadIdx.x;  // 1024 threads

  if (tid < KDIM * KDIM) {
    int a = tid / KDIM, b = tid % KDIM;
    float s = 0.f;
    for (int j = 0; j < RDIM; j++) s += W[a * RDIM + j] * W[b * RDIM + j];
    aug[a][b] = 0.5f * s + (a == b ? 1.f : 0.f);
  }
  for (int idx = tid; idx < KDIM * 34; idx += 1024) {
    int a = idx / 34, c = 30 + idx % 34;
    aug[a][c] = (c - 30 == a) ? 1.f : 0.f;
  }
  __syncthreads();

  for (int i = 0; i < KDIM; i++) {
    if (tid == 0) pivinv = 1.f / aug[i][i];
    __syncthreads();
    if (tid < 64) aug[i][tid] *= pivinv;
    __syncthreads();
    if (tid < KDIM) fac[tid] = aug[tid][i];
    __syncthreads();
    for (int idx = tid; idx < KDIM * 64; idx += 1024) {
      int r = idx / 64, c = idx % 64;
      if (r != i) aug[r][c] -= fac[r] * aug[i][c];
    }
    __syncthreads();
  }
  for (int idx = tid; idx < KDIM * KDIM; idx += 1024)
    Sinv[idx] = aug[idx / KDIM][30 + idx % KDIM];
}

// ---------------------------------------------------------------------------
// Persistent ADMM kernel — 512 threads, 8 rows/block, 128 blocks.
//  * M1: warps = (row-pair x k-quarter): each W row read once per 2 rows
//    -> W crossbar traffic halved vs (row x k-half)
//  * pr/ps state in registers (owner thread j = tid); ev in smem (M1 reads)
//  * FFMA2 everywhere; W zero-padded to 32 k-rows
// ---------------------------------------------------------------------------
#define AROWS 8

__global__ __launch_bounds__(512, 1)
void admm_kernel(const float* __restrict__ costP, const float* __restrict__ b3,
                 const float* __restrict__ W, const float* __restrict__ cap,
                 const float* __restrict__ SinvG, float* __restrict__ out) {
  extern __shared__ float sm[];
  float* Ws   = sm;                     // [32][512] (rows 30,31 zero)
  float* ev   = Ws + 32 * 512;          // [8][512]
  float* cst  = ev + AROWS * 512;       // [8][512]
  float* pk   = cst + AROWS * 512;      // [8][32]
  float* gk   = pk + AROWS * 32;        // [8][32]
  float* ts   = gk + AROWS * 32;        // [8][32]
  float* y1s  = ts + AROWS * 32;        // [8][32] (lanes 30,31 stay zero)
  float* tcap = y1s + AROWS * 32;       // [32]
  float* Ssm  = tcap + 32;              // [30][33]

  const int tid = threadIdx.x;          // 0..511
  const int lane = tid & 31;
  const int wid = tid >> 5;             // 0..15
  const int row0 = blockIdx.x * AROWS;  // 128 blocks x 8 = 1024 exact
  const int j = tid;

  // ---- init ----
  for (int idx = tid; idx < 32 * 512; idx += 512) {
    int k = idx >> 9, jj = idx & 511;
    Ws[idx] = (k < KDIM && jj < RDIM) ? W[k * RDIM + jj] : 0.f;
  }
#pragma unroll
  for (int r = 0; r < AROWS; r++) {
    float cv = 0.f;
    if (j < RDIM) {
      cv = b3[j];
#pragma unroll
      for (int z = 0; z < KSPLIT; z++)
        cv += costP[(size_t)z * BDIM * PSTRIDE + (size_t)(row0 + r) * PSTRIDE + j];
    }
    cst[r * 512 + j] = cv;
    ev[r * 512 + j] = cv;   // p = 0 -> e = cost
  }
  for (int idx = tid; idx < KDIM * 33; idx += 512) {
    int k = idx / 33, m = idx % 33;
    Ssm[idx] = (m < KDIM) ? SinvG[k * KDIM + m] : 0.f;
  }
  for (int idx = tid; idx < AROWS * 32; idx += 512) {
    pk[idx] = 0.f; gk[idx] = 0.f; ts[idx] = 0.f; y1s[idx] = 0.f;
  }
  __syncthreads();

  // tcap_k = (sum_j W[k][j]) - 2*cap_k  (16 warps, 2 k each; k<30 guard)
  {
    int k = wid * 2;
#pragma unroll
    for (int q = 0; q < 2; q++, k++) {
      if (k < KDIM) {
        float s = 0.f;
#pragma unroll
        for (int m = 0; m < 16; m++) s += Ws[k * 512 + lane + 32 * m];
#pragma unroll
        for (int o = 16; o > 0; o >>= 1) s += __shfl_down_sync(0xffffffffu, s, o);
        if (lane == 0) tcap[k] = s - 2.f * cap[k];
      }
    }
  }
  __syncthreads();

  // M2 weights: Wr2[kk] = (Ws[2kk][j], Ws[2kk+1][j]) (k up to 31, zero-padded)
  unsigned long long Wr2[16];
#pragma unroll
  for (int kk = 0; kk < 16; kk++)
    Wr2[kk] = pack2(Ws[(2 * kk) * 512 + j], Ws[(2 * kk + 1) * 512 + j]);

  // Per-thread persistent state (owner thread = j)
  float prr[AROWS], psr[AROWS];
#pragma unroll
  for (int r = 0; r < AROWS; r++) { prr[r] = 0.f; psr[r] = 0.f; }

  const int rp = wid & 3;        // row-pair index -> rows 2rp, 2rp+1
  const int kq = wid >> 2;       // k-quarter -> k = 8kq .. 8kq+7
  const int r0m = 2 * rp, r1m = 2 * rp + 1;
  const uint32_t ws_a = smem_u32(Ws);
  const uint32_t ev_a = smem_u32(ev);
  const uint32_t y_a  = smem_u32(y1s);

  for (int it = 0; it < NITER; it++) {
    // ---- M1: gk[r][k] = sum_j W[k][j] e[r][j]; each W row read once per 2 rows ----
    {
      unsigned long long e0[8], e1[8];
      const uint32_t eb0 = ev_a + ((uint32_t)(r0m * 512 + lane * 4) << 2);
      const uint32_t eb1 = ev_a + ((uint32_t)(r1m * 512 + lane * 4) << 2);
#pragma unroll
      for (int s = 0; s < 4; s++) {
        lds_v2b64(e0[2 * s], e0[2 * s + 1], eb0 + 512 * s);
        lds_v2b64(e1[2 * s], e1[2 * s + 1], eb1 + 512 * s);
      }
#pragma unroll
      for (int kk = 0; kk < 8; kk++) {
        const int k = kq * 8 + kk;
        const uint32_t wb = ws_a + ((uint32_t)(k * 512 + lane * 4) << 2);
        unsigned long long a00 = 0ull, a01 = 0ull, a10 = 0ull, a11 = 0ull, w0, w1;
#pragma unroll
        for (int s = 0; s < 4; s++) {
          lds_v2b64(w0, w1, wb + 512 * s);
          a00 = ffma2(w0, e0[2 * s], a00);
          a01 = ffma2(w1, e0[2 * s + 1], a01);
          a10 = ffma2(w0, e1[2 * s], a10);
          a11 = ffma2(w1, e1[2 * s + 1], a11);
        }
        float2 f0 = unpack2(fadd2(a00, a01));
        float2 f1 = unpack2(fadd2(a10, a11));
        float v0 = f0.x + f0.y;
        float v1 = f1.x + f1.y;
#pragma unroll
        for (int o = 16; o > 0; o >>= 1) {
          v0 += __shfl_down_sync(0xffffffffu, v0, o);
          v1 += __shfl_down_sync(0xffffffffu, v1, o);
        }
        if (lane == 0) { gk[r0m * 32 + k] = v0; gk[r1m * 32 + k] = v1; }
      }
    }
    __syncthreads();

    // ---- Solve: y1 = Sinv(0.5*gk + |p_k| + tcap); p_k update (warps 0..7) ----
    if (wid < AROWS) {
      const int r = wid;
      float pkv = 0.f;
      if (lane < KDIM) {
        pkv = pk[r * 32 + lane];
        ts[r * 32 + lane] = 0.5f * gk[r * 32 + lane] + fabsf(pkv) + tcap[lane];
      }
      __syncwarp(0xffffffffu);
      if (lane < KDIM) {
        float y = 0.f;
#pragma unroll
        for (int m = 0; m < KDIM; m++) y += Ssm[lane * 33 + m] * ts[r * 32 + m];
        y1s[r * 32 + lane] = y;
        float xk = 0.5f * (fabsf(pkv) - y);
        pk[r * 32 + lane] = xk + fminf(pkv, 0.f);
        if (it == NITER - 1)
          out[(size_t)(row0 + r) * N2_DIM + RDIM + lane] = xk;
      }
    }
    __syncthreads();

    // ---- M2+E: wt_j = (W^T y1)_j; update p_r/p_s (regs); recompute e ----
#pragma unroll
    for (int r = 0; r < AROWS; r++) {
      unsigned long long a0 = 0ull, a1 = 0ull, y0, y1v;
      const uint32_t yb = y_a + (uint32_t)(r * 128);
#pragma unroll
      for (int kk8 = 0; kk8 < 8; kk8++) {
        lds_v2b64(y0, y1v, yb + kk8 * 16);
        a0 = ffma2(Wr2[2 * kk8], y0, a0);
        a1 = ffma2(Wr2[2 * kk8 + 1], y1v, a1);
      }
      float2 f = unpack2(fadd2(a0, a1));
      float wt = f.x + f.y;

      float e0 = ev[r * 512 + j];
      float xr = 0.25f * (e0 - wt) + 0.5f;
      float xs = 1.f - xr;
      float np = xr + fminf(prr[r], 0.f);
      float ns = xs + fminf(psr[r], 0.f);
      prr[r] = np;
      psr[r] = ns;
      ev[r * 512 + j] = cst[r * 512 + j] + fabsf(np) - fabsf(ns);
      if (it == NITER - 1 && j < RDIM) {
        out[(size_t)(row0 + r) * N2_DIM + j] = xr;
        out[(size_t)(row0 + r) * N2_DIM + RDIM + KDIM + j] = xs;
      }
    }
    __syncthreads();
  }
}

// ---------------------------------------------------------------------------
extern "C" void kernel_launch(void* const* d_in, const int* in_sizes, int n_in,
                              void* d_out, int out_size) {
  const float* d   = (const float*)d_in[0];  // [1024,32]
  const float* W1  = (const float*)d_in[1];  // [3200,32]
  const float* b1  = (const float*)d_in[2];  // [3200]
  const float* W2  = (const float*)d_in[3];  // [3200,3200]
  const float* b2  = (const float*)d_in[4];  // [3200]
  const float* W3  = (const float*)d_in[5];  // [500,3200]
  const float* b3  = (const float*)d_in[6];  // [500]
  const float* Wm  = (const float*)d_in[7];  // [30,500]
  const float* cap = (const float*)d_in[8];  // [30]
  float* out = (float*)d_out;                // [1024,1030]

  __nv_bfloat16 *dh, *dl, *w1h, *w1l, *w2h, *w2l, *w3h, *w3l, *h1h, *h1l, *h2h, *h2l;
  float *costP, *sinv;
  cudaGetSymbolAddress((void**)&dh, g_dh);   cudaGetSymbolAddress((void**)&dl, g_dl);
  cudaGetSymbolAddress((void**)&w1h, g_W1h); cudaGetSymbolAddress((void**)&w1l, g_W1l);
  cudaGetSymbolAddress((void**)&w2h, g_W2h); cudaGetSymbolAddress((void**)&w2l, g_W2l);
  cudaGetSymbolAddress((void**)&w3h, g_W3h); cudaGetSymbolAddress((void**)&w3l, g_W3l);
  cudaGetSymbolAddress((void**)&h1h, g_h1h); cudaGetSymbolAddress((void**)&h1l, g_h1l);
  cudaGetSymbolAddress((void**)&h2h, g_h2h); cudaGetSymbolAddress((void**)&h2l, g_h2l);
  cudaGetSymbolAddress((void**)&costP, g_costP);
  cudaGetSymbolAddress((void**)&sinv, g_Sinv);

  // 1) Fused hi/lo bf16 splits of all inputs
  cvt_all<<<(CVT_C4 + 255) / 256, 256>>>(d, W1, W2, W3, dh, dl, w1h, w1l, w2h, w2l, w3h, w3l);

  // 2) Sinv = (I + 0.5 W W^T)^-1
  setup_sinv<<<1, 1024>>>(Wm, sinv);

  const int gemm_smem = 3 * STAGE_B;  // 98304 B
  cudaFuncSetAttribute(mma_gemm<0>, cudaFuncAttributeMaxDynamicSharedMemorySize, gemm_smem);
  cudaFuncSetAttribute(mma_gemm<1>, cudaFuncAttributeMaxDynamicSharedMemorySize, gemm_smem);

  // 3-5) MLP on tensor cores (bf16x3 split via mma.sync)
  mma_gemm<0><<<dim3(HDIM / 128, BDIM / 128), 256, gemm_smem>>>(
      dh, dl, w1h, w1l, b1, nullptr, h1h, h1l, BDIM, HDIM, CDIM, CDIM);
  mma_gemm<0><<<dim3(HDIM / 128, BDIM / 128), 256, gemm_smem>>>(
      h1h, h1l, w2h, w2l, b2, nullptr, h2h, h2l, BDIM, HDIM, HDIM, HDIM);
  mma_gemm<1><<<dim3((RDIM + 127) / 128, BDIM / 128, KSPLIT), 256, gemm_smem>>>(
      h2h, h2l, w3h, w3l, nullptr, costP, nullptr, nullptr, BDIM, RDIM, HDIM, HDIM / KSPLIT);

  // 6) ADMM (persistent; cost-reduce folded into init; row-pair x k-quarter M1)
  const int admm_smem = (32 * 512 + 2 * AROWS * 512 + 4 * AROWS * 32 + 32 + KDIM * 33) * (int)sizeof(float);
  cudaFuncSetAttribute(admm_kernel, cudaFuncAttributeMaxDynamicSharedMemorySize, admm_smem);
  admm_kernel<<<BDIM / AROWS, 512, admm_smem>>>(costP, b3, Wm, cap, sinv, out);
}

// round 10
// speedup vs baseline: 5.0291x; 1.9989x over previous
#include <cuda_runtime.h>
#include <cuda_bf16.h>
#include <cstdint>

// Problem constants
#define CDIM 32
#define HDIM 3200
#define BDIM 1024
#define RDIM 500
#define KDIM 30
#define N2_DIM 1030
#define NITER 200
#define KSPLIT 4
#define PSTRIDE 512
#define ADMM_EPS 1e-6f

// ---------------------------------------------------------------------------
// Device-global scratch (no allocation allowed)
// ---------------------------------------------------------------------------
__device__ __nv_bfloat16 g_dh[BDIM * CDIM],  g_dl[BDIM * CDIM];
__device__ __nv_bfloat16 g_W1h[HDIM * CDIM], g_W1l[HDIM * CDIM];
__device__ __nv_bfloat16 g_W2h[HDIM * HDIM], g_W2l[HDIM * HDIM];
__device__ __nv_bfloat16 g_W3h[RDIM * HDIM], g_W3l[RDIM * HDIM];
__device__ __nv_bfloat16 g_h1h[BDIM * HDIM], g_h1l[BDIM * HDIM];
__device__ __nv_bfloat16 g_h2h[BDIM * HDIM], g_h2l[BDIM * HDIM];
__device__ float g_costP[KSPLIT * BDIM * PSTRIDE];
__device__ float g_Sinv[KDIM * KDIM];

// ---------------------------------------------------------------------------
// PTX helpers (plain sm_80+/sm_100 base features — no arch-'a' gated instrs)
// ---------------------------------------------------------------------------
__device__ __forceinline__ uint32_t smem_u32(const void* p) {
  uint32_t a;
  asm("{ .reg .u64 t; cvta.to.shared.u64 t, %1; cvt.u32.u64 %0, t; }" : "=r"(a) : "l"(p));
  return a;
}
__device__ __forceinline__ void ldsm4(uint32_t* r, uint32_t a) {
  asm volatile("ldmatrix.sync.aligned.m8n8.x4.shared.b16 {%0,%1,%2,%3}, [%4];"
               : "=r"(r[0]), "=r"(r[1]), "=r"(r[2]), "=r"(r[3]) : "r"(a));
}
__device__ __forceinline__ void mma16816(float* c, const uint32_t* a, const uint32_t* b) {
  asm volatile(
      "mma.sync.aligned.m16n8k16.row.col.f32.bf16.bf16.f32 "
      "{%0,%1,%2,%3}, {%4,%5,%6,%7}, {%8,%9}, {%0,%1,%2,%3};"
      : "+f"(c[0]), "+f"(c[1]), "+f"(c[2]), "+f"(c[3])
      : "r"(a[0]), "r"(a[1]), "r"(a[2]), "r"(a[3]), "r"(b[0]), "r"(b[1]));
}
#define CP_COMMIT() asm volatile("cp.async.commit_group;" ::: "memory")
#define CP_WAIT(n)  asm volatile("cp.async.wait_group %0;" :: "n"(n) : "memory")

// Packed fp32x2 (Blackwell FFMA2 path; base PTX, sm_100+)
__device__ __forceinline__ unsigned long long ffma2(unsigned long long a, unsigned long long b,
                                                    unsigned long long c) {
  unsigned long long d;
  asm("fma.rn.f32x2 %0, %1, %2, %3;" : "=l"(d) : "l"(a), "l"(b), "l"(c));
  return d;
}
__device__ __forceinline__ unsigned long long fadd2(unsigned long long a, unsigned long long b) {
  unsigned long long d;
  asm("add.rn.f32x2 %0, %1, %2;" : "=l"(d) : "l"(a), "l"(b));
  return d;
}
__device__ __forceinline__ void lds_v2b64(unsigned long long& a, unsigned long long& b, uint32_t addr) {
  asm volatile("ld.shared.v2.b64 {%0,%1}, [%2];" : "=l"(a), "=l"(b) : "r"(addr));
}
__device__ __forceinline__ float2 unpack2(unsigned long long v) {
  float2 f;
  asm("mov.b64 {%0,%1}, %2;" : "=f"(f.x), "=f"(f.y) : "l"(v));
  return f;
}
__device__ __forceinline__ unsigned long long pack2(float x, float y) {
  unsigned long long v;
  asm("mov.b64 %0, {%1,%2};" : "=l"(v) : "f"(x), "f"(y));
  return v;
}

// SW64 swizzle for 64-byte rows (conflict-free ldmatrix over 8-row atoms)
__device__ __forceinline__ uint32_t sw64(uint32_t bo) { return bo ^ ((bo >> 3) & 0x30); }

// ---------------------------------------------------------------------------
// Fused fp32 -> (bf16 hi, bf16 lo) split for all four input tensors.
// ---------------------------------------------------------------------------
#define CVT_N4_D   8192
#define CVT_N4_W1  25600
#define CVT_N4_W2  2560000
#define CVT_N4_W3  400000
#define CVT_C1 (CVT_N4_D)
#define CVT_C2 (CVT_C1 + CVT_N4_W1)
#define CVT_C3 (CVT_C2 + CVT_N4_W2)
#define CVT_C4 (CVT_C3 + CVT_N4_W3)

__global__ void cvt_all(const float* __restrict__ d, const float* __restrict__ W1,
                        const float* __restrict__ W2, const float* __restrict__ W3,
                        __nv_bfloat16* dh, __nv_bfloat16* dl,
                        __nv_bfloat16* w1h, __nv_bfloat16* w1l,
                        __nv_bfloat16* w2h, __nv_bfloat16* w2l,
                        __nv_bfloat16* w3h, __nv_bfloat16* w3l) {
  int i = blockIdx.x * 256 + threadIdx.x;
  const float* src;
  __nv_bfloat16 *ph, *pl;
  int off;
  if (i < CVT_C1)      { src = d;  ph = dh;  pl = dl;  off = i; }
  else if (i < CVT_C2) { src = W1; ph = w1h; pl = w1l; off = i - CVT_C1; }
  else if (i < CVT_C3) { src = W2; ph = w2h; pl = w2l; off = i - CVT_C2; }
  else if (i < CVT_C4) { src = W3; ph = w3h; pl = w3l; off = i - CVT_C3; }
  else return;
  float4 v = reinterpret_cast<const float4*>(src)[off];
  __nv_bfloat16 h0 = __float2bfloat16_rn(v.x), h1 = __float2bfloat16_rn(v.y);
  __nv_bfloat16 h2 = __float2bfloat16_rn(v.z), h3 = __float2bfloat16_rn(v.w);
  __nv_bfloat16 l0 = __float2bfloat16_rn(v.x - __bfloat162float(h0));
  __nv_bfloat16 l1 = __float2bfloat16_rn(v.y - __bfloat162float(h1));
  __nv_bfloat16 l2 = __float2bfloat16_rn(v.z - __bfloat162float(h2));
  __nv_bfloat16 l3 = __float2bfloat16_rn(v.w - __bfloat162float(h3));
  uint2 phv, plv;
  phv.x = ((uint32_t)__bfloat16_as_ushort(h1) << 16) | __bfloat16_as_ushort(h0);
  phv.y = ((uint32_t)__bfloat16_as_ushort(h3) << 16) | __bfloat16_as_ushort(h2);
  plv.x = ((uint32_t)__bfloat16_as_ushort(l1) << 16) | __bfloat16_as_ushort(l0);
  plv.y = ((uint32_t)__bfloat16_as_ushort(l3) << 16) | __bfloat16_as_ushort(l2);
  reinterpret_cast<uint2*>(ph)[off] = phv;
  reinterpret_cast<uint2*>(pl)[off] = plv;
}

// ---------------------------------------------------------------------------
// Async tile loader: 128 rows x 32 bf16 (64 B/row), SW64 swizzle, cp.async 16B
// ---------------------------------------------------------------------------
__device__ __forceinline__ void load_tile_async(uint32_t tile, const __nv_bfloat16* __restrict__ g,
                                                int row0, int rmax, int ldk, int k0, int kend,
                                                int tid) {
#pragma unroll
  for (int t = 0; t < 2; t++) {
    int v = tid + t * 256;          // 0..511
    int r = v >> 2;                 // tile row 0..127
    int cs = v & 3;                 // 16B segment (4 per 64B row)
    int gr = row0 + r;
    int gk = k0 + cs * 8;
    uint32_t dst = tile + sw64(((uint32_t)r << 6) + ((uint32_t)cs << 4));
    if (gr < rmax && gk < kend) {
      const void* src = g + (size_t)gr * ldk + gk;
      asm volatile("cp.async.cg.shared.global [%0], [%1], 16;" :: "r"(dst), "l"(src));
    } else {
      asm volatile("st.shared.v4.b32 [%0], {%1,%1,%1,%1};" :: "r"(dst), "r"(0u));
    }
  }
}

// ---------------------------------------------------------------------------
// bf16x3 split GEMM via mma.sync m16n8k16 (unchanged from R9 passing version)
// ---------------------------------------------------------------------------
#define STAGE_B 32768  // 4 arrays x 8KB

template <int MODE>
__global__ __launch_bounds__(256, 2)
void mma_gemm(const __nv_bfloat16* __restrict__ Ah, const __nv_bfloat16* __restrict__ Al,
              const __nv_bfloat16* __restrict__ Bh, const __nv_bfloat16* __restrict__ Bl,
              const float* __restrict__ bias, float* __restrict__ Pf,
              __nv_bfloat16* __restrict__ Ch, __nv_bfloat16* __restrict__ Cl,
              int M, int N, int K, int kchunk) {
  extern __shared__ char smem[];
  const uint32_t sb = smem_u32(smem);
  const int tid = threadIdx.x, wid = tid >> 5, lane = tid & 31;
  const int m0 = blockIdx.y * 128, n0 = blockIdx.x * 128;
  const int warp_m = wid & 1;
  const int warp_n = wid >> 1;

  const int kbeg = (MODE == 1) ? blockIdx.z * kchunk : 0;
  const int kend = (kbeg + kchunk < K) ? (kbeg + kchunk) : K;
  const int NC = (kend - kbeg + 31) / 32;

  float acc[4][4][4];
#pragma unroll
  for (int mt = 0; mt < 4; mt++)
#pragma unroll
    for (int nt = 0; nt < 4; nt++)
#pragma unroll
      for (int i = 0; i < 4; i++) acc[mt][nt][i] = 0.f;

#pragma unroll
  for (int s = 0; s < 2; s++) {
    uint32_t tb = sb + s * STAGE_B;
    int k0 = kbeg + s * 32;
    load_tile_async(tb + 0,     Ah, m0, M, K, k0, kend, tid);
    load_tile_async(tb + 8192,  Al, m0, M, K, k0, kend, tid);
    load_tile_async(tb + 16384, Bh, n0, N, K, k0, kend, tid);
    load_tile_async(tb + 24576, Bl, n0, N, K, k0, kend, tid);
    CP_COMMIT();
  }

  const int a_r = (lane & 15);
  const uint32_t a_koff = (lane & 16) ? 16u : 0u;
  const int b_r = ((lane & 16) ? 8 : 0) + (lane & 7);
  const uint32_t b_koff = (lane & 8) ? 16u : 0u;

  for (int c = 0; c < NC; c++) {
    if (c + 2 < NC) {
      uint32_t tb = sb + ((c + 2) % 3) * STAGE_B;
      int k0 = kbeg + (c + 2) * 32;
      load_tile_async(tb + 0,     Ah, m0, M, K, k0, kend, tid);
      load_tile_async(tb + 8192,  Al, m0, M, K, k0, kend, tid);
      load_tile_async(tb + 16384, Bh, n0, N, K, k0, kend, tid);
      load_tile_async(tb + 24576, Bl, n0, N, K, k0, kend, tid);
      CP_COMMIT();
      CP_WAIT(2);
    } else if (c + 1 < NC) {
      CP_WAIT(1);
    } else {
      CP_WAIT(0);
    }
    __syncthreads();

    const uint32_t tb = sb + (c % 3) * STAGE_B;
#pragma unroll
    for (int ks = 0; ks < 2; ks++) {
      const uint32_t kb = ks * 32;
      uint32_t bh[8], bl[8];
#pragma unroll
      for (int g2 = 0; g2 < 2; g2++) {
        uint32_t sw = sw64(((uint32_t)(warp_n * 32 + g2 * 16 + b_r) << 6) + kb + b_koff);
        ldsm4(bh + g2 * 4, tb + 16384 + sw);
        ldsm4(bl + g2 * 4, tb + 24576 + sw);
      }
#pragma unroll
      for (int mt = 0; mt < 4; mt++) {
        uint32_t ah[4], al[4];
        uint32_t sw = sw64(((uint32_t)(warp_m * 64 + mt * 16 + a_r) << 6) + kb + a_koff);
        ldsm4(ah, tb + sw);
        ldsm4(al, tb + 8192 + sw);
#pragma unroll
        for (int nt = 0; nt < 4; nt++) {
          mma16816(acc[mt][nt], ah, bh + nt * 2);
          mma16816(acc[mt][nt], al, bh + nt * 2);
          mma16816(acc[mt][nt], ah, bl + nt * 2);
        }
      }
    }
    __syncthreads();
  }

#pragma unroll
  for (int mt = 0; mt < 4; mt++) {
#pragma unroll
    for (int nt = 0; nt < 4; nt++) {
      const int col = n0 + warp_n * 32 + nt * 8 + ((lane & 3) << 1);
      const int r0 = m0 + warp_m * 64 + mt * 16 + (lane >> 2);
#pragma unroll
      for (int h = 0; h < 2; h++) {
        const int row = r0 + h * 8;
        float v0 = acc[mt][nt][h * 2 + 0];
        float v1 = acc[mt][nt][h * 2 + 1];
        if (MODE == 0) {
          v0 += bias[col];
          v1 += bias[col + 1];
          v0 = (v0 > 0.f) ? v0 : 0.1f * v0;
          v1 = (v1 > 0.f) ? v1 : 0.1f * v1;
          __nv_bfloat16 h0 = __float2bfloat16_rn(v0), h1 = __float2bfloat16_rn(v1);
          __nv_bfloat16 l0 = __float2bfloat16_rn(v0 - __bfloat162float(h0));
          __nv_bfloat16 l1 = __float2bfloat16_rn(v1 - __bfloat162float(h1));
          uint32_t ph = ((uint32_t)__bfloat16_as_ushort(h1) << 16) | __bfloat16_as_ushort(h0);
          uint32_t pl = ((uint32_t)__bfloat16_as_ushort(l1) << 16) | __bfloat16_as_ushort(l0);
          *reinterpret_cast<uint32_t*>(Ch + (size_t)row * N + col) = ph;
          *reinterpret_cast<uint32_t*>(Cl + (size_t)row * N + col) = pl;
        } else {
          float* dst = Pf + (size_t)blockIdx.z * BDIM * PSTRIDE + (size_t)row * PSTRIDE + col;
          *reinterpret_cast<float2*>(dst) = make_float2(v0, v1);
        }
      }
    }
  }
}

// ---------------------------------------------------------------------------
// Setup: S = I + 0.5 * W W^T (30x30), invert via Gauss-Jordan. 1024 threads.
// ---------------------------------------------------------------------------
__global__ void setup_sinv(const float* __restrict__ W, float* __restrict__ Sinv) {
  __shared__ float aug[KDIM][64];
  __shared__ float fac[KDIM];
  __shared__ float pivinv;
  const int tid = threadIdx.x;  // 1024 threads

  if (tid < KDIM * KDIM) {
    int a = tid / KDIM, b = tid % KDIM;
    float s = 0.f;
    for (int j = 0; j < RDIM; j++) s += W[a * RDIM + j] * W[b * RDIM + j];
    aug[a][b] = 0.5f * s + (a == b ? 1.f : 0.f);
  }
  for (int idx = tid; idx < KDIM * 34; idx += 1024) {
    int a = idx / 34, c = 30 + idx % 34;
    aug[a][c] = (c - 30 == a) ? 1.f : 0.f;
  }
  __syncthreads();

  for (int i = 0; i < KDIM; i++) {
    if (tid == 0) pivinv = 1.f / aug[i][i];
    __syncthreads();
    if (tid < 64) aug[i][tid] *= pivinv;
    __syncthreads();
    if (tid < KDIM) fac[tid] = aug[tid][i];
    __syncthreads();
    for (int idx = tid; idx < KDIM * 64; idx += 1024) {
      int r = idx / 64, c = idx % 64;
      if (r != i) aug[r][c] -= fac[r] * aug[i][c];
    }
    __syncthreads();
  }
  for (int idx = tid; idx < KDIM * KDIM; idx += 1024)
    Sinv[idx] = aug[idx / KDIM][30 + idx % KDIM];
}

// ---------------------------------------------------------------------------
// Persistent ADMM kernel — 512 threads, 8 rows/block, 128 blocks.
//  * deterministic early exit: block leaves the loop once max|Δp| < ADMM_EPS
//    (strictly safe: if never converged, all NITER iterations run)
//  * M1: warps = (row-pair x k-quarter); pr/ps in registers; FFMA2 matvecs
// ---------------------------------------------------------------------------
#define AROWS 8

__global__ __launch_bounds__(512, 1)
void admm_kernel(const float* __restrict__ costP, const float* __restrict__ b3,
                 const float* __restrict__ W, const float* __restrict__ cap,
                 const float* __restrict__ SinvG, float* __restrict__ out) {
  extern __shared__ float sm[];
  float* Ws   = sm;                     // [32][512] (rows 30,31 zero)
  float* ev   = Ws + 32 * 512;          // [8][512]
  float* cst  = ev + AROWS * 512;       // [8][512]
  float* pk   = cst + AROWS * 512;      // [8][32]
  float* gk   = pk + AROWS * 32;        // [8][32]
  float* ts   = gk + AROWS * 32;        // [8][32]
  float* y1s  = ts + AROWS * 32;        // [8][32] (lanes 30,31 stay zero)
  float* tcap = y1s + AROWS * 32;       // [32]
  float* Ssm  = tcap + 32;              // [30][33]
  float* wmax = Ssm + KDIM * 33;        // [24]: [0..15] M2 warps, [16..23] solve warps

  const int tid = threadIdx.x;          // 0..511
  const int lane = tid & 31;
  const int wid = tid >> 5;             // 0..15
  const int row0 = blockIdx.x * AROWS;  // 128 blocks x 8 = 1024 exact
  const int j = tid;

  // ---- init ----
  for (int idx = tid; idx < 32 * 512; idx += 512) {
    int k = idx >> 9, jj = idx & 511;
    Ws[idx] = (k < KDIM && jj < RDIM) ? W[k * RDIM + jj] : 0.f;
  }
#pragma unroll
  for (int r = 0; r < AROWS; r++) {
    float cv = 0.f;
    if (j < RDIM) {
      cv = b3[j];
#pragma unroll
      for (int z = 0; z < KSPLIT; z++)
        cv += costP[(size_t)z * BDIM * PSTRIDE + (size_t)(row0 + r) * PSTRIDE + j];
    }
    cst[r * 512 + j] = cv;
    ev[r * 512 + j] = cv;   // p = 0 -> e = cost
  }
  for (int idx = tid; idx < KDIM * 33; idx += 512) {
    int k = idx / 33, m = idx % 33;
    Ssm[idx] = (m < KDIM) ? SinvG[k * KDIM + m] : 0.f;
  }
  for (int idx = tid; idx < AROWS * 32; idx += 512) {
    pk[idx] = 0.f; gk[idx] = 0.f; ts[idx] = 0.f; y1s[idx] = 0.f;
  }
  if (tid < 24) wmax[tid] = 1e30f;
  __syncthreads();

  // tcap_k = (sum_j W[k][j]) - 2*cap_k
  {
    int k = wid * 2;
#pragma unroll
    for (int q = 0; q < 2; q++, k++) {
      if (k < KDIM) {
        float s = 0.f;
#pragma unroll
        for (int m = 0; m < 16; m++) s += Ws[k * 512 + lane + 32 * m];
#pragma unroll
        for (int o = 16; o > 0; o >>= 1) s += __shfl_down_sync(0xffffffffu, s, o);
        if (lane == 0) tcap[k] = s - 2.f * cap[k];
      }
    }
  }
  __syncthreads();

  // M2 weights: Wr2[kk] = (Ws[2kk][j], Ws[2kk+1][j]) (k up to 31, zero-padded)
  unsigned long long Wr2[16];
#pragma unroll
  for (int kk = 0; kk < 16; kk++)
    Wr2[kk] = pack2(Ws[(2 * kk) * 512 + j], Ws[(2 * kk + 1) * 512 + j]);

  // Per-thread persistent state (owner thread = j)
  float prr[AROWS], psr[AROWS];
#pragma unroll
  for (int r = 0; r < AROWS; r++) { prr[r] = 0.f; psr[r] = 0.f; }

  const int rp = wid & 3;        // row-pair index -> rows 2rp, 2rp+1
  const int kq = wid >> 2;       // k-quarter -> k = 8kq .. 8kq+7
  const int r0m = 2 * rp, r1m = 2 * rp + 1;
  const uint32_t ws_a = smem_u32(Ws);
  const uint32_t ev_a = smem_u32(ev);
  const uint32_t y_a  = smem_u32(y1s);

  bool conv = false;
  for (int it = 0; it < NITER; it++) {
    const bool last = conv || (it == NITER - 1);

    // ---- M1: gk[r][k] = sum_j W[k][j] e[r][j]; each W row read once per 2 rows ----
    {
      unsigned long long e0[8], e1[8];
      const uint32_t eb0 = ev_a + ((uint32_t)(r0m * 512 + lane * 4) << 2);
      const uint32_t eb1 = ev_a + ((uint32_t)(r1m * 512 + lane * 4) << 2);
#pragma unroll
      for (int s = 0; s < 4; s++) {
        lds_v2b64(e0[2 * s], e0[2 * s + 1], eb0 + 512 * s);
        lds_v2b64(e1[2 * s], e1[2 * s + 1], eb1 + 512 * s);
      }
#pragma unroll
      for (int kk = 0; kk < 8; kk++) {
        const int k = kq * 8 + kk;
        const uint32_t wb = ws_a + ((uint32_t)(k * 512 + lane * 4) << 2);
        unsigned long long a00 = 0ull, a01 = 0ull, a10 = 0ull, a11 = 0ull, w0, w1;
#pragma unroll
        for (int s = 0; s < 4; s++) {
          lds_v2b64(w0, w1, wb + 512 * s);
          a00 = ffma2(w0, e0[2 * s], a00);
          a01 = ffma2(w1, e0[2 * s + 1], a01);
          a10 = ffma2(w0, e1[2 * s], a10);
          a11 = ffma2(w1, e1[2 * s + 1], a11);
        }
        float2 f0 = unpack2(fadd2(a00, a01));
        float2 f1 = unpack2(fadd2(a10, a11));
        float v0 = f0.x + f0.y;
        float v1 = f1.x + f1.y;
#pragma unroll
        for (int o = 16; o > 0; o >>= 1) {
          v0 += __shfl_down_sync(0xffffffffu, v0, o);
          v1 += __shfl_down_sync(0xffffffffu, v1, o);
        }
        if (lane == 0) { gk[r0m * 32 + k] = v0; gk[r1m * 32 + k] = v1; }
      }
    }
    __syncthreads();

    // ---- Solve: y1 = Sinv(0.5*gk + |p_k| + tcap); p_k update (warps 0..7) ----
    if (wid < AROWS) {
      const int r = wid;
      float pkv = 0.f;
      if (lane < KDIM) {
        pkv = pk[r * 32 + lane];
        ts[r * 32 + lane] = 0.5f * gk[r * 32 + lane] + fabsf(pkv) + tcap[lane];
      }
      __syncwarp(0xffffffffu);
      float dk = 0.f;
      if (lane < KDIM) {
        float y = 0.f;
#pragma unroll
        for (int m = 0; m < KDIM; m++) y += Ssm[lane * 33 + m] * ts[r * 32 + m];
        y1s[r * 32 + lane] = y;
        float xk = 0.5f * (fabsf(pkv) - y);
        float npk = xk + fminf(pkv, 0.f);
        pk[r * 32 + lane] = npk;
        dk = fabsf(npk - pkv);
        if (last)
          out[(size_t)(row0 + r) * N2_DIM + RDIM + lane] = xk;
      }
#pragma unroll
      for (int o = 16; o > 0; o >>= 1) dk = fmaxf(dk, __shfl_down_sync(0xffffffffu, dk, o));
      if (lane == 0) wmax[16 + r] = dk;
    }
    __syncthreads();

    // ---- M2+E: wt_j = (W^T y1)_j; update p_r/p_s (regs); recompute e ----
    float dm = 0.f;
#pragma unroll
    for (int r = 0; r < AROWS; r++) {
      unsigned long long a0 = 0ull, a1 = 0ull, y0, y1v;
      const uint32_t yb = y_a + (uint32_t)(r * 128);
#pragma unroll
      for (int kk8 = 0; kk8 < 8; kk8++) {
        lds_v2b64(y0, y1v, yb + kk8 * 16);
        a0 = ffma2(Wr2[2 * kk8], y0, a0);
        a1 = ffma2(Wr2[2 * kk8 + 1], y1v, a1);
      }
      float2 f = unpack2(fadd2(a0, a1));
      float wt = f.x + f.y;

      float e0 = ev[r * 512 + j];
      float xr = 0.25f * (e0 - wt) + 0.5f;
      float xs = 1.f - xr;
      float np = xr + fminf(prr[r], 0.f);
      float ns = xs + fminf(psr[r], 0.f);
      dm = fmaxf(dm, fmaxf(fabsf(np - prr[r]), fabsf(ns - psr[r])));
      prr[r] = np;
      psr[r] = ns;
      ev[r * 512 + j] = cst[r * 512 + j] + fabsf(np) - fabsf(ns);
      if (last && j < RDIM) {
        out[(size_t)(row0 + r) * N2_DIM + j] = xr;
        out[(size_t)(row0 + r) * N2_DIM + RDIM + KDIM + j] = xs;
      }
    }
#pragma unroll
    for (int o = 16; o > 0; o >>= 1) dm = fmaxf(dm, __shfl_down_sync(0xffffffffu, dm, o));
    if (lane == 0) wmax[wid] = dm;
    __syncthreads();

    if (last) break;
    // convergence test (uniform across block): max of all 24 warp maxima
    float mx = 0.f;
#pragma unroll
    for (int q = 0; q < 24; q++) mx = fmaxf(mx, wmax[q]);
    conv = (mx < ADMM_EPS);
  }
}

// ---------------------------------------------------------------------------
extern "C" void kernel_launch(void* const* d_in, const int* in_sizes, int n_in,
                              void* d_out, int out_size) {
  const float* d   = (const float*)d_in[0];  // [1024,32]
  const float* W1  = (const float*)d_in[1];  // [3200,32]
  const float* b1  = (const float*)d_in[2];  // [3200]
  const float* W2  = (const float*)d_in[3];  // [3200,3200]
  const float* b2  = (const float*)d_in[4];  // [3200]
  const float* W3  = (const float*)d_in[5];  // [500,3200]
  const float* b3  = (const float*)d_in[6];  // [500]
  const float* Wm  = (const float*)d_in[7];  // [30,500]
  const float* cap = (const float*)d_in[8];  // [30]
  float* out = (float*)d_out;                // [1024,1030]

  __nv_bfloat16 *dh, *dl, *w1h, *w1l, *w2h, *w2l, *w3h, *w3l, *h1h, *h1l, *h2h, *h2l;
  float *costP, *sinv;
  cudaGetSymbolAddress((void**)&dh, g_dh);   cudaGetSymbolAddress((void**)&dl, g_dl);
  cudaGetSymbolAddress((void**)&w1h, g_W1h); cudaGetSymbolAddress((void**)&w1l, g_W1l);
  cudaGetSymbolAddress((void**)&w2h, g_W2h); cudaGetSymbolAddress((void**)&w2l, g_W2l);
  cudaGetSymbolAddress((void**)&w3h, g_W3h); cudaGetSymbolAddress((void**)&w3l, g_W3l);
  cudaGetSymbolAddress((void**)&h1h, g_h1h); cudaGetSymbolAddress((void**)&h1l, g_h1l);
  cudaGetSymbolAddress((void**)&h2h, g_h2h); cudaGetSymbolAddress((void**)&h2l, g_h2l);
  cudaGetSymbolAddress((void**)&costP, g_costP);
  cudaGetSymbolAddress((void**)&sinv, g_Sinv);

  // 1) Fused hi/lo bf16 splits of all inputs
  cvt_all<<<(CVT_C4 + 255) / 256, 256>>>(d, W1, W2, W3, dh, dl, w1h, w1l, w2h, w2l, w3h, w3l);

  // 2) Sinv = (I + 0.5 W W^T)^-1
  setup_sinv<<<1, 1024>>>(Wm, sinv);

  const int gemm_smem = 3 * STAGE_B;  // 98304 B
  cudaFuncSetAttribute(mma_gemm<0>, cudaFuncAttributeMaxDynamicSharedMemorySize, gemm_smem);
  cudaFuncSetAttribute(mma_gemm<1>, cudaFuncAttributeMaxDynamicSharedMemorySize, gemm_smem);

  // 3-5) MLP on tensor cores (bf16x3 split via mma.sync)
  mma_gemm<0><<<dim3(HDIM / 128, BDIM / 128), 256, gemm_smem>>>(
      dh, dl, w1h, w1l, b1, nullptr, h1h, h1l, BDIM, HDIM, CDIM, CDIM);
  mma_gemm<0><<<dim3(HDIM / 128, BDIM / 128), 256, gemm_smem>>>(
      h1h, h1l, w2h, w2l, b2, nullptr, h2h, h2l, BDIM, HDIM, HDIM, HDIM);
  mma_gemm<1><<<dim3((RDIM + 127) / 128, BDIM / 128, KSPLIT), 256, gemm_smem>>>(
      h2h, h2l, w3h, w3l, nullptr, costP, nullptr, nullptr, BDIM, RDIM, HDIM, HDIM / KSPLIT);

  // 6) ADMM (persistent; early exit on block convergence)
  const int admm_smem = (32 * 512 + 2 * AROWS * 512 + 4 * AROWS * 32 + 32 + KDIM * 33 + 24) * (int)sizeof(float);
  cudaFuncSetAttribute(admm_kernel, cudaFuncAttributeMaxDynamicSharedMemorySize, admm_smem);
  admm_kernel<<<BDIM / AROWS, 512, admm_smem>>>(costP, b3, Wm, cap, sinv, out);
}

// round 11
// speedup vs baseline: 5.4634x; 1.0864x over previous
#include <cuda_runtime.h>
#include <cuda_bf16.h>
#include <cstdint>

// Problem constants
#define CDIM 32
#define HDIM 3200
#define BDIM 1024
#define RDIM 500
#define KDIM 30
#define N2_DIM 1030
#define NITER 200
#define KSPLIT 4
#define PSTRIDE 512
#define ADMM_EPS 1e-5f

// ---------------------------------------------------------------------------
// Device-global scratch (no allocation allowed)
// ---------------------------------------------------------------------------
__device__ __nv_bfloat16 g_dh[BDIM * CDIM],  g_dl[BDIM * CDIM];
__device__ __nv_bfloat16 g_W1h[HDIM * CDIM], g_W1l[HDIM * CDIM];
__device__ __nv_bfloat16 g_W2h[HDIM * HDIM], g_W2l[HDIM * HDIM];
__device__ __nv_bfloat16 g_W3h[RDIM * HDIM], g_W3l[RDIM * HDIM];
__device__ __nv_bfloat16 g_h1h[BDIM * HDIM], g_h1l[BDIM * HDIM];
__device__ __nv_bfloat16 g_h2h[BDIM * HDIM], g_h2l[BDIM * HDIM];
__device__ float g_costP[KSPLIT * BDIM * PSTRIDE];
__device__ float g_Sinv[KDIM * KDIM];

// ---------------------------------------------------------------------------
// PTX helpers (plain sm_80+/sm_100 base features — no arch-'a' gated instrs)
// ---------------------------------------------------------------------------
__device__ __forceinline__ uint32_t smem_u32(const void* p) {
  uint32_t a;
  asm("{ .reg .u64 t; cvta.to.shared.u64 t, %1; cvt.u32.u64 %0, t; }" : "=r"(a) : "l"(p));
  return a;
}
__device__ __forceinline__ void ldsm4(uint32_t* r, uint32_t a) {
  asm volatile("ldmatrix.sync.aligned.m8n8.x4.shared.b16 {%0,%1,%2,%3}, [%4];"
               : "=r"(r[0]), "=r"(r[1]), "=r"(r[2]), "=r"(r[3]) : "r"(a));
}
__device__ __forceinline__ void mma16816(float* c, const uint32_t* a, const uint32_t* b) {
  asm volatile(
      "mma.sync.aligned.m16n8k16.row.col.f32.bf16.bf16.f32 "
      "{%0,%1,%2,%3}, {%4,%5,%6,%7}, {%8,%9}, {%0,%1,%2,%3};"
      : "+f"(c[0]), "+f"(c[1]), "+f"(c[2]), "+f"(c[3])
      : "r"(a[0]), "r"(a[1]), "r"(a[2]), "r"(a[3]), "r"(b[0]), "r"(b[1]));
}
#define CP_COMMIT() asm volatile("cp.async.commit_group;" ::: "memory")
#define CP_WAIT(n)  asm volatile("cp.async.wait_group %0;" :: "n"(n) : "memory")

// Packed fp32x2 (Blackwell FFMA2 path; base PTX, sm_100+)
__device__ __forceinline__ unsigned long long ffma2(unsigned long long a, unsigned long long b,
                                                    unsigned long long c) {
  unsigned long long d;
  asm("fma.rn.f32x2 %0, %1, %2, %3;" : "=l"(d) : "l"(a), "l"(b), "l"(c));
  return d;
}
__device__ __forceinline__ unsigned long long fadd2(unsigned long long a, unsigned long long b) {
  unsigned long long d;
  asm("add.rn.f32x2 %0, %1, %2;" : "=l"(d) : "l"(a), "l"(b));
  return d;
}
__device__ __forceinline__ void lds_v2b64(unsigned long long& a, unsigned long long& b, uint32_t addr) {
  asm volatile("ld.shared.v2.b64 {%0,%1}, [%2];" : "=l"(a), "=l"(b) : "r"(addr));
}
__device__ __forceinline__ float2 unpack2(unsigned long long v) {
  float2 f;
  asm("mov.b64 {%0,%1}, %2;" : "=f"(f.x), "=f"(f.y) : "l"(v));
  return f;
}
__device__ __forceinline__ unsigned long long pack2(float x, float y) {
  unsigned long long v;
  asm("mov.b64 %0, {%1,%2};" : "=l"(v) : "f"(x), "f"(y));
  return v;
}

// SW64 swizzle for 64-byte rows (conflict-free ldmatrix over 8-row atoms)
__device__ __forceinline__ uint32_t sw64(uint32_t bo) { return bo ^ ((bo >> 3) & 0x30); }

// ---------------------------------------------------------------------------
// Fused fp32 -> (bf16 hi, bf16 lo) split for all four input tensors.
// ---------------------------------------------------------------------------
#define CVT_N4_D   8192
#define CVT_N4_W1  25600
#define CVT_N4_W2  2560000
#define CVT_N4_W3  400000
#define CVT_C1 (CVT_N4_D)
#define CVT_C2 (CVT_C1 + CVT_N4_W1)
#define CVT_C3 (CVT_C2 + CVT_N4_W2)
#define CVT_C4 (CVT_C3 + CVT_N4_W3)

__global__ void cvt_all(const float* __restrict__ d, const float* __restrict__ W1,
                        const float* __restrict__ W2, const float* __restrict__ W3,
                        __nv_bfloat16* dh, __nv_bfloat16* dl,
                        __nv_bfloat16* w1h, __nv_bfloat16* w1l,
                        __nv_bfloat16* w2h, __nv_bfloat16* w2l,
                        __nv_bfloat16* w3h, __nv_bfloat16* w3l) {
  int i = blockIdx.x * 256 + threadIdx.x;
  const float* src;
  __nv_bfloat16 *ph, *pl;
  int off;
  if (i < CVT_C1)      { src = d;  ph = dh;  pl = dl;  off = i; }
  else if (i < CVT_C2) { src = W1; ph = w1h; pl = w1l; off = i - CVT_C1; }
  else if (i < CVT_C3) { src = W2; ph = w2h; pl = w2l; off = i - CVT_C2; }
  else if (i < CVT_C4) { src = W3; ph = w3h; pl = w3l; off = i - CVT_C3; }
  else return;
  float4 v = reinterpret_cast<const float4*>(src)[off];
  __nv_bfloat16 h0 = __float2bfloat16_rn(v.x), h1 = __float2bfloat16_rn(v.y);
  __nv_bfloat16 h2 = __float2bfloat16_rn(v.z), h3 = __float2bfloat16_rn(v.w);
  __nv_bfloat16 l0 = __float2bfloat16_rn(v.x - __bfloat162float(h0));
  __nv_bfloat16 l1 = __float2bfloat16_rn(v.y - __bfloat162float(h1));
  __nv_bfloat16 l2 = __float2bfloat16_rn(v.z - __bfloat162float(h2));
  __nv_bfloat16 l3 = __float2bfloat16_rn(v.w - __bfloat162float(h3));
  uint2 phv, plv;
  phv.x = ((uint32_t)__bfloat16_as_ushort(h1) << 16) | __bfloat16_as_ushort(h0);
  phv.y = ((uint32_t)__bfloat16_as_ushort(h3) << 16) | __bfloat16_as_ushort(h2);
  plv.x = ((uint32_t)__bfloat16_as_ushort(l1) << 16) | __bfloat16_as_ushort(l0);
  plv.y = ((uint32_t)__bfloat16_as_ushort(l3) << 16) | __bfloat16_as_ushort(l2);
  reinterpret_cast<uint2*>(ph)[off] = phv;
  reinterpret_cast<uint2*>(pl)[off] = plv;
}

// ---------------------------------------------------------------------------
// Async tile loader: ROWS x 32 bf16 (64 B/row), SW64 swizzle, cp.async 16B
// ---------------------------------------------------------------------------
template <int ROWS>
__device__ __forceinline__ void load_tile_async(uint32_t tile, const __nv_bfloat16* __restrict__ g,
                                                int row0, int rmax, int ldk, int k0, int kend,
                                                int tid) {
  constexpr int NV = ROWS * 4;     // 16B vectors per tile
#pragma unroll
  for (int t = 0; t < NV / 256; t++) {
    int v = tid + t * 256;
    int r = v >> 2;                 // tile row
    int cs = v & 3;                 // 16B segment (4 per 64B row)
    int gr = row0 + r;
    int gk = k0 + cs * 8;
    uint32_t dst = tile + sw64(((uint32_t)r << 6) + ((uint32_t)cs << 4));
    if (gr < rmax && gk < kend) {
      const void* src = g + (size_t)gr * ldk + gk;
      asm volatile("cp.async.cg.shared.global [%0], [%1], 16;" :: "r"(dst), "l"(src));
    } else {
      asm volatile("st.shared.v4.b32 [%0], {%1,%1,%1,%1};" :: "r"(dst), "r"(0u));
    }
  }
}

// ---------------------------------------------------------------------------
// bf16x3 split GEMM via mma.sync m16n8k16.
// Tile 64M x 128N, BK=32, 3-stage cp.async, 8 warps (4 warp_m x 2 warp_n),
// each warp 16M x 64N. Balanced grids: GEMM2 -> 400 CTAs.
// MODE 0: full-K, bias+lrelu, emit bf16 hi/lo. MODE 1: split-K fp32 partials.
// ---------------------------------------------------------------------------
#define STAGE_B 24576  // Ah 4KB | Al 4KB | Bh 8KB | Bl 8KB

template <int MODE>
__global__ __launch_bounds__(256, 2)
void mma_gemm(const __nv_bfloat16* __restrict__ Ah, const __nv_bfloat16* __restrict__ Al,
              const __nv_bfloat16* __restrict__ Bh, const __nv_bfloat16* __restrict__ Bl,
              const float* __restrict__ bias, float* __restrict__ Pf,
              __nv_bfloat16* __restrict__ Ch, __nv_bfloat16* __restrict__ Cl,
              int M, int N, int K, int kchunk) {
  extern __shared__ char smem[];
  const uint32_t sb = smem_u32(smem);
  const int tid = threadIdx.x, wid = tid >> 5, lane = tid & 31;
  const int m0 = blockIdx.y * 64, n0 = blockIdx.x * 128;
  const int warp_m = wid & 3;    // 4 x 16 rows
  const int warp_n = wid >> 2;   // 2 x 64 cols

  const int kbeg = (MODE == 1) ? blockIdx.z * kchunk : 0;
  const int kend = (kbeg + kchunk < K) ? (kbeg + kchunk) : K;
  const int NC = (kend - kbeg + 31) / 32;

  float acc[8][4];
#pragma unroll
  for (int nt = 0; nt < 8; nt++)
#pragma unroll
    for (int i = 0; i < 4; i++) acc[nt][i] = 0.f;

  // Prologue: stages 0,1
#pragma unroll
  for (int s = 0; s < 2; s++) {
    uint32_t tb = sb + s * STAGE_B;
    int k0 = kbeg + s * 32;
    load_tile_async<64>(tb + 0,      Ah, m0, M, K, k0, kend, tid);
    load_tile_async<64>(tb + 4096,   Al, m0, M, K, k0, kend, tid);
    load_tile_async<128>(tb + 8192,  Bh, n0, N, K, k0, kend, tid);
    load_tile_async<128>(tb + 16384, Bl, n0, N, K, k0, kend, tid);
    CP_COMMIT();
  }

  const int a_r = (lane & 15);
  const uint32_t a_koff = (lane & 16) ? 16u : 0u;
  const int b_r = ((lane & 16) ? 8 : 0) + (lane & 7);
  const uint32_t b_koff = (lane & 8) ? 16u : 0u;

  for (int c = 0; c < NC; c++) {
    if (c + 2 < NC) {
      uint32_t tb = sb + ((c + 2) % 3) * STAGE_B;
      int k0 = kbeg + (c + 2) * 32;
      load_tile_async<64>(tb + 0,      Ah, m0, M, K, k0, kend, tid);
      load_tile_async<64>(tb + 4096,   Al, m0, M, K, k0, kend, tid);
      load_tile_async<128>(tb + 8192,  Bh, n0, N, K, k0, kend, tid);
      load_tile_async<128>(tb + 16384, Bl, n0, N, K, k0, kend, tid);
      CP_COMMIT();
      CP_WAIT(2);
    } else if (c + 1 < NC) {
      CP_WAIT(1);
    } else {
      CP_WAIT(0);
    }
    __syncthreads();

    const uint32_t tb = sb + (c % 3) * STAGE_B;
#pragma unroll
    for (int ks = 0; ks < 2; ks++) {
      const uint32_t kb = ks * 32;
      uint32_t bh[16], bl[16];
#pragma unroll
      for (int g2 = 0; g2 < 4; g2++) {
        uint32_t sw = sw64(((uint32_t)(warp_n * 64 + g2 * 16 + b_r) << 6) + kb + b_koff);
        ldsm4(bh + g2 * 4, tb + 8192 + sw);
        ldsm4(bl + g2 * 4, tb + 16384 + sw);
      }
      uint32_t ah[4], al[4];
      {
        uint32_t sw = sw64(((uint32_t)(warp_m * 16 + a_r) << 6) + kb + a_koff);
        ldsm4(ah, tb + sw);
        ldsm4(al, tb + 4096 + sw);
      }
#pragma unroll
      for (int nt = 0; nt < 8; nt++) {
        mma16816(acc[nt], ah, bh + nt * 2);
        mma16816(acc[nt], al, bh + nt * 2);
        mma16816(acc[nt], ah, bl + nt * 2);
      }
    }
    __syncthreads();
  }

  // Epilogue
#pragma unroll
  for (int nt = 0; nt < 8; nt++) {
    const int col = n0 + warp_n * 64 + nt * 8 + ((lane & 3) << 1);
    const int r0 = m0 + warp_m * 16 + (lane >> 2);
#pragma unroll
    for (int h = 0; h < 2; h++) {
      const int row = r0 + h * 8;
      float v0 = acc[nt][h * 2 + 0];
      float v1 = acc[nt][h * 2 + 1];
      if (MODE == 0) {
        if (col < N) {
          v0 += bias[col];
          v1 += bias[col + 1];
          v0 = (v0 > 0.f) ? v0 : 0.1f * v0;
          v1 = (v1 > 0.f) ? v1 : 0.1f * v1;
          __nv_bfloat16 h0 = __float2bfloat16_rn(v0), h1 = __float2bfloat16_rn(v1);
          __nv_bfloat16 l0 = __float2bfloat16_rn(v0 - __bfloat162float(h0));
          __nv_bfloat16 l1 = __float2bfloat16_rn(v1 - __bfloat162float(h1));
          uint32_t ph = ((uint32_t)__bfloat16_as_ushort(h1) << 16) | __bfloat16_as_ushort(h0);
          uint32_t pl = ((uint32_t)__bfloat16_as_ushort(l1) << 16) | __bfloat16_as_ushort(l0);
          *reinterpret_cast<uint32_t*>(Ch + (size_t)row * N + col) = ph;
          *reinterpret_cast<uint32_t*>(Cl + (size_t)row * N + col) = pl;
        }
      } else {
        if (col < PSTRIDE) {
          float* dst = Pf + (size_t)blockIdx.z * BDIM * PSTRIDE + (size_t)row * PSTRIDE + col;
          *reinterpret_cast<float2*>(dst) = make_float2(v0, v1);
        }
      }
    }
  }
}

// ---------------------------------------------------------------------------
// Setup: S = I + 0.5 * W W^T (30x30), invert via Gauss-Jordan. 1024 threads.
// ---------------------------------------------------------------------------
__global__ void setup_sinv(const float* __restrict__ W, float* __restrict__ Sinv) {
  __shared__ float aug[KDIM][64];
  __shared__ float fac[KDIM];
  __shared__ float pivinv;
  const int tid = threadIdx.x;  // 1024 threads

  if (tid < KDIM * KDIM) {
    int a = tid / KDIM, b = tid % KDIM;
    float s = 0.f;
    for (int j = 0; j < RDIM; j++) s += W[a * RDIM + j] * W[b * RDIM + j];
    aug[a][b] = 0.5f * s + (a == b ? 1.f : 0.f);
  }
  for (int idx = tid; idx < KDIM * 34; idx += 1024) {
    int a = idx / 34, c = 30 + idx % 34;
    aug[a][c] = (c - 30 == a) ? 1.f : 0.f;
  }
  __syncthreads();

  for (int i = 0; i < KDIM; i++) {
    if (tid == 0) pivinv = 1.f / aug[i][i];
    __syncthreads();
    if (tid < 64) aug[i][tid] *= pivinv;
    __syncthreads();
    if (tid < KDIM) fac[tid] = aug[tid][i];
    __syncthreads();
    for (int idx = tid; idx < KDIM * 64; idx += 1024) {
      int r = idx / 64, c = idx % 64;
      if (r != i) aug[r][c] -= fac[r] * aug[i][c];
    }
    __syncthreads();
  }
  for (int idx = tid; idx < KDIM * KDIM; idx += 1024)
    Sinv[idx] = aug[idx / KDIM][30 + idx % KDIM];
}

// ---------------------------------------------------------------------------
// Persistent ADMM kernel — 512 threads, 8 rows/block, 128 blocks.
//  * deterministic early exit: block leaves once max|Δp| < ADMM_EPS
//  * M1: warps = (row-pair x k-quarter); pr/ps in registers; FFMA2 matvecs
// ---------------------------------------------------------------------------
#define AROWS 8

__global__ __launch_bounds__(512, 1)
void admm_kernel(const float* __restrict__ costP, const float* __restrict__ b3,
                 const float* __restrict__ W, const float* __restrict__ cap,
                 const float* __restrict__ SinvG, float* __restrict__ out) {
  extern __shared__ float sm[];
  float* Ws   = sm;                     // [32][512] (rows 30,31 zero)
  float* ev   = Ws + 32 * 512;          // [8][512]
  float* cst  = ev + AROWS * 512;       // [8][512]
  float* pk   = cst + AROWS * 512;      // [8][32]
  float* gk   = pk + AROWS * 32;        // [8][32]
  float* ts   = gk + AROWS * 32;        // [8][32]
  float* y1s  = ts + AROWS * 32;        // [8][32] (lanes 30,31 stay zero)
  float* tcap = y1s + AROWS * 32;       // [32]
  float* Ssm  = tcap + 32;              // [30][33]
  float* wmax = Ssm + KDIM * 33;        // [24]

  const int tid = threadIdx.x;          // 0..511
  const int lane = tid & 31;
  const int wid = tid >> 5;             // 0..15
  const int row0 = blockIdx.x * AROWS;  // 128 blocks x 8 = 1024 exact
  const int j = tid;

  // ---- init ----
  for (int idx = tid; idx < 32 * 512; idx += 512) {
    int k = idx >> 9, jj = idx & 511;
    Ws[idx] = (k < KDIM && jj < RDIM) ? W[k * RDIM + jj] : 0.f;
  }
#pragma unroll
  for (int r = 0; r < AROWS; r++) {
    float cv = 0.f;
    if (j < RDIM) {
      cv = b3[j];
#pragma unroll
      for (int z = 0; z < KSPLIT; z++)
        cv += costP[(size_t)z * BDIM * PSTRIDE + (size_t)(row0 + r) * PSTRIDE + j];
    }
    cst[r * 512 + j] = cv;
    ev[r * 512 + j] = cv;   // p = 0 -> e = cost
  }
  for (int idx = tid; idx < KDIM * 33; idx += 512) {
    int k = idx / 33, m = idx % 33;
    Ssm[idx] = (m < KDIM) ? SinvG[k * KDIM + m] : 0.f;
  }
  for (int idx = tid; idx < AROWS * 32; idx += 512) {
    pk[idx] = 0.f; gk[idx] = 0.f; ts[idx] = 0.f; y1s[idx] = 0.f;
  }
  if (tid < 24) wmax[tid] = 1e30f;
  __syncthreads();

  // tcap_k = (sum_j W[k][j]) - 2*cap_k
  {
    int k = wid * 2;
#pragma unroll
    for (int q = 0; q < 2; q++, k++) {
      if (k < KDIM) {
        float s = 0.f;
#pragma unroll
        for (int m = 0; m < 16; m++) s += Ws[k * 512 + lane + 32 * m];
#pragma unroll
        for (int o = 16; o > 0; o >>= 1) s += __shfl_down_sync(0xffffffffu, s, o);
        if (lane == 0) tcap[k] = s - 2.f * cap[k];
      }
    }
  }
  __syncthreads();

  // M2 weights: Wr2[kk] = (Ws[2kk][j], Ws[2kk+1][j]) (k up to 31, zero-padded)
  unsigned long long Wr2[16];
#pragma unroll
  for (int kk = 0; kk < 16; kk++)
    Wr2[kk] = pack2(Ws[(2 * kk) * 512 + j], Ws[(2 * kk + 1) * 512 + j]);

  // Per-thread persistent state (owner thread = j)
  float prr[AROWS], psr[AROWS];
#pragma unroll
  for (int r = 0; r < AROWS; r++) { prr[r] = 0.f; psr[r] = 0.f; }

  const int rp = wid & 3;        // row-pair index -> rows 2rp, 2rp+1
  const int kq = wid >> 2;       // k-quarter -> k = 8kq .. 8kq+7
  const int r0m = 2 * rp, r1m = 2 * rp + 1;
  const uint32_t ws_a = smem_u32(Ws);
  const uint32_t ev_a = smem_u32(ev);
  const uint32_t y_a  = smem_u32(y1s);

  bool conv = false;
  for (int it = 0; it < NITER; it++) {
    const bool last = conv || (it == NITER - 1);

    // ---- M1: gk[r][k] = sum_j W[k][j] e[r][j] ----
    {
      unsigned long long e0[8], e1[8];
      const uint32_t eb0 = ev_a + ((uint32_t)(r0m * 512 + lane * 4) << 2);
      const uint32_t eb1 = ev_a + ((uint32_t)(r1m * 512 + lane * 4) << 2);
#pragma unroll
      for (int s = 0; s < 4; s++) {
        lds_v2b64(e0[2 * s], e0[2 * s + 1], eb0 + 512 * s);
        lds_v2b64(e1[2 * s], e1[2 * s + 1], eb1 + 512 * s);
      }
#pragma unroll
      for (int kk = 0; kk < 8; kk++) {
        const int k = kq * 8 + kk;
        const uint32_t wb = ws_a + ((uint32_t)(k * 512 + lane * 4) << 2);
        unsigned long long a00 = 0ull, a01 = 0ull, a10 = 0ull, a11 = 0ull, w0, w1;
#pragma unroll
        for (int s = 0; s < 4; s++) {
          lds_v2b64(w0, w1, wb + 512 * s);
          a00 = ffma2(w0, e0[2 * s], a00);
          a01 = ffma2(w1, e0[2 * s + 1], a01);
          a10 = ffma2(w0, e1[2 * s], a10);
          a11 = ffma2(w1, e1[2 * s + 1], a11);
        }
        float2 f0 = unpack2(fadd2(a00, a01));
        float2 f1 = unpack2(fadd2(a10, a11));
        float v0 = f0.x + f0.y;
        float v1 = f1.x + f1.y;
#pragma unroll
        for (int o = 16; o > 0; o >>= 1) {
          v0 += __shfl_down_sync(0xffffffffu, v0, o);
          v1 += __shfl_down_sync(0xffffffffu, v1, o);
        }
        if (lane == 0) { gk[r0m * 32 + k] = v0; gk[r1m * 32 + k] = v1; }
      }
    }
    __syncthreads();

    // ---- Solve: y1 = Sinv(0.5*gk + |p_k| + tcap); p_k update (warps 0..7) ----
    if (wid < AROWS) {
      const int r = wid;
      float pkv = 0.f;
      if (lane < KDIM) {
        pkv = pk[r * 32 + lane];
        ts[r * 32 + lane] = 0.5f * gk[r * 32 + lane] + fabsf(pkv) + tcap[lane];
      }
      __syncwarp(0xffffffffu);
      float dk = 0.f;
      if (lane < KDIM) {
        float y = 0.f;
#pragma unroll
        for (int m = 0; m < KDIM; m++) y += Ssm[lane * 33 + m] * ts[r * 32 + m];
        y1s[r * 32 + lane] = y;
        float xk = 0.5f * (fabsf(pkv) - y);
        float npk = xk + fminf(pkv, 0.f);
        pk[r * 32 + lane] = npk;
        dk = fabsf(npk - pkv);
        if (last)
          out[(size_t)(row0 + r) * N2_DIM + RDIM + lane] = xk;
      }
#pragma unroll
      for (int o = 16; o > 0; o >>= 1) dk = fmaxf(dk, __shfl_down_sync(0xffffffffu, dk, o));
      if (lane == 0) wmax[16 + r] = dk;
    }
    __syncthreads();

    // ---- M2+E: wt_j = (W^T y1)_j; update p_r/p_s (regs); recompute e ----
    float dm = 0.f;
#pragma unroll
    for (int r = 0; r < AROWS; r++) {
      unsigned long long a0 = 0ull, a1 = 0ull, y0, y1v;
      const uint32_t yb = y_a + (uint32_t)(r * 128);
#pragma unroll
      for (int kk8 = 0; kk8 < 8; kk8++) {
        lds_v2b64(y0, y1v, yb + kk8 * 16);
        a0 = ffma2(Wr2[2 * kk8], y0, a0);
        a1 = ffma2(Wr2[2 * kk8 + 1], y1v, a1);
      }
      float2 f = unpack2(fadd2(a0, a1));
      float wt = f.x + f.y;

      float e0 = ev[r * 512 + j];
      float xr = 0.25f * (e0 - wt) + 0.5f;
      float xs = 1.f - xr;
      float np = xr + fminf(prr[r], 0.f);
      float ns = xs + fminf(psr[r], 0.f);
      dm = fmaxf(dm, fmaxf(fabsf(np - prr[r]), fabsf(ns - psr[r])));
      prr[r] = np;
      psr[r] = ns;
      ev[r * 512 + j] = cst[r * 512 + j] + fabsf(np) - fabsf(ns);
      if (last && j < RDIM) {
        out[(size_t)(row0 + r) * N2_DIM + j] = xr;
        out[(size_t)(row0 + r) * N2_DIM + RDIM + KDIM + j] = xs;
      }
    }
#pragma unroll
    for (int o = 16; o > 0; o >>= 1) dm = fmaxf(dm, __shfl_down_sync(0xffffffffu, dm, o));
    if (lane == 0) wmax[wid] = dm;
    __syncthreads();

    if (last) break;
    float mx = 0.f;
#pragma unroll
    for (int q = 0; q < 24; q++) mx = fmaxf(mx, wmax[q]);
    conv = (mx < ADMM_EPS);
  }
}

// ---------------------------------------------------------------------------
extern "C" void kernel_launch(void* const* d_in, const int* in_sizes, int n_in,
                              void* d_out, int out_size) {
  const float* d   = (const float*)d_in[0];  // [1024,32]
  const float* W1  = (const float*)d_in[1];  // [3200,32]
  const float* b1  = (const float*)d_in[2];  // [3200]
  const float* W2  = (const float*)d_in[3];  // [3200,3200]
  const float* b2  = (const float*)d_in[4];  // [3200]
  const float* W3  = (const float*)d_in[5];  // [500,3200]
  const float* b3  = (const float*)d_in[6];  // [500]
  const float* Wm  = (const float*)d_in[7];  // [30,500]
  const float* cap = (const float*)d_in[8];  // [30]
  float* out = (float*)d_out;                // [1024,1030]

  __nv_bfloat16 *dh, *dl, *w1h, *w1l, *w2h, *w2l, *w3h, *w3l, *h1h, *h1l, *h2h, *h2l;
  float *costP, *sinv;
  cudaGetSymbolAddress((void**)&dh, g_dh);   cudaGetSymbolAddress((void**)&dl, g_dl);
  cudaGetSymbolAddress((void**)&w1h, g_W1h); cudaGetSymbolAddress((void**)&w1l, g_W1l);
  cudaGetSymbolAddress((void**)&w2h, g_W2h); cudaGetSymbolAddress((void**)&w2l, g_W2l);
  cudaGetSymbolAddress((void**)&w3h, g_W3h); cudaGetSymbolAddress((void**)&w3l, g_W3l);
  cudaGetSymbolAddress((void**)&h1h, g_h1h); cudaGetSymbolAddress((void**)&h1l, g_h1l);
  cudaGetSymbolAddress((void**)&h2h, g_h2h); cudaGetSymbolAddress((void**)&h2l, g_h2l);
  cudaGetSymbolAddress((void**)&costP, g_costP);
  cudaGetSymbolAddress((void**)&sinv, g_Sinv);

  // 1) Fused hi/lo bf16 splits of all inputs
  cvt_all<<<(CVT_C4 + 255) / 256, 256>>>(d, W1, W2, W3, dh, dl, w1h, w1l, w2h, w2l, w3h, w3l);

  // 2) Sinv = (I + 0.5 W W^T)^-1
  setup_sinv<<<1, 1024>>>(Wm, sinv);

  const int gemm_smem = 3 * STAGE_B;  // 73728 B
  cudaFuncSetAttribute(mma_gemm<0>, cudaFuncAttributeMaxDynamicSharedMemorySize, gemm_smem);
  cudaFuncSetAttribute(mma_gemm<1>, cudaFuncAttributeMaxDynamicSharedMemorySize, gemm_smem);

  // 3-5) MLP on tensor cores (bf16x3 split via mma.sync); 64M x 128N tiles
  mma_gemm<0><<<dim3(HDIM / 128, BDIM / 64), 256, gemm_smem>>>(
      dh, dl, w1h, w1l, b1, nullptr, h1h, h1l, BDIM, HDIM, CDIM, CDIM);
  mma_gemm<0><<<dim3(HDIM / 128, BDIM / 64), 256, gemm_smem>>>(
      h1h, h1l, w2h, w2l, b2, nullptr, h2h, h2l, BDIM, HDIM, HDIM, HDIM);
  mma_gemm<1><<<dim3((RDIM + 127) / 128, BDIM / 64, KSPLIT), 256, gemm_smem>>>(
      h2h, h2l, w3h, w3l, nullptr, costP, nullptr, nullptr, BDIM, RDIM, HDIM, HDIM / KSPLIT);

  // 6) ADMM (persistent; early exit on block convergence)
  const int admm_smem = (32 * 512 + 2 * AROWS * 512 + 4 * AROWS * 32 + 32 + KDIM * 33 + 24) * (int)sizeof(float);
  cudaFuncSetAttribute(admm_kernel, cudaFuncAttributeMaxDynamicSharedMemorySize, admm_smem);
  admm_kernel<<<BDIM / AROWS, 512, admm_smem>>>(costP, b3, Wm, cap, sinv, out);
}

// round 12
// speedup vs baseline: 6.0776x; 1.1124x over previous
#include <cuda_runtime.h>
#include <cuda_bf16.h>
#include <cstdint>

// Problem constants
#define CDIM 32
#define HDIM 3200
#define BDIM 1024
#define RDIM 500
#define KDIM 30
#define N2_DIM 1030
#define NITER 200
#define KSPLIT 4
#define PSTRIDE 512
#define ADMM_EPS 3e-5f

// ---------------------------------------------------------------------------
// Device-global scratch (no allocation allowed)
// ---------------------------------------------------------------------------
__device__ __nv_bfloat16 g_dh[BDIM * CDIM],  g_dl[BDIM * CDIM];
__device__ __nv_bfloat16 g_W1h[HDIM * CDIM], g_W1l[HDIM * CDIM];
__device__ __nv_bfloat16 g_W2h[HDIM * HDIM], g_W2l[HDIM * HDIM];
__device__ __nv_bfloat16 g_W3h[RDIM * HDIM], g_W3l[RDIM * HDIM];
__device__ __nv_bfloat16 g_h1h[BDIM * HDIM], g_h1l[BDIM * HDIM];
__device__ __nv_bfloat16 g_h2h[BDIM * HDIM], g_h2l[BDIM * HDIM];
__device__ float g_costP[KSPLIT * BDIM * PSTRIDE];
__device__ float g_Sinv[KDIM * KDIM];

// ---------------------------------------------------------------------------
// PTX helpers (plain sm_80+/sm_100 base features — no arch-'a' gated instrs)
// ---------------------------------------------------------------------------
__device__ __forceinline__ uint32_t smem_u32(const void* p) {
  uint32_t a;
  asm("{ .reg .u64 t; cvta.to.shared.u64 t, %1; cvt.u32.u64 %0, t; }" : "=r"(a) : "l"(p));
  return a;
}
__device__ __forceinline__ void ldsm4(uint32_t* r, uint32_t a) {
  asm volatile("ldmatrix.sync.aligned.m8n8.x4.shared.b16 {%0,%1,%2,%3}, [%4];"
               : "=r"(r[0]), "=r"(r[1]), "=r"(r[2]), "=r"(r[3]) : "r"(a));
}
__device__ __forceinline__ void mma16816(float* c, const uint32_t* a, const uint32_t* b) {
  asm volatile(
      "mma.sync.aligned.m16n8k16.row.col.f32.bf16.bf16.f32 "
      "{%0,%1,%2,%3}, {%4,%5,%6,%7}, {%8,%9}, {%0,%1,%2,%3};"
      : "+f"(c[0]), "+f"(c[1]), "+f"(c[2]), "+f"(c[3])
      : "r"(a[0]), "r"(a[1]), "r"(a[2]), "r"(a[3]), "r"(b[0]), "r"(b[1]));
}
#define CP_COMMIT() asm volatile("cp.async.commit_group;" ::: "memory")
#define CP_WAIT(n)  asm volatile("cp.async.wait_group %0;" :: "n"(n) : "memory")

// Packed fp32x2 (Blackwell FFMA2 path; base PTX, sm_100+)
__device__ __forceinline__ unsigned long long ffma2(unsigned long long a, unsigned long long b,
                                                    unsigned long long c) {
  unsigned long long d;
  asm("fma.rn.f32x2 %0, %1, %2, %3;" : "=l"(d) : "l"(a), "l"(b), "l"(c));
  return d;
}
__device__ __forceinline__ unsigned long long fadd2(unsigned long long a, unsigned long long b) {
  unsigned long long d;
  asm("add.rn.f32x2 %0, %1, %2;" : "=l"(d) : "l"(a), "l"(b));
  return d;
}
__device__ __forceinline__ void lds_v2b64(unsigned long long& a, unsigned long long& b, uint32_t addr) {
  asm volatile("ld.shared.v2.b64 {%0,%1}, [%2];" : "=l"(a), "=l"(b) : "r"(addr));
}
__device__ __forceinline__ float2 unpack2(unsigned long long v) {
  float2 f;
  asm("mov.b64 {%0,%1}, %2;" : "=f"(f.x), "=f"(f.y) : "l"(v));
  return f;
}
__device__ __forceinline__ unsigned long long pack2(float x, float y) {
  unsigned long long v;
  asm("mov.b64 %0, {%1,%2};" : "=l"(v) : "f"(x), "f"(y));
  return v;
}

// SW64 swizzle for 64-byte rows (conflict-free ldmatrix over 8-row atoms)
__device__ __forceinline__ uint32_t sw64(uint32_t bo) { return bo ^ ((bo >> 3) & 0x30); }

// ---------------------------------------------------------------------------
// Fused fp32 -> (bf16 hi, bf16 lo) split for all four input tensors.
// ---------------------------------------------------------------------------
#define CVT_N4_D   8192
#define CVT_N4_W1  25600
#define CVT_N4_W2  2560000
#define CVT_N4_W3  400000
#define CVT_C1 (CVT_N4_D)
#define CVT_C2 (CVT_C1 + CVT_N4_W1)
#define CVT_C3 (CVT_C2 + CVT_N4_W2)
#define CVT_C4 (CVT_C3 + CVT_N4_W3)

__global__ void cvt_all(const float* __restrict__ d, const float* __restrict__ W1,
                        const float* __restrict__ W2, const float* __restrict__ W3,
                        __nv_bfloat16* dh, __nv_bfloat16* dl,
                        __nv_bfloat16* w1h, __nv_bfloat16* w1l,
                        __nv_bfloat16* w2h, __nv_bfloat16* w2l,
                        __nv_bfloat16* w3h, __nv_bfloat16* w3l) {
  int i = blockIdx.x * 256 + threadIdx.x;
  const float* src;
  __nv_bfloat16 *ph, *pl;
  int off;
  if (i < CVT_C1)      { src = d;  ph = dh;  pl = dl;  off = i; }
  else if (i < CVT_C2) { src = W1; ph = w1h; pl = w1l; off = i - CVT_C1; }
  else if (i < CVT_C3) { src = W2; ph = w2h; pl = w2l; off = i - CVT_C2; }
  else if (i < CVT_C4) { src = W3; ph = w3h; pl = w3l; off = i - CVT_C3; }
  else return;
  float4 v = reinterpret_cast<const float4*>(src)[off];
  __nv_bfloat16 h0 = __float2bfloat16_rn(v.x), h1 = __float2bfloat16_rn(v.y);
  __nv_bfloat16 h2 = __float2bfloat16_rn(v.z), h3 = __float2bfloat16_rn(v.w);
  __nv_bfloat16 l0 = __float2bfloat16_rn(v.x - __bfloat162float(h0));
  __nv_bfloat16 l1 = __float2bfloat16_rn(v.y - __bfloat162float(h1));
  __nv_bfloat16 l2 = __float2bfloat16_rn(v.z - __bfloat162float(h2));
  __nv_bfloat16 l3 = __float2bfloat16_rn(v.w - __bfloat162float(h3));
  uint2 phv, plv;
  phv.x = ((uint32_t)__bfloat16_as_ushort(h1) << 16) | __bfloat16_as_ushort(h0);
  phv.y = ((uint32_t)__bfloat16_as_ushort(h3) << 16) | __bfloat16_as_ushort(h2);
  plv.x = ((uint32_t)__bfloat16_as_ushort(l1) << 16) | __bfloat16_as_ushort(l0);
  plv.y = ((uint32_t)__bfloat16_as_ushort(l3) << 16) | __bfloat16_as_ushort(l2);
  reinterpret_cast<uint2*>(ph)[off] = phv;
  reinterpret_cast<uint2*>(pl)[off] = plv;
}

// ---------------------------------------------------------------------------
// Async tile loader: ROWS x 32 bf16 (64 B/row), SW64 swizzle, cp.async 16B
// ---------------------------------------------------------------------------
template <int ROWS>
__device__ __forceinline__ void load_tile_async(uint32_t tile, const __nv_bfloat16* __restrict__ g,
                                                int row0, int rmax, int ldk, int k0, int kend,
                                                int tid) {
  constexpr int NV = ROWS * 4;     // 16B vectors per tile
#pragma unroll
  for (int t = 0; t < NV / 256; t++) {
    int v = tid + t * 256;
    int r = v >> 2;                 // tile row
    int cs = v & 3;                 // 16B segment (4 per 64B row)
    int gr = row0 + r;
    int gk = k0 + cs * 8;
    uint32_t dst = tile + sw64(((uint32_t)r << 6) + ((uint32_t)cs << 4));
    if (gr < rmax && gk < kend) {
      const void* src = g + (size_t)gr * ldk + gk;
      asm volatile("cp.async.cg.shared.global [%0], [%1], 16;" :: "r"(dst), "l"(src));
    } else {
      asm volatile("st.shared.v4.b32 [%0], {%1,%1,%1,%1};" :: "r"(dst), "r"(0u));
    }
  }
}

// ---------------------------------------------------------------------------
// bf16x3 split GEMM via mma.sync m16n8k16.
// Tile 64M x 128N, BK=32, 3-stage cp.async, 3 CTAs/SM (400 CTAs -> 1 wave).
// 8 warps in (2 warp_m x 4 warp_n): each warp 32M x 32N (2 m-tiles x 4 n-tiles)
//  -> A and B fragments each re-read only 2x (8 B/output LDS traffic).
// MODE 0: full-K, bias+lrelu, emit bf16 hi/lo. MODE 1: split-K fp32 partials.
// ---------------------------------------------------------------------------
#define STAGE_B 24576  // Ah 4KB | Al 4KB | Bh 8KB | Bl 8KB

template <int MODE>
__global__ __launch_bounds__(256, 3)
void mma_gemm(const __nv_bfloat16* __restrict__ Ah, const __nv_bfloat16* __restrict__ Al,
              const __nv_bfloat16* __restrict__ Bh, const __nv_bfloat16* __restrict__ Bl,
              const float* __restrict__ bias, float* __restrict__ Pf,
              __nv_bfloat16* __restrict__ Ch, __nv_bfloat16* __restrict__ Cl,
              int M, int N, int K, int kchunk) {
  extern __shared__ char smem[];
  const uint32_t sb = smem_u32(smem);
  const int tid = threadIdx.x, wid = tid >> 5, lane = tid & 31;
  const int m0 = blockIdx.y * 64, n0 = blockIdx.x * 128;
  const int warp_m = wid & 1;    // 2 x 32 rows
  const int warp_n = wid >> 1;   // 4 x 32 cols

  const int kbeg = (MODE == 1) ? blockIdx.z * kchunk : 0;
  const int kend = (kbeg + kchunk < K) ? (kbeg + kchunk) : K;
  const int NC = (kend - kbeg + 31) / 32;

  float acc[2][4][4];
#pragma unroll
  for (int mt = 0; mt < 2; mt++)
#pragma unroll
    for (int nt = 0; nt < 4; nt++)
#pragma unroll
      for (int i = 0; i < 4; i++) acc[mt][nt][i] = 0.f;

  // Prologue: stages 0,1
#pragma unroll
  for (int s = 0; s < 2; s++) {
    uint32_t tb = sb + s * STAGE_B;
    int k0 = kbeg + s * 32;
    load_tile_async<64>(tb + 0,      Ah, m0, M, K, k0, kend, tid);
    load_tile_async<64>(tb + 4096,   Al, m0, M, K, k0, kend, tid);
    load_tile_async<128>(tb + 8192,  Bh, n0, N, K, k0, kend, tid);
    load_tile_async<128>(tb + 16384, Bl, n0, N, K, k0, kend, tid);
    CP_COMMIT();
  }

  const int a_r = (lane & 15);
  const uint32_t a_koff = (lane & 16) ? 16u : 0u;
  const int b_r = ((lane & 16) ? 8 : 0) + (lane & 7);
  const uint32_t b_koff = (lane & 8) ? 16u : 0u;

  for (int c = 0; c < NC; c++) {
    if (c + 2 < NC) {
      uint32_t tb = sb + ((c + 2) % 3) * STAGE_B;
      int k0 = kbeg + (c + 2) * 32;
      load_tile_async<64>(tb + 0,      Ah, m0, M, K, k0, kend, tid);
      load_tile_async<64>(tb + 4096,   Al, m0, M, K, k0, kend, tid);
      load_tile_async<128>(tb + 8192,  Bh, n0, N, K, k0, kend, tid);
      load_tile_async<128>(tb + 16384, Bl, n0, N, K, k0, kend, tid);
      CP_COMMIT();
      CP_WAIT(2);
    } else if (c + 1 < NC) {
      CP_WAIT(1);
    } else {
      CP_WAIT(0);
    }
    __syncthreads();

    const uint32_t tb = sb + (c % 3) * STAGE_B;
#pragma unroll
    for (int ks = 0; ks < 2; ks++) {
      const uint32_t kb = ks * 32;
      uint32_t bh[8], bl[8];
#pragma unroll
      for (int g2 = 0; g2 < 2; g2++) {
        uint32_t sw = sw64(((uint32_t)(warp_n * 32 + g2 * 16 + b_r) << 6) + kb + b_koff);
        ldsm4(bh + g2 * 4, tb + 8192 + sw);
        ldsm4(bl + g2 * 4, tb + 16384 + sw);
      }
#pragma unroll
      for (int mt = 0; mt < 2; mt++) {
        uint32_t ah[4], al[4];
        uint32_t sw = sw64(((uint32_t)(warp_m * 32 + mt * 16 + a_r) << 6) + kb + a_koff);
        ldsm4(ah, tb + sw);
        ldsm4(al, tb + 4096 + sw);
#pragma unroll
        for (int nt = 0; nt < 4; nt++) {
          mma16816(acc[mt][nt], ah, bh + nt * 2);
          mma16816(acc[mt][nt], al, bh + nt * 2);
          mma16816(acc[mt][nt], ah, bl + nt * 2);
        }
      }
    }
    __syncthreads();
  }

  // Epilogue
#pragma unroll
  for (int mt = 0; mt < 2; mt++) {
#pragma unroll
    for (int nt = 0; nt < 4; nt++) {
      const int col = n0 + warp_n * 32 + nt * 8 + ((lane & 3) << 1);
      const int r0 = m0 + warp_m * 32 + mt * 16 + (lane >> 2);
#pragma unroll
      for (int h = 0; h < 2; h++) {
        const int row = r0 + h * 8;
        float v0 = acc[mt][nt][h * 2 + 0];
        float v1 = acc[mt][nt][h * 2 + 1];
        if (MODE == 0) {
          if (col < N) {
            v0 += bias[col];
            v1 += bias[col + 1];
            v0 = (v0 > 0.f) ? v0 : 0.1f * v0;
            v1 = (v1 > 0.f) ? v1 : 0.1f * v1;
            __nv_bfloat16 h0 = __float2bfloat16_rn(v0), h1 = __float2bfloat16_rn(v1);
            __nv_bfloat16 l0 = __float2bfloat16_rn(v0 - __bfloat162float(h0));
            __nv_bfloat16 l1 = __float2bfloat16_rn(v1 - __bfloat162float(h1));
            uint32_t ph = ((uint32_t)__bfloat16_as_ushort(h1) << 16) | __bfloat16_as_ushort(h0);
            uint32_t pl = ((uint32_t)__bfloat16_as_ushort(l1) << 16) | __bfloat16_as_ushort(l0);
            *reinterpret_cast<uint32_t*>(Ch + (size_t)row * N + col) = ph;
            *reinterpret_cast<uint32_t*>(Cl + (size_t)row * N + col) = pl;
          }
        } else {
          if (col < PSTRIDE) {
            float* dst = Pf + (size_t)blockIdx.z * BDIM * PSTRIDE + (size_t)row * PSTRIDE + col;
            *reinterpret_cast<float2*>(dst) = make_float2(v0, v1);
          }
        }
      }
    }
  }
}

// ---------------------------------------------------------------------------
// Setup: S = I + 0.5 * W W^T (30x30), invert via Gauss-Jordan. 1024 threads.
// ---------------------------------------------------------------------------
__global__ void setup_sinv(const float* __restrict__ W, float* __restrict__ Sinv) {
  __shared__ float aug[KDIM][64];
  __shared__ float fac[KDIM];
  __shared__ float pivinv;
  const int tid = threadIdx.x;  // 1024 threads

  if (tid < KDIM * KDIM) {
    int a = tid / KDIM, b = tid % KDIM;
    float s = 0.f;
    for (int j = 0; j < RDIM; j++) s += W[a * RDIM + j] * W[b * RDIM + j];
    aug[a][b] = 0.5f * s + (a == b ? 1.f : 0.f);
  }
  for (int idx = tid; idx < KDIM * 34; idx += 1024) {
    int a = idx / 34, c = 30 + idx % 34;
    aug[a][c] = (c - 30 == a) ? 1.f : 0.f;
  }
  __syncthreads();

  for (int i = 0; i < KDIM; i++) {
    if (tid == 0) pivinv = 1.f / aug[i][i];
    __syncthreads();
    if (tid < 64) aug[i][tid] *= pivinv;
    __syncthreads();
    if (tid < KDIM) fac[tid] = aug[tid][i];
    __syncthreads();
    for (int idx = tid; idx < KDIM * 64; idx += 1024) {
      int r = idx / 64, c = idx % 64;
      if (r != i) aug[r][c] -= fac[r] * aug[i][c];
    }
    __syncthreads();
  }
  for (int idx = tid; idx < KDIM * KDIM; idx += 1024)
    Sinv[idx] = aug[idx / KDIM][30 + idx % KDIM];
}

// ---------------------------------------------------------------------------
// Persistent ADMM kernel — 512 threads, 8 rows/block, 128 blocks.
//  * deterministic early exit: block leaves once max|Δp| < ADMM_EPS
//  * M1: warps = (row-pair x k-quarter); pr/ps in registers; FFMA2 matvecs
// ---------------------------------------------------------------------------
#define AROWS 8

__global__ __launch_bounds__(512, 1)
void admm_kernel(const float* __restrict__ costP, const float* __restrict__ b3,
                 const float* __restrict__ W, const float* __restrict__ cap,
                 const float* __restrict__ SinvG, float* __restrict__ out) {
  extern __shared__ float sm[];
  float* Ws   = sm;                     // [32][512] (rows 30,31 zero)
  float* ev   = Ws + 32 * 512;          // [8][512]
  float* cst  = ev + AROWS * 512;       // [8][512]
  float* pk   = cst + AROWS * 512;      // [8][32]
  float* gk   = pk + AROWS * 32;        // [8][32]
  float* ts   = gk + AROWS * 32;        // [8][32]
  float* y1s  = ts + AROWS * 32;        // [8][32] (lanes 30,31 stay zero)
  float* tcap = y1s + AROWS * 32;       // [32]
  float* Ssm  = tcap + 32;              // [30][33]
  float* wmax = Ssm + KDIM * 33;        // [24]

  const int tid = threadIdx.x;          // 0..511
  const int lane = tid & 31;
  const int wid = tid >> 5;             // 0..15
  const int row0 = blockIdx.x * AROWS;  // 128 blocks x 8 = 1024 exact
  const int j = tid;

  // ---- init ----
  for (int idx = tid; idx < 32 * 512; idx += 512) {
    int k = idx >> 9, jj = idx & 511;
    Ws[idx] = (k < KDIM && jj < RDIM) ? W[k * RDIM + jj] : 0.f;
  }
#pragma unroll
  for (int r = 0; r < AROWS; r++) {
    float cv = 0.f;
    if (j < RDIM) {
      cv = b3[j];
#pragma unroll
      for (int z = 0; z < KSPLIT; z++)
        cv += costP[(size_t)z * BDIM * PSTRIDE + (size_t)(row0 + r) * PSTRIDE + j];
    }
    cst[r * 512 + j] = cv;
    ev[r * 512 + j] = cv;   // p = 0 -> e = cost
  }
  for (int idx = tid; idx < KDIM * 33; idx += 512) {
    int k = idx / 33, m = idx % 33;
    Ssm[idx] = (m < KDIM) ? SinvG[k * KDIM + m] : 0.f;
  }
  for (int idx = tid; idx < AROWS * 32; idx += 512) {
    pk[idx] = 0.f; gk[idx] = 0.f; ts[idx] = 0.f; y1s[idx] = 0.f;
  }
  if (tid < 24) wmax[tid] = 1e30f;
  __syncthreads();

  // tcap_k = (sum_j W[k][j]) - 2*cap_k
  {
    int k = wid * 2;
#pragma unroll
    for (int q = 0; q < 2; q++, k++) {
      if (k < KDIM) {
        float s = 0.f;
#pragma unroll
        for (int m = 0; m < 16; m++) s += Ws[k * 512 + lane + 32 * m];
#pragma unroll
        for (int o = 16; o > 0; o >>= 1) s += __shfl_down_sync(0xffffffffu, s, o);
        if (lane == 0) tcap[k] = s - 2.f * cap[k];
      }
    }
  }
  __syncthreads();

  // M2 weights: Wr2[kk] = (Ws[2kk][j], Ws[2kk+1][j]) (k up to 31, zero-padded)
  unsigned long long Wr2[16];
#pragma unroll
  for (int kk = 0; kk < 16; kk++)
    Wr2[kk] = pack2(Ws[(2 * kk) * 512 + j], Ws[(2 * kk + 1) * 512 + j]);

  // Per-thread persistent state (owner thread = j)
  float prr[AROWS], psr[AROWS];
#pragma unroll
  for (int r = 0; r < AROWS; r++) { prr[r] = 0.f; psr[r] = 0.f; }

  const int rp = wid & 3;        // row-pair index -> rows 2rp, 2rp+1
  const int kq = wid >> 2;       // k-quarter -> k = 8kq .. 8kq+7
  const int r0m = 2 * rp, r1m = 2 * rp + 1;
  const uint32_t ws_a = smem_u32(Ws);
  const uint32_t ev_a = smem_u32(ev);
  const uint32_t y_a  = smem_u32(y1s);

  bool conv = false;
  for (int it = 0; it < NITER; it++) {
    const bool last = conv || (it == NITER - 1);

    // ---- M1: gk[r][k] = sum_j W[k][j] e[r][j] ----
    {
      unsigned long long e0[8], e1[8];
      const uint32_t eb0 = ev_a + ((uint32_t)(r0m * 512 + lane * 4) << 2);
      const uint32_t eb1 = ev_a + ((uint32_t)(r1m * 512 + lane * 4) << 2);
#pragma unroll
      for (int s = 0; s < 4; s++) {
        lds_v2b64(e0[2 * s], e0[2 * s + 1], eb0 + 512 * s);
        lds_v2b64(e1[2 * s], e1[2 * s + 1], eb1 + 512 * s);
      }
#pragma unroll
      for (int kk = 0; kk < 8; kk++) {
        const int k = kq * 8 + kk;
        const uint32_t wb = ws_a + ((uint32_t)(k * 512 + lane * 4) << 2);
        unsigned long long a00 = 0ull, a01 = 0ull, a10 = 0ull, a11 = 0ull, w0, w1;
#pragma unroll
        for (int s = 0; s < 4; s++) {
          lds_v2b64(w0, w1, wb + 512 * s);
          a00 = ffma2(w0, e0[2 * s], a00);
          a01 = ffma2(w1, e0[2 * s + 1], a01);
          a10 = ffma2(w0, e1[2 * s], a10);
          a11 = ffma2(w1, e1[2 * s + 1], a11);
        }
        float2 f0 = unpack2(fadd2(a00, a01));
        float2 f1 = unpack2(fadd2(a10, a11));
        float v0 = f0.x + f0.y;
        float v1 = f1.x + f1.y;
#pragma unroll
        for (int o = 16; o > 0; o >>= 1) {
          v0 += __shfl_down_sync(0xffffffffu, v0, o);
          v1 += __shfl_down_sync(0xffffffffu, v1, o);
        }
        if (lane == 0) { gk[r0m * 32 + k] = v0; gk[r1m * 32 + k] = v1; }
      }
    }
    __syncthreads();

    // ---- Solve: y1 = Sinv(0.5*gk + |p_k| + tcap); p_k update (warps 0..7) ----
    if (wid < AROWS) {
      const int r = wid;
      float pkv = 0.f;
      if (lane < KDIM) {
        pkv = pk[r * 32 + lane];
        ts[r * 32 + lane] = 0.5f * gk[r * 32 + lane] + fabsf(pkv) + tcap[lane];
      }
      __syncwarp(0xffffffffu);
      float dk = 0.f;
      if (lane < KDIM) {
        float y = 0.f;
#pragma unroll
        for (int m = 0; m < KDIM; m++) y += Ssm[lane * 33 + m] * ts[r * 32 + m];
        y1s[r * 32 + lane] = y;
        float xk = 0.5f * (fabsf(pkv) - y);
        float npk = xk + fminf(pkv, 0.f);
        pk[r * 32 + lane] = npk;
        dk = fabsf(npk - pkv);
        if (last)
          out[(size_t)(row0 + r) * N2_DIM + RDIM + lane] = xk;
      }
#pragma unroll
      for (int o = 16; o > 0; o >>= 1) dk = fmaxf(dk, __shfl_down_sync(0xffffffffu, dk, o));
      if (lane == 0) wmax[16 + r] = dk;
    }
    __syncthreads();

    // ---- M2+E: wt_j = (W^T y1)_j; update p_r/p_s (regs); recompute e ----
    float dm = 0.f;
#pragma unroll
    for (int r = 0; r < AROWS; r++) {
      unsigned long long a0 = 0ull, a1 = 0ull, y0, y1v;
      const uint32_t yb = y_a + (uint32_t)(r * 128);
#pragma unroll
      for (int kk8 = 0; kk8 < 8; kk8++) {
        lds_v2b64(y0, y1v, yb + kk8 * 16);
        a0 = ffma2(Wr2[2 * kk8], y0, a0);
        a1 = ffma2(Wr2[2 * kk8 + 1], y1v, a1);
      }
      float2 f = unpack2(fadd2(a0, a1));
      float wt = f.x + f.y;

      float e0 = ev[r * 512 + j];
      float xr = 0.25f * (e0 - wt) + 0.5f;
      float xs = 1.f - xr;
      float np = xr + fminf(prr[r], 0.f);
      float ns = xs + fminf(psr[r], 0.f);
      dm = fmaxf(dm, fmaxf(fabsf(np - prr[r]), fabsf(ns - psr[r])));
      prr[r] = np;
      psr[r] = ns;
      ev[r * 512 + j] = cst[r * 512 + j] + fabsf(np) - fabsf(ns);
      if (last && j < RDIM) {
        out[(size_t)(row0 + r) * N2_DIM + j] = xr;
        out[(size_t)(row0 + r) * N2_DIM + RDIM + KDIM + j] = xs;
      }
    }
#pragma unroll
    for (int o = 16; o > 0; o >>= 1) dm = fmaxf(dm, __shfl_down_sync(0xffffffffu, dm, o));
    if (lane == 0) wmax[wid] = dm;
    __syncthreads();

    if (last) break;
    float mx = 0.f;
#pragma unroll
    for (int q = 0; q < 24; q++) mx = fmaxf(mx, wmax[q]);
    conv = (mx < ADMM_EPS);
  }
}

// ---------------------------------------------------------------------------
extern "C" void kernel_launch(void* const* d_in, const int* in_sizes, int n_in,
                              void* d_out, int out_size) {
  const float* d   = (const float*)d_in[0];  // [1024,32]
  const float* W1  = (const float*)d_in[1];  // [3200,32]
  const float* b1  = (const float*)d_in[2];  // [3200]
  const float* W2  = (const float*)d_in[3];  // [3200,3200]
  const float* b2  = (const float*)d_in[4];  // [3200]
  const float* W3  = (const float*)d_in[5];  // [500,3200]
  const float* b3  = (const float*)d_in[6];  // [500]
  const float* Wm  = (const float*)d_in[7];  // [30,500]
  const float* cap = (const float*)d_in[8];  // [30]
  float* out = (float*)d_out;                // [1024,1030]

  __nv_bfloat16 *dh, *dl, *w1h, *w1l, *w2h, *w2l, *w3h, *w3l, *h1h, *h1l, *h2h, *h2l;
  float *costP, *sinv;
  cudaGetSymbolAddress((void**)&dh, g_dh);   cudaGetSymbolAddress((void**)&dl, g_dl);
  cudaGetSymbolAddress((void**)&w1h, g_W1h); cudaGetSymbolAddress((void**)&w1l, g_W1l);
  cudaGetSymbolAddress((void**)&w2h, g_W2h); cudaGetSymbolAddress((void**)&w2l, g_W2l);
  cudaGetSymbolAddress((void**)&w3h, g_W3h); cudaGetSymbolAddress((void**)&w3l, g_W3l);
  cudaGetSymbolAddress((void**)&h1h, g_h1h); cudaGetSymbolAddress((void**)&h1l, g_h1l);
  cudaGetSymbolAddress((void**)&h2h, g_h2h); cudaGetSymbolAddress((void**)&h2l, g_h2l);
  cudaGetSymbolAddress((void**)&costP, g_costP);
  cudaGetSymbolAddress((void**)&sinv, g_Sinv);

  // 1) Fused hi/lo bf16 splits of all inputs
  cvt_all<<<(CVT_C4 + 255) / 256, 256>>>(d, W1, W2, W3, dh, dl, w1h, w1l, w2h, w2l, w3h, w3l);

  // 2) Sinv = (I + 0.5 W W^T)^-1
  setup_sinv<<<1, 1024>>>(Wm, sinv);

  const int gemm_smem = 3 * STAGE_B;  // 73728 B
  cudaFuncSetAttribute(mma_gemm<0>, cudaFuncAttributeMaxDynamicSharedMemorySize, gemm_smem);
  cudaFuncSetAttribute(mma_gemm<1>, cudaFuncAttributeMaxDynamicSharedMemorySize, gemm_smem);

  // 3-5) MLP on tensor cores (bf16x3 split via mma.sync); 64M x 128N tiles, 3 CTA/SM
  mma_gemm<0><<<dim3(HDIM / 128, BDIM / 64), 256, gemm_smem>>>(
      dh, dl, w1h, w1l, b1, nullptr, h1h, h1l, BDIM, HDIM, CDIM, CDIM);
  mma_gemm<0><<<dim3(HDIM / 128, BDIM / 64), 256, gemm_smem>>>(
      h1h, h1l, w2h, w2l, b2, nullptr, h2h, h2l, BDIM, HDIM, HDIM, HDIM);
  mma_gemm<1><<<dim3((RDIM + 127) / 128, BDIM / 64, KSPLIT), 256, gemm_smem>>>(
      h2h, h2l, w3h, w3l, nullptr, costP, nullptr, nullptr, BDIM, RDIM, HDIM, HDIM / KSPLIT);

  // 6) ADMM (persistent; early exit on block convergence)
  const int admm_smem = (32 * 512 + 2 * AROWS * 512 + 4 * AROWS * 32 + 32 + KDIM * 33 + 24) * (int)sizeof(float);
  cudaFuncSetAttribute(admm_kernel, cudaFuncAttributeMaxDynamicSharedMemorySize, admm_smem);
  admm_kernel<<<BDIM / AROWS, 512, admm_smem>>>(costP, b3, Wm, cap, sinv, out);
}

// round 13
// speedup vs baseline: 6.5033x; 1.0700x over previous
#include <cuda_runtime.h>
#include <cuda_bf16.h>
#include <cstdint>

// Problem constants
#define CDIM 32
#define HDIM 3200
#define BDIM 1024
#define RDIM 500
#define KDIM 30
#define N2_DIM 1030
#define NITER 200
#define KSPLIT 4
#define PSTRIDE 512
#define ADMM_EPS 2.5e-4f

// ---------------------------------------------------------------------------
// Device-global scratch (no allocation allowed)
// ---------------------------------------------------------------------------
__device__ __nv_bfloat16 g_dh[BDIM * CDIM],  g_dl[BDIM * CDIM];
__device__ __nv_bfloat16 g_W1h[HDIM * CDIM], g_W1l[HDIM * CDIM];
__device__ __nv_bfloat16 g_W2h[HDIM * HDIM], g_W2l[HDIM * HDIM];
__device__ __nv_bfloat16 g_W3h[RDIM * HDIM], g_W3l[RDIM * HDIM];
__device__ __nv_bfloat16 g_h1h[BDIM * HDIM], g_h1l[BDIM * HDIM];
__device__ __nv_bfloat16 g_h2h[BDIM * HDIM], g_h2l[BDIM * HDIM];
__device__ float g_costP[KSPLIT * BDIM * PSTRIDE];
__device__ float g_Sinv[KDIM * KDIM];

// ---------------------------------------------------------------------------
// PTX helpers (plain sm_80+/sm_100 base features — no arch-'a' gated instrs)
// ---------------------------------------------------------------------------
__device__ __forceinline__ uint32_t smem_u32(const void* p) {
  uint32_t a;
  asm("{ .reg .u64 t; cvta.to.shared.u64 t, %1; cvt.u32.u64 %0, t; }" : "=r"(a) : "l"(p));
  return a;
}
__device__ __forceinline__ void ldsm4(uint32_t* r, uint32_t a) {
  asm volatile("ldmatrix.sync.aligned.m8n8.x4.shared.b16 {%0,%1,%2,%3}, [%4];"
               : "=r"(r[0]), "=r"(r[1]), "=r"(r[2]), "=r"(r[3]) : "r"(a));
}
__device__ __forceinline__ void mma16816(float* c, const uint32_t* a, const uint32_t* b) {
  asm volatile(
      "mma.sync.aligned.m16n8k16.row.col.f32.bf16.bf16.f32 "
      "{%0,%1,%2,%3}, {%4,%5,%6,%7}, {%8,%9}, {%0,%1,%2,%3};"
      : "+f"(c[0]), "+f"(c[1]), "+f"(c[2]), "+f"(c[3])
      : "r"(a[0]), "r"(a[1]), "r"(a[2]), "r"(a[3]), "r"(b[0]), "r"(b[1]));
}
#define CP_COMMIT() asm volatile("cp.async.commit_group;" ::: "memory")
#define CP_WAIT(n)  asm volatile("cp.async.wait_group %0;" :: "n"(n) : "memory")

// Packed fp32x2 (Blackwell FFMA2 path; base PTX, sm_100+)
__device__ __forceinline__ unsigned long long ffma2(unsigned long long a, unsigned long long b,
                                                    unsigned long long c) {
  unsigned long long d;
  asm("fma.rn.f32x2 %0, %1, %2, %3;" : "=l"(d) : "l"(a), "l"(b), "l"(c));
  return d;
}
__device__ __forceinline__ unsigned long long fadd2(unsigned long long a, unsigned long long b) {
  unsigned long long d;
  asm("add.rn.f32x2 %0, %1, %2;" : "=l"(d) : "l"(a), "l"(b));
  return d;
}
__device__ __forceinline__ void lds_v2b64(unsigned long long& a, unsigned long long& b, uint32_t addr) {
  asm volatile("ld.shared.v2.b64 {%0,%1}, [%2];" : "=l"(a), "=l"(b) : "r"(addr));
}
__device__ __forceinline__ float2 unpack2(unsigned long long v) {
  float2 f;
  asm("mov.b64 {%0,%1}, %2;" : "=f"(f.x), "=f"(f.y) : "l"(v));
  return f;
}
__device__ __forceinline__ unsigned long long pack2(float x, float y) {
  unsigned long long v;
  asm("mov.b64 %0, {%1,%2};" : "=l"(v) : "f"(x), "f"(y));
  return v;
}

// SW64 swizzle for 64-byte rows (conflict-free ldmatrix over 8-row atoms)
__device__ __forceinline__ uint32_t sw64(uint32_t bo) { return bo ^ ((bo >> 3) & 0x30); }

// ---------------------------------------------------------------------------
// Fused fp32 -> (bf16 hi, bf16 lo) split for all four input tensors.
// ---------------------------------------------------------------------------
#define CVT_N4_D   8192
#define CVT_N4_W1  25600
#define CVT_N4_W2  2560000
#define CVT_N4_W3  400000
#define CVT_C1 (CVT_N4_D)
#define CVT_C2 (CVT_C1 + CVT_N4_W1)
#define CVT_C3 (CVT_C2 + CVT_N4_W2)
#define CVT_C4 (CVT_C3 + CVT_N4_W3)

__global__ void cvt_all(const float* __restrict__ d, const float* __restrict__ W1,
                        const float* __restrict__ W2, const float* __restrict__ W3,
                        __nv_bfloat16* dh, __nv_bfloat16* dl,
                        __nv_bfloat16* w1h, __nv_bfloat16* w1l,
                        __nv_bfloat16* w2h, __nv_bfloat16* w2l,
                        __nv_bfloat16* w3h, __nv_bfloat16* w3l) {
  int i = blockIdx.x * 256 + threadIdx.x;
  const float* src;
  __nv_bfloat16 *ph, *pl;
  int off;
  if (i < CVT_C1)      { src = d;  ph = dh;  pl = dl;  off = i; }
  else if (i < CVT_C2) { src = W1; ph = w1h; pl = w1l; off = i - CVT_C1; }
  else if (i < CVT_C3) { src = W2; ph = w2h; pl = w2l; off = i - CVT_C2; }
  else if (i < CVT_C4) { src = W3; ph = w3h; pl = w3l; off = i - CVT_C3; }
  else return;
  float4 v = reinterpret_cast<const float4*>(src)[off];
  __nv_bfloat16 h0 = __float2bfloat16_rn(v.x), h1 = __float2bfloat16_rn(v.y);
  __nv_bfloat16 h2 = __float2bfloat16_rn(v.z), h3 = __float2bfloat16_rn(v.w);
  __nv_bfloat16 l0 = __float2bfloat16_rn(v.x - __bfloat162float(h0));
  __nv_bfloat16 l1 = __float2bfloat16_rn(v.y - __bfloat162float(h1));
  __nv_bfloat16 l2 = __float2bfloat16_rn(v.z - __bfloat162float(h2));
  __nv_bfloat16 l3 = __float2bfloat16_rn(v.w - __bfloat162float(h3));
  uint2 phv, plv;
  phv.x = ((uint32_t)__bfloat16_as_ushort(h1) << 16) | __bfloat16_as_ushort(h0);
  phv.y = ((uint32_t)__bfloat16_as_ushort(h3) << 16) | __bfloat16_as_ushort(h2);
  plv.x = ((uint32_t)__bfloat16_as_ushort(l1) << 16) | __bfloat16_as_ushort(l0);
  plv.y = ((uint32_t)__bfloat16_as_ushort(l3) << 16) | __bfloat16_as_ushort(l2);
  reinterpret_cast<uint2*>(ph)[off] = phv;
  reinterpret_cast<uint2*>(pl)[off] = plv;
}

// ---------------------------------------------------------------------------
// Async tile loader: ROWS x 32 bf16 (64 B/row), SW64 swizzle, cp.async 16B
// ---------------------------------------------------------------------------
template <int ROWS>
__device__ __forceinline__ void load_tile_async(uint32_t tile, const __nv_bfloat16* __restrict__ g,
                                                int row0, int rmax, int ldk, int k0, int kend,
                                                int tid) {
  constexpr int NV = ROWS * 4;     // 16B vectors per tile
#pragma unroll
  for (int t = 0; t < NV / 256; t++) {
    int v = tid + t * 256;
    int r = v >> 2;                 // tile row
    int cs = v & 3;                 // 16B segment (4 per 64B row)
    int gr = row0 + r;
    int gk = k0 + cs * 8;
    uint32_t dst = tile + sw64(((uint32_t)r << 6) + ((uint32_t)cs << 4));
    if (gr < rmax && gk < kend) {
      const void* src = g + (size_t)gr * ldk + gk;
      asm volatile("cp.async.cg.shared.global [%0], [%1], 16;" :: "r"(dst), "l"(src));
    } else {
      asm volatile("st.shared.v4.b32 [%0], {%1,%1,%1,%1};" :: "r"(dst), "r"(0u));
    }
  }
}

// ---------------------------------------------------------------------------
// bf16x3 split GEMM via mma.sync m16n8k16.
// Tile 64M x 128N, BK=32, 3-stage cp.async, 3 CTAs/SM (400 CTAs -> 1 wave).
// 8 warps in (2 warp_m x 4 warp_n): each warp 32M x 32N.
// MODE 0: full-K, bias+lrelu, emit bf16 hi/lo. MODE 1: split-K fp32 partials.
// ---------------------------------------------------------------------------
#define STAGE_B 24576  // Ah 4KB | Al 4KB | Bh 8KB | Bl 8KB

template <int MODE>
__global__ __launch_bounds__(256, 3)
void mma_gemm(const __nv_bfloat16* __restrict__ Ah, const __nv_bfloat16* __restrict__ Al,
              const __nv_bfloat16* __restrict__ Bh, const __nv_bfloat16* __restrict__ Bl,
              const float* __restrict__ bias, float* __restrict__ Pf,
              __nv_bfloat16* __restrict__ Ch, __nv_bfloat16* __restrict__ Cl,
              int M, int N, int K, int kchunk) {
  extern __shared__ char smem[];
  const uint32_t sb = smem_u32(smem);
  const int tid = threadIdx.x, wid = tid >> 5, lane = tid & 31;
  const int m0 = blockIdx.y * 64, n0 = blockIdx.x * 128;
  const int warp_m = wid & 1;    // 2 x 32 rows
  const int warp_n = wid >> 1;   // 4 x 32 cols

  const int kbeg = (MODE == 1) ? blockIdx.z * kchunk : 0;
  const int kend = (kbeg + kchunk < K) ? (kbeg + kchunk) : K;
  const int NC = (kend - kbeg + 31) / 32;

  float acc[2][4][4];
#pragma unroll
  for (int mt = 0; mt < 2; mt++)
#pragma unroll
    for (int nt = 0; nt < 4; nt++)
#pragma unroll
      for (int i = 0; i < 4; i++) acc[mt][nt][i] = 0.f;

  // Prologue: stages 0,1 (skip stage 1 entirely if K fits in one chunk)
#pragma unroll
  for (int s = 0; s < 2; s++) {
    if (s == 1 && NC < 2) break;
    uint32_t tb = sb + s * STAGE_B;
    int k0 = kbeg + s * 32;
    load_tile_async<64>(tb + 0,      Ah, m0, M, K, k0, kend, tid);
    load_tile_async<64>(tb + 4096,   Al, m0, M, K, k0, kend, tid);
    load_tile_async<128>(tb + 8192,  Bh, n0, N, K, k0, kend, tid);
    load_tile_async<128>(tb + 16384, Bl, n0, N, K, k0, kend, tid);
    CP_COMMIT();
  }

  const int a_r = (lane & 15);
  const uint32_t a_koff = (lane & 16) ? 16u : 0u;
  const int b_r = ((lane & 16) ? 8 : 0) + (lane & 7);
  const uint32_t b_koff = (lane & 8) ? 16u : 0u;

  for (int c = 0; c < NC; c++) {
    if (c + 2 < NC) {
      uint32_t tb = sb + ((c + 2) % 3) * STAGE_B;
      int k0 = kbeg + (c + 2) * 32;
      load_tile_async<64>(tb + 0,      Ah, m0, M, K, k0, kend, tid);
      load_tile_async<64>(tb + 4096,   Al, m0, M, K, k0, kend, tid);
      load_tile_async<128>(tb + 8192,  Bh, n0, N, K, k0, kend, tid);
      load_tile_async<128>(tb + 16384, Bl, n0, N, K, k0, kend, tid);
      CP_COMMIT();
      CP_WAIT(2);
    } else if (c + 1 < NC) {
      CP_WAIT(1);
    } else {
      CP_WAIT(0);
    }
    __syncthreads();

    const uint32_t tb = sb + (c % 3) * STAGE_B;
#pragma unroll
    for (int ks = 0; ks < 2; ks++) {
      const uint32_t kb = ks * 32;
      uint32_t bh[8], bl[8];
#pragma unroll
      for (int g2 = 0; g2 < 2; g2++) {
        uint32_t sw = sw64(((uint32_t)(warp_n * 32 + g2 * 16 + b_r) << 6) + kb + b_koff);
        ldsm4(bh + g2 * 4, tb + 8192 + sw);
        ldsm4(bl + g2 * 4, tb + 16384 + sw);
      }
#pragma unroll
      for (int mt = 0; mt < 2; mt++) {
        uint32_t ah[4], al[4];
        uint32_t sw = sw64(((uint32_t)(warp_m * 32 + mt * 16 + a_r) << 6) + kb + a_koff);
        ldsm4(ah, tb + sw);
        ldsm4(al, tb + 4096 + sw);
#pragma unroll
        for (int nt = 0; nt < 4; nt++) {
          mma16816(acc[mt][nt], ah, bh + nt * 2);
          mma16816(acc[mt][nt], al, bh + nt * 2);
          mma16816(acc[mt][nt], ah, bl + nt * 2);
        }
      }
    }
    __syncthreads();
  }

  // Epilogue
#pragma unroll
  for (int mt = 0; mt < 2; mt++) {
#pragma unroll
    for (int nt = 0; nt < 4; nt++) {
      const int col = n0 + warp_n * 32 + nt * 8 + ((lane & 3) << 1);
      const int r0 = m0 + warp_m * 32 + mt * 16 + (lane >> 2);
#pragma unroll
      for (int h = 0; h < 2; h++) {
        const int row = r0 + h * 8;
        float v0 = acc[mt][nt][h * 2 + 0];
        float v1 = acc[mt][nt][h * 2 + 1];
        if (MODE == 0) {
          if (col < N) {
            v0 += bias[col];
            v1 += bias[col + 1];
            v0 = (v0 > 0.f) ? v0 : 0.1f * v0;
            v1 = (v1 > 0.f) ? v1 : 0.1f * v1;
            __nv_bfloat16 h0 = __float2bfloat16_rn(v0), h1 = __float2bfloat16_rn(v1);
            __nv_bfloat16 l0 = __float2bfloat16_rn(v0 - __bfloat162float(h0));
            __nv_bfloat16 l1 = __float2bfloat16_rn(v1 - __bfloat162float(h1));
            uint32_t ph = ((uint32_t)__bfloat16_as_ushort(h1) << 16) | __bfloat16_as_ushort(h0);
            uint32_t pl = ((uint32_t)__bfloat16_as_ushort(l1) << 16) | __bfloat16_as_ushort(l0);
            *reinterpret_cast<uint32_t*>(Ch + (size_t)row * N + col) = ph;
            *reinterpret_cast<uint32_t*>(Cl + (size_t)row * N + col) = pl;
          }
        } else {
          if (col < PSTRIDE) {
            float* dst = Pf + (size_t)blockIdx.z * BDIM * PSTRIDE + (size_t)row * PSTRIDE + col;
            *reinterpret_cast<float2*>(dst) = make_float2(v0, v1);
          }
        }
      }
    }
  }
}

// ---------------------------------------------------------------------------
// Setup: S = I + 0.5 * W W^T (30x30), invert via Gauss-Jordan. 1024 threads.
// ---------------------------------------------------------------------------
__global__ void setup_sinv(const float* __restrict__ W, float* __restrict__ Sinv) {
  __shared__ float aug[KDIM][64];
  __shared__ float fac[KDIM];
  __shared__ float pivinv;
  const int tid = threadIdx.x;  // 1024 threads

  if (tid < KDIM * KDIM) {
    int a = tid / KDIM, b = tid % KDIM;
    float s = 0.f;
    for (int j = 0; j < RDIM; j++) s += W[a * RDIM + j] * W[b * RDIM + j];
    aug[a][b] = 0.5f * s + (a == b ? 1.f : 0.f);
  }
  for (int idx = tid; idx < KDIM * 34; idx += 1024) {
    int a = idx / 34, c = 30 + idx % 34;
    aug[a][c] = (c - 30 == a) ? 1.f : 0.f;
  }
  __syncthreads();

  for (int i = 0; i < KDIM; i++) {
    if (tid == 0) pivinv = 1.f / aug[i][i];
    __syncthreads();
    if (tid < 64) aug[i][tid] *= pivinv;
    __syncthreads();
    if (tid < KDIM) fac[tid] = aug[tid][i];
    __syncthreads();
    for (int idx = tid; idx < KDIM * 64; idx += 1024) {
      int r = idx / 64, c = idx % 64;
      if (r != i) aug[r][c] -= fac[r] * aug[i][c];
    }
    __syncthreads();
  }
  for (int idx = tid; idx < KDIM * KDIM; idx += 1024)
    Sinv[idx] = aug[idx / KDIM][30 + idx % KDIM];
}

// ---------------------------------------------------------------------------
// Persistent ADMM kernel — 512 threads, 8 rows/block, 128 blocks.
//  * deterministic early exit: block leaves once max|Δp| < ADMM_EPS
//  * M1: warps = (row-pair x k-quarter); pr/ps in registers; FFMA2 matvecs
// ---------------------------------------------------------------------------
#define AROWS 8

__global__ __launch_bounds__(512, 1)
void admm_kernel(const float* __restrict__ costP, const float* __restrict__ b3,
                 const float* __restrict__ W, const float* __restrict__ cap,
                 const float* __restrict__ SinvG, float* __restrict__ out) {
  extern __shared__ float sm[];
  float* Ws   = sm;                     // [32][512] (rows 30,31 zero)
  float* ev   = Ws + 32 * 512;          // [8][512]
  float* cst  = ev + AROWS * 512;       // [8][512]
  float* pk   = cst + AROWS * 512;      // [8][32]
  float* gk   = pk + AROWS * 32;        // [8][32]
  float* ts   = gk + AROWS * 32;        // [8][32]
  float* y1s  = ts + AROWS * 32;        // [8][32] (lanes 30,31 stay zero)
  float* tcap = y1s + AROWS * 32;       // [32]
  float* Ssm  = tcap + 32;              // [30][33]
  float* wmax = Ssm + KDIM * 33;        // [24]

  const int tid = threadIdx.x;          // 0..511
  const int lane = tid & 31;
  const int wid = tid >> 5;             // 0..15
  const int row0 = blockIdx.x * AROWS;  // 128 blocks x 8 = 1024 exact
  const int j = tid;

  // ---- init ----
  for (int idx = tid; idx < 32 * 512; idx += 512) {
    int k = idx >> 9, jj = idx & 511;
    Ws[idx] = (k < KDIM && jj < RDIM) ? W[k * RDIM + jj] : 0.f;
  }
#pragma unroll
  for (int r = 0; r < AROWS; r++) {
    float cv = 0.f;
    if (j < RDIM) {
      cv = b3[j];
#pragma unroll
      for (int z = 0; z < KSPLIT; z++)
        cv += costP[(size_t)z * BDIM * PSTRIDE + (size_t)(row0 + r) * PSTRIDE + j];
    }
    cst[r * 512 + j] = cv;
    ev[r * 512 + j] = cv;   // p = 0 -> e = cost
  }
  for (int idx = tid; idx < KDIM * 33; idx += 512) {
    int k = idx / 33, m = idx % 33;
    Ssm[idx] = (m < KDIM) ? SinvG[k * KDIM + m] : 0.f;
  }
  for (int idx = tid; idx < AROWS * 32; idx += 512) {
    pk[idx] = 0.f; gk[idx] = 0.f; ts[idx] = 0.f; y1s[idx] = 0.f;
  }
  if (tid < 24) wmax[tid] = 1e30f;
  __syncthreads();

  // tcap_k = (sum_j W[k][j]) - 2*cap_k
  {
    int k = wid * 2;
#pragma unroll
    for (int q = 0; q < 2; q++, k++) {
      if (k < KDIM) {
        float s = 0.f;
#pragma unroll
        for (int m = 0; m < 16; m++) s += Ws[k * 512 + lane + 32 * m];
#pragma unroll
        for (int o = 16; o > 0; o >>= 1) s += __shfl_down_sync(0xffffffffu, s, o);
        if (lane == 0) tcap[k] = s - 2.f * cap[k];
      }
    }
  }
  __syncthreads();

  // M2 weights: Wr2[kk] = (Ws[2kk][j], Ws[2kk+1][j]) (k up to 31, zero-padded)
  unsigned long long Wr2[16];
#pragma unroll
  for (int kk = 0; kk < 16; kk++)
    Wr2[kk] = pack2(Ws[(2 * kk) * 512 + j], Ws[(2 * kk + 1) * 512 + j]);

  // Per-thread persistent state (owner thread = j)
  float prr[AROWS], psr[AROWS];
#pragma unroll
  for (int r = 0; r < AROWS; r++) { prr[r] = 0.f; psr[r] = 0.f; }

  const int rp = wid & 3;        // row-pair index -> rows 2rp, 2rp+1
  const int kq = wid >> 2;       // k-quarter -> k = 8kq .. 8kq+7
  const int r0m = 2 * rp, r1m = 2 * rp + 1;
  const uint32_t ws_a = smem_u32(Ws);
  const uint32_t ev_a = smem_u32(ev);
  const uint32_t y_a  = smem_u32(y1s);

  bool conv = false;
  for (int it = 0; it < NITER; it++) {
    const bool last = conv || (it == NITER - 1);

    // ---- M1: gk[r][k] = sum_j W[k][j] e[r][j] ----
    {
      unsigned long long e0[8], e1[8];
      const uint32_t eb0 = ev_a + ((uint32_t)(r0m * 512 + lane * 4) << 2);
      const uint32_t eb1 = ev_a + ((uint32_t)(r1m * 512 + lane * 4) << 2);
#pragma unroll
      for (int s = 0; s < 4; s++) {
        lds_v2b64(e0[2 * s], e0[2 * s + 1], eb0 + 512 * s);
        lds_v2b64(e1[2 * s], e1[2 * s + 1], eb1 + 512 * s);
      }
#pragma unroll
      for (int kk = 0; kk < 8; kk++) {
        const int k = kq * 8 + kk;
        const uint32_t wb = ws_a + ((uint32_t)(k * 512 + lane * 4) << 2);
        unsigned long long a00 = 0ull, a01 = 0ull, a10 = 0ull, a11 = 0ull, w0, w1;
#pragma unroll
        for (int s = 0; s < 4; s++) {
          lds_v2b64(w0, w1, wb + 512 * s);
          a00 = ffma2(w0, e0[2 * s], a00);
          a01 = ffma2(w1, e0[2 * s + 1], a01);
          a10 = ffma2(w0, e1[2 * s], a10);
          a11 = ffma2(w1, e1[2 * s + 1], a11);
        }
        float2 f0 = unpack2(fadd2(a00, a01));
        float2 f1 = unpack2(fadd2(a10, a11));
        float v0 = f0.x + f0.y;
        float v1 = f1.x + f1.y;
#pragma unroll
        for (int o = 16; o > 0; o >>= 1) {
          v0 += __shfl_down_sync(0xffffffffu, v0, o);
          v1 += __shfl_down_sync(0xffffffffu, v1, o);
        }
        if (lane == 0) { gk[r0m * 32 + k] = v0; gk[r1m * 32 + k] = v1; }
      }
    }
    __syncthreads();

    // ---- Solve: y1 = Sinv(0.5*gk + |p_k| + tcap); p_k update (warps 0..7) ----
    if (wid < AROWS) {
      const int r = wid;
      float pkv = 0.f;
      if (lane < KDIM) {
        pkv = pk[r * 32 + lane];
        ts[r * 32 + lane] = 0.5f * gk[r * 32 + lane] + fabsf(pkv) + tcap[lane];
      }
      __syncwarp(0xffffffffu);
      float dk = 0.f;
      if (lane < KDIM) {
        float y = 0.f;
#pragma unroll
        for (int m = 0; m < KDIM; m++) y += Ssm[lane * 33 + m] * ts[r * 32 + m];
        y1s[r * 32 + lane] = y;
        float xk = 0.5f * (fabsf(pkv) - y);
        float npk = xk + fminf(pkv, 0.f);
        pk[r * 32 + lane] = npk;
        dk = fabsf(npk - pkv);
        if (last)
          out[(size_t)(row0 + r) * N2_DIM + RDIM + lane] = xk;
      }
#pragma unroll
      for (int o = 16; o > 0; o >>= 1) dk = fmaxf(dk, __shfl_down_sync(0xffffffffu, dk, o));
      if (lane == 0) wmax[16 + r] = dk;
    }
    __syncthreads();

    // ---- M2+E: wt_j = (W^T y1)_j; update p_r/p_s (regs); recompute e ----
    float dm = 0.f;
#pragma unroll
    for (int r = 0; r < AROWS; r++) {
      unsigned long long a0 = 0ull, a1 = 0ull, y0, y1v;
      const uint32_t yb = y_a + (uint32_t)(r * 128);
#pragma unroll
      for (int kk8 = 0; kk8 < 8; kk8++) {
        lds_v2b64(y0, y1v, yb + kk8 * 16);
        a0 = ffma2(Wr2[2 * kk8], y0, a0);
        a1 = ffma2(Wr2[2 * kk8 + 1], y1v, a1);
      }
      float2 f = unpack2(fadd2(a0, a1));
      float wt = f.x + f.y;

      float e0 = ev[r * 512 + j];
      float xr = 0.25f * (e0 - wt) + 0.5f;
      float xs = 1.f - xr;
      float np = xr + fminf(prr[r], 0.f);
      float ns = xs + fminf(psr[r], 0.f);
      dm = fmaxf(dm, fmaxf(fabsf(np - prr[r]), fabsf(ns - psr[r])));
      prr[r] = np;
      psr[r] = ns;
      ev[r * 512 + j] = cst[r * 512 + j] + fabsf(np) - fabsf(ns);
      if (last && j < RDIM) {
        out[(size_t)(row0 + r) * N2_DIM + j] = xr;
        out[(size_t)(row0 + r) * N2_DIM + RDIM + KDIM + j] = xs;
      }
    }
#pragma unroll
    for (int o = 16; o > 0; o >>= 1) dm = fmaxf(dm, __shfl_down_sync(0xffffffffu, dm, o));
    if (lane == 0) wmax[wid] = dm;
    __syncthreads();

    if (last) break;
    float mx = 0.f;
#pragma unroll
    for (int q = 0; q < 24; q++) mx = fmaxf(mx, wmax[q]);
    conv = (mx < ADMM_EPS);
  }
}

// ---------------------------------------------------------------------------
extern "C" void kernel_launch(void* const* d_in, const int* in_sizes, int n_in,
                              void* d_out, int out_size) {
  const float* d   = (const float*)d_in[0];  // [1024,32]
  const float* W1  = (const float*)d_in[1];  // [3200,32]
  const float* b1  = (const float*)d_in[2];  // [3200]
  const float* W2  = (const float*)d_in[3];  // [3200,3200]
  const float* b2  = (const float*)d_in[4];  // [3200]
  const float* W3  = (const float*)d_in[5];  // [500,3200]
  const float* b3  = (const float*)d_in[6];  // [500]
  const float* Wm  = (const float*)d_in[7];  // [30,500]
  const float* cap = (const float*)d_in[8];  // [30]
  float* out = (float*)d_out;                // [1024,1030]

  __nv_bfloat16 *dh, *dl, *w1h, *w1l, *w2h, *w2l, *w3h, *w3l, *h1h, *h1l, *h2h, *h2l;
  float *costP, *sinv;
  cudaGetSymbolAddress((void**)&dh, g_dh);   cudaGetSymbolAddress((void**)&dl, g_dl);
  cudaGetSymbolAddress((void**)&w1h, g_W1h); cudaGetSymbolAddress((void**)&w1l, g_W1l);
  cudaGetSymbolAddress((void**)&w2h, g_W2h); cudaGetSymbolAddress((void**)&w2l, g_W2l);
  cudaGetSymbolAddress((void**)&w3h, g_W3h); cudaGetSymbolAddress((void**)&w3l, g_W3l);
  cudaGetSymbolAddress((void**)&h1h, g_h1h); cudaGetSymbolAddress((void**)&h1l, g_h1l);
  cudaGetSymbolAddress((void**)&h2h, g_h2h); cudaGetSymbolAddress((void**)&h2l, g_h2l);
  cudaGetSymbolAddress((void**)&costP, g_costP);
  cudaGetSymbolAddress((void**)&sinv, g_Sinv);

  // 1) Fused hi/lo bf16 splits of all inputs
  cvt_all<<<(CVT_C4 + 255) / 256, 256>>>(d, W1, W2, W3, dh, dl, w1h, w1l, w2h, w2l, w3h, w3l);

  // 2) Sinv = (I + 0.5 W W^T)^-1
  setup_sinv<<<1, 1024>>>(Wm, sinv);

  const int gemm_smem = 3 * STAGE_B;  // 73728 B
  cudaFuncSetAttribute(mma_gemm<0>, cudaFuncAttributeMaxDynamicSharedMemorySize, gemm_smem);
  cudaFuncSetAttribute(mma_gemm<1>, cudaFuncAttributeMaxDynamicSharedMemorySize, gemm_smem);

  // 3-5) MLP on tensor cores (bf16x3 split via mma.sync); 64M x 128N tiles, 3 CTA/SM
  mma_gemm<0><<<dim3(HDIM / 128, BDIM / 64), 256, gemm_smem>>>(
      dh, dl, w1h, w1l, b1, nullptr, h1h, h1l, BDIM, HDIM, CDIM, CDIM);
  mma_gemm<0><<<dim3(HDIM / 128, BDIM / 64), 256, gemm_smem>>>(
      h1h, h1l, w2h, w2l, b2, nullptr, h2h, h2l, BDIM, HDIM, HDIM, HDIM);
  mma_gemm<1><<<dim3((RDIM + 127) / 128, BDIM / 64, KSPLIT), 256, gemm_smem>>>(
      h2h, h2l, w3h, w3l, nullptr, costP, nullptr, nullptr, BDIM, RDIM, HDIM, HDIM / KSPLIT);

  // 6) ADMM (persistent; early exit on block convergence)
  const int admm_smem = (32 * 512 + 2 * AROWS * 512 + 4 * AROWS * 32 + 32 + KDIM * 33 + 24) * (int)sizeof(float);
  cudaFuncSetAttribute(admm_kernel, cudaFuncAttributeMaxDynamicSharedMemorySize, admm_smem);
  admm_kernel<<<BDIM / AROWS, 512, admm_smem>>>(costP, b3, Wm, cap, sinv, out);
}

// round 14
// speedup vs baseline: 6.8117x; 1.0474x over previous
#include <cuda_runtime.h>
#include <cuda_bf16.h>
#include <cstdint>

// Problem constants
#define CDIM 32
#define HDIM 3200
#define BDIM 1024
#define RDIM 500
#define KDIM 30
#define N2_DIM 1030
#define NITER 200
#define KSPLIT 4
#define PSTRIDE 512
#define ADMM_EPS 2.5e-4f
#define ALPHA 1.6f   // ADMM over-relaxation (fixed point unchanged)

// ---------------------------------------------------------------------------
// Device-global scratch (no allocation allowed)
// ---------------------------------------------------------------------------
__device__ __nv_bfloat16 g_dh[BDIM * CDIM],  g_dl[BDIM * CDIM];
__device__ __nv_bfloat16 g_W1h[HDIM * CDIM], g_W1l[HDIM * CDIM];
__device__ __nv_bfloat16 g_W2h[HDIM * HDIM], g_W2l[HDIM * HDIM];
__device__ __nv_bfloat16 g_W3h[RDIM * HDIM], g_W3l[RDIM * HDIM];
__device__ __nv_bfloat16 g_h1h[BDIM * HDIM], g_h1l[BDIM * HDIM];
__device__ __nv_bfloat16 g_h2h[BDIM * HDIM], g_h2l[BDIM * HDIM];
__device__ float g_costP[KSPLIT * BDIM * PSTRIDE];
__device__ float g_Sinv[KDIM * KDIM];

// ---------------------------------------------------------------------------
// PTX helpers (plain sm_80+/sm_100 base features — no arch-'a' gated instrs)
// ---------------------------------------------------------------------------
__device__ __forceinline__ uint32_t smem_u32(const void* p) {
  uint32_t a;
  asm("{ .reg .u64 t; cvta.to.shared.u64 t, %1; cvt.u32.u64 %0, t; }" : "=r"(a) : "l"(p));
  return a;
}
__device__ __forceinline__ void ldsm4(uint32_t* r, uint32_t a) {
  asm volatile("ldmatrix.sync.aligned.m8n8.x4.shared.b16 {%0,%1,%2,%3}, [%4];"
               : "=r"(r[0]), "=r"(r[1]), "=r"(r[2]), "=r"(r[3]) : "r"(a));
}
__device__ __forceinline__ void mma16816(float* c, const uint32_t* a, const uint32_t* b) {
  asm volatile(
      "mma.sync.aligned.m16n8k16.row.col.f32.bf16.bf16.f32 "
      "{%0,%1,%2,%3}, {%4,%5,%6,%7}, {%8,%9}, {%0,%1,%2,%3};"
      : "+f"(c[0]), "+f"(c[1]), "+f"(c[2]), "+f"(c[3])
      : "r"(a[0]), "r"(a[1]), "r"(a[2]), "r"(a[3]), "r"(b[0]), "r"(b[1]));
}
#define CP_COMMIT() asm volatile("cp.async.commit_group;" ::: "memory")
#define CP_WAIT(n)  asm volatile("cp.async.wait_group %0;" :: "n"(n) : "memory")

// Packed fp32x2 (Blackwell FFMA2 path; base PTX, sm_100+)
__device__ __forceinline__ unsigned long long ffma2(unsigned long long a, unsigned long long b,
                                                    unsigned long long c) {
  unsigned long long d;
  asm("fma.rn.f32x2 %0, %1, %2, %3;" : "=l"(d) : "l"(a), "l"(b), "l"(c));
  return d;
}
__device__ __forceinline__ unsigned long long fadd2(unsigned long long a, unsigned long long b) {
  unsigned long long d;
  asm("add.rn.f32x2 %0, %1, %2;" : "=l"(d) : "l"(a), "l"(b));
  return d;
}
__device__ __forceinline__ void lds_v2b64(unsigned long long& a, unsigned long long& b, uint32_t addr) {
  asm volatile("ld.shared.v2.b64 {%0,%1}, [%2];" : "=l"(a), "=l"(b) : "r"(addr));
}
__device__ __forceinline__ float2 unpack2(unsigned long long v) {
  float2 f;
  asm("mov.b64 {%0,%1}, %2;" : "=f"(f.x), "=f"(f.y) : "l"(v));
  return f;
}
__device__ __forceinline__ unsigned long long pack2(float x, float y) {
  unsigned long long v;
  asm("mov.b64 %0, {%1,%2};" : "=l"(v) : "f"(x), "f"(y));
  return v;
}

// SW64 swizzle for 64-byte rows (conflict-free ldmatrix over 8-row atoms)
__device__ __forceinline__ uint32_t sw64(uint32_t bo) { return bo ^ ((bo >> 3) & 0x30); }

// ---------------------------------------------------------------------------
// Fused fp32 -> (bf16 hi, bf16 lo) split for all four input tensors.
// ---------------------------------------------------------------------------
#define CVT_N4_D   8192
#define CVT_N4_W1  25600
#define CVT_N4_W2  2560000
#define CVT_N4_W3  400000
#define CVT_C1 (CVT_N4_D)
#define CVT_C2 (CVT_C1 + CVT_N4_W1)
#define CVT_C3 (CVT_C2 + CVT_N4_W2)
#define CVT_C4 (CVT_C3 + CVT_N4_W3)

__global__ void cvt_all(const float* __restrict__ d, const float* __restrict__ W1,
                        const float* __restrict__ W2, const float* __restrict__ W3,
                        __nv_bfloat16* dh, __nv_bfloat16* dl,
                        __nv_bfloat16* w1h, __nv_bfloat16* w1l,
                        __nv_bfloat16* w2h, __nv_bfloat16* w2l,
                        __nv_bfloat16* w3h, __nv_bfloat16* w3l) {
  int i = blockIdx.x * 256 + threadIdx.x;
  const float* src;
  __nv_bfloat16 *ph, *pl;
  int off;
  if (i < CVT_C1)      { src = d;  ph = dh;  pl = dl;  off = i; }
  else if (i < CVT_C2) { src = W1; ph = w1h; pl = w1l; off = i - CVT_C1; }
  else if (i < CVT_C3) { src = W2; ph = w2h; pl = w2l; off = i - CVT_C2; }
  else if (i < CVT_C4) { src = W3; ph = w3h; pl = w3l; off = i - CVT_C3; }
  else return;
  float4 v = reinterpret_cast<const float4*>(src)[off];
  __nv_bfloat16 h0 = __float2bfloat16_rn(v.x), h1 = __float2bfloat16_rn(v.y);
  __nv_bfloat16 h2 = __float2bfloat16_rn(v.z), h3 = __float2bfloat16_rn(v.w);
  __nv_bfloat16 l0 = __float2bfloat16_rn(v.x - __bfloat162float(h0));
  __nv_bfloat16 l1 = __float2bfloat16_rn(v.y - __bfloat162float(h1));
  __nv_bfloat16 l2 = __float2bfloat16_rn(v.z - __bfloat162float(h2));
  __nv_bfloat16 l3 = __float2bfloat16_rn(v.w - __bfloat162float(h3));
  uint2 phv, plv;
  phv.x = ((uint32_t)__bfloat16_as_ushort(h1) << 16) | __bfloat16_as_ushort(h0);
  phv.y = ((uint32_t)__bfloat16_as_ushort(h3) << 16) | __bfloat16_as_ushort(h2);
  plv.x = ((uint32_t)__bfloat16_as_ushort(l1) << 16) | __bfloat16_as_ushort(l0);
  plv.y = ((uint32_t)__bfloat16_as_ushort(l3) << 16) | __bfloat16_as_ushort(l2);
  reinterpret_cast<uint2*>(ph)[off] = phv;
  reinterpret_cast<uint2*>(pl)[off] = plv;
}

// ---------------------------------------------------------------------------
// Async tile loader: ROWS x 32 bf16 (64 B/row), SW64 swizzle, cp.async 16B
// ---------------------------------------------------------------------------
template <int ROWS>
__device__ __forceinline__ void load_tile_async(uint32_t tile, const __nv_bfloat16* __restrict__ g,
                                                int row0, int rmax, int ldk, int k0, int kend,
                                                int tid) {
  constexpr int NV = ROWS * 4;     // 16B vectors per tile
#pragma unroll
  for (int t = 0; t < NV / 256; t++) {
    int v = tid + t * 256;
    int r = v >> 2;                 // tile row
    int cs = v & 3;                 // 16B segment (4 per 64B row)
    int gr = row0 + r;
    int gk = k0 + cs * 8;
    uint32_t dst = tile + sw64(((uint32_t)r << 6) + ((uint32_t)cs << 4));
    if (gr < rmax && gk < kend) {
      const void* src = g + (size_t)gr * ldk + gk;
      asm volatile("cp.async.cg.shared.global [%0], [%1], 16;" :: "r"(dst), "l"(src));
    } else {
      asm volatile("st.shared.v4.b32 [%0], {%1,%1,%1,%1};" :: "r"(dst), "r"(0u));
    }
  }
}

// ---------------------------------------------------------------------------
// bf16x3 split GEMM via mma.sync m16n8k16.
// Tile 64M x 128N, BK=32, 3-stage cp.async, 3 CTAs/SM, ONE barrier per chunk:
//   wait(c) -> sync -> issue load(c+2) into buf (c-1)%3 (reads done pre-sync)
//   -> compute(c).
// 8 warps in (2 warp_m x 4 warp_n): each warp 32M x 32N.
// MODE 0: full-K, bias+lrelu, emit bf16 hi/lo. MODE 1: split-K fp32 partials.
// ---------------------------------------------------------------------------
#define STAGE_B 24576  // Ah 4KB | Al 4KB | Bh 8KB | Bl 8KB

template <int MODE>
__global__ __launch_bounds__(256, 3)
void mma_gemm(const __nv_bfloat16* __restrict__ Ah, const __nv_bfloat16* __restrict__ Al,
              const __nv_bfloat16* __restrict__ Bh, const __nv_bfloat16* __restrict__ Bl,
              const float* __restrict__ bias, float* __restrict__ Pf,
              __nv_bfloat16* __restrict__ Ch, __nv_bfloat16* __restrict__ Cl,
              int M, int N, int K, int kchunk) {
  extern __shared__ char smem[];
  const uint32_t sb = smem_u32(smem);
  const int tid = threadIdx.x, wid = tid >> 5, lane = tid & 31;
  const int m0 = blockIdx.y * 64, n0 = blockIdx.x * 128;
  const int warp_m = wid & 1;    // 2 x 32 rows
  const int warp_n = wid >> 1;   // 4 x 32 cols

  const int kbeg = (MODE == 1) ? blockIdx.z * kchunk : 0;
  const int kend = (kbeg + kchunk < K) ? (kbeg + kchunk) : K;
  const int NC = (kend - kbeg + 31) / 32;

  float acc[2][4][4];
#pragma unroll
  for (int mt = 0; mt < 2; mt++)
#pragma unroll
    for (int nt = 0; nt < 4; nt++)
#pragma unroll
      for (int i = 0; i < 4; i++) acc[mt][nt][i] = 0.f;

  // Prologue: stages 0,1 (skip stage 1 if K fits in one chunk)
#pragma unroll
  for (int s = 0; s < 2; s++) {
    if (s == 1 && NC < 2) break;
    uint32_t tb = sb + s * STAGE_B;
    int k0 = kbeg + s * 32;
    load_tile_async<64>(tb + 0,      Ah, m0, M, K, k0, kend, tid);
    load_tile_async<64>(tb + 4096,   Al, m0, M, K, k0, kend, tid);
    load_tile_async<128>(tb + 8192,  Bh, n0, N, K, k0, kend, tid);
    load_tile_async<128>(tb + 16384, Bl, n0, N, K, k0, kend, tid);
    CP_COMMIT();
  }

  const int a_r = (lane & 15);
  const uint32_t a_koff = (lane & 16) ? 16u : 0u;
  const int b_r = ((lane & 16) ? 8 : 0) + (lane & 7);
  const uint32_t b_koff = (lane & 8) ? 16u : 0u;

  for (int c = 0; c < NC; c++) {
    // Ensure chunk c data arrived (allow 1 newer group in flight)
    if (c + 1 < NC) { CP_WAIT(1); } else { CP_WAIT(0); }
    __syncthreads();  // data visible to all; buf (c-1)%3 reads all complete

    if (c + 2 < NC) {
      uint32_t tb = sb + ((c + 2) % 3) * STAGE_B;
      int k0 = kbeg + (c + 2) * 32;
      load_tile_async<64>(tb + 0,      Ah, m0, M, K, k0, kend, tid);
      load_tile_async<64>(tb + 4096,   Al, m0, M, K, k0, kend, tid);
      load_tile_async<128>(tb + 8192,  Bh, n0, N, K, k0, kend, tid);
      load_tile_async<128>(tb + 16384, Bl, n0, N, K, k0, kend, tid);
      CP_COMMIT();
    }

    const uint32_t tb = sb + (c % 3) * STAGE_B;
#pragma unroll
    for (int ks = 0; ks < 2; ks++) {
      const uint32_t kb = ks * 32;
      uint32_t bh[8], bl[8];
#pragma unroll
      for (int g2 = 0; g2 < 2; g2++) {
        uint32_t sw = sw64(((uint32_t)(warp_n * 32 + g2 * 16 + b_r) << 6) + kb + b_koff);
        ldsm4(bh + g2 * 4, tb + 8192 + sw);
        ldsm4(bl + g2 * 4, tb + 16384 + sw);
      }
#pragma unroll
      for (int mt = 0; mt < 2; mt++) {
        uint32_t ah[4], al[4];
        uint32_t sw = sw64(((uint32_t)(warp_m * 32 + mt * 16 + a_r) << 6) + kb + a_koff);
        ldsm4(ah, tb + sw);
        ldsm4(al, tb + 4096 + sw);
#pragma unroll
        for (int nt = 0; nt < 4; nt++) {
          mma16816(acc[mt][nt], ah, bh + nt * 2);
          mma16816(acc[mt][nt], al, bh + nt * 2);
          mma16816(acc[mt][nt], ah, bl + nt * 2);
        }
      }
    }
  }

  // Epilogue
#pragma unroll
  for (int mt = 0; mt < 2; mt++) {
#pragma unroll
    for (int nt = 0; nt < 4; nt++) {
      const int col = n0 + warp_n * 32 + nt * 8 + ((lane & 3) << 1);
      const int r0 = m0 + warp_m * 32 + mt * 16 + (lane >> 2);
#pragma unroll
      for (int h = 0; h < 2; h++) {
        const int row = r0 + h * 8;
        float v0 = acc[mt][nt][h * 2 + 0];
        float v1 = acc[mt][nt][h * 2 + 1];
        if (MODE == 0) {
          if (col < N) {
            v0 += bias[col];
            v1 += bias[col + 1];
            v0 = (v0 > 0.f) ? v0 : 0.1f * v0;
            v1 = (v1 > 0.f) ? v1 : 0.1f * v1;
            __nv_bfloat16 h0 = __float2bfloat16_rn(v0), h1 = __float2bfloat16_rn(v1);
            __nv_bfloat16 l0 = __float2bfloat16_rn(v0 - __bfloat162float(h0));
            __nv_bfloat16 l1 = __float2bfloat16_rn(v1 - __bfloat162float(h1));
            uint32_t ph = ((uint32_t)__bfloat16_as_ushort(h1) << 16) | __bfloat16_as_ushort(h0);
            uint32_t pl = ((uint32_t)__bfloat16_as_ushort(l1) << 16) | __bfloat16_as_ushort(l0);
            *reinterpret_cast<uint32_t*>(Ch + (size_t)row * N + col) = ph;
            *reinterpret_cast<uint32_t*>(Cl + (size_t)row * N + col) = pl;
          }
        } else {
          if (col < PSTRIDE) {
            float* dst = Pf + (size_t)blockIdx.z * BDIM * PSTRIDE + (size_t)row * PSTRIDE + col;
            *reinterpret_cast<float2*>(dst) = make_float2(v0, v1);
          }
        }
      }
    }
  }
}

// ---------------------------------------------------------------------------
// Setup: S = I + 0.5 * W W^T (30x30), invert via Gauss-Jordan. 1024 threads.
// ---------------------------------------------------------------------------
__global__ void setup_sinv(const float* __restrict__ W, float* __restrict__ Sinv) {
  __shared__ float aug[KDIM][64];
  __shared__ float fac[KDIM];
  __shared__ float pivinv;
  const int tid = threadIdx.x;  // 1024 threads

  if (tid < KDIM * KDIM) {
    int a = tid / KDIM, b = tid % KDIM;
    float s = 0.f;
    for (int j = 0; j < RDIM; j++) s += W[a * RDIM + j] * W[b * RDIM + j];
    aug[a][b] = 0.5f * s + (a == b ? 1.f : 0.f);
  }
  for (int idx = tid; idx < KDIM * 34; idx += 1024) {
    int a = idx / 34, c = 30 + idx % 34;
    aug[a][c] = (c - 30 == a) ? 1.f : 0.f;
  }
  __syncthreads();

  for (int i = 0; i < KDIM; i++) {
    if (tid == 0) pivinv = 1.f / aug[i][i];
    __syncthreads();
    if (tid < 64) aug[i][tid] *= pivinv;
    __syncthreads();
    if (tid < KDIM) fac[tid] = aug[tid][i];
    __syncthreads();
    for (int idx = tid; idx < KDIM * 64; idx += 1024) {
      int r = idx / 64, c = idx % 64;
      if (r != i) aug[r][c] -= fac[r] * aug[i][c];
    }
    __syncthreads();
  }
  for (int idx = tid; idx < KDIM * KDIM; idx += 1024)
    Sinv[idx] = aug[idx / KDIM][30 + idx % KDIM];
}

// ---------------------------------------------------------------------------
// Persistent ADMM kernel — 512 threads, 8 rows/block, 128 blocks.
//  * over-relaxation alpha=1.6: p <- p + alpha*(x - max(p,0)); same fixed point
//  * deterministic early exit: block leaves once max|dp| < ADMM_EPS
//  * M1: warps = (row-pair x k-quarter); pr/ps in registers; FFMA2 matvecs
// ---------------------------------------------------------------------------
#define AROWS 8

__global__ __launch_bounds__(512, 1)
void admm_kernel(const float* __restrict__ costP, const float* __restrict__ b3,
                 const float* __restrict__ W, const float* __restrict__ cap,
                 const float* __restrict__ SinvG, float* __restrict__ out) {
  extern __shared__ float sm[];
  float* Ws   = sm;                     // [32][512] (rows 30,31 zero)
  float* ev   = Ws + 32 * 512;          // [8][512]
  float* cst  = ev + AROWS * 512;       // [8][512]
  float* pk   = cst + AROWS * 512;      // [8][32]
  float* gk   = pk + AROWS * 32;        // [8][32]
  float* ts   = gk + AROWS * 32;        // [8][32]
  float* y1s  = ts + AROWS * 32;        // [8][32] (lanes 30,31 stay zero)
  float* tcap = y1s + AROWS * 32;       // [32]
  float* Ssm  = tcap + 32;              // [30][33]
  float* wmax = Ssm + KDIM * 33;        // [24]

  const int tid = threadIdx.x;          // 0..511
  const int lane = tid & 31;
  const int wid = tid >> 5;             // 0..15
  const int row0 = blockIdx.x * AROWS;  // 128 blocks x 8 = 1024 exact
  const int j = tid;

  // ---- init ----
  for (int idx = tid; idx < 32 * 512; idx += 512) {
    int k = idx >> 9, jj = idx & 511;
    Ws[idx] = (k < KDIM && jj < RDIM) ? W[k * RDIM + jj] : 0.f;
  }
#pragma unroll
  for (int r = 0; r < AROWS; r++) {
    float cv = 0.f;
    if (j < RDIM) {
      cv = b3[j];
#pragma unroll
      for (int z = 0; z < KSPLIT; z++)
        cv += costP[(size_t)z * BDIM * PSTRIDE + (size_t)(row0 + r) * PSTRIDE + j];
    }
    cst[r * 512 + j] = cv;
    ev[r * 512 + j] = cv;   // p = 0 -> e = cost
  }
  for (int idx = tid; idx < KDIM * 33; idx += 512) {
    int k = idx / 33, m = idx % 33;
    Ssm[idx] = (m < KDIM) ? SinvG[k * KDIM + m] : 0.f;
  }
  for (int idx = tid; idx < AROWS * 32; idx += 512) {
    pk[idx] = 0.f; gk[idx] = 0.f; ts[idx] = 0.f; y1s[idx] = 0.f;
  }
  if (tid < 24) wmax[tid] = 1e30f;
  __syncthreads();

  // tcap_k = (sum_j W[k][j]) - 2*cap_k
  {
    int k = wid * 2;
#pragma unroll
    for (int q = 0; q < 2; q++, k++) {
      if (k < KDIM) {
        float s = 0.f;
#pragma unroll
        for (int m = 0; m < 16; m++) s += Ws[k * 512 + lane + 32 * m];
#pragma unroll
        for (int o = 16; o > 0; o >>= 1) s += __shfl_down_sync(0xffffffffu, s, o);
        if (lane == 0) tcap[k] = s - 2.f * cap[k];
      }
    }
  }
  __syncthreads();

  // M2 weights: Wr2[kk] = (Ws[2kk][j], Ws[2kk+1][j]) (k up to 31, zero-padded)
  unsigned long long Wr2[16];
#pragma unroll
  for (int kk = 0; kk < 16; kk++)
    Wr2[kk] = pack2(Ws[(2 * kk) * 512 + j], Ws[(2 * kk + 1) * 512 + j]);

  // Per-thread persistent state (owner thread = j)
  float prr[AROWS], psr[AROWS];
#pragma unroll
  for (int r = 0; r < AROWS; r++) { prr[r] = 0.f; psr[r] = 0.f; }

  const int rp = wid & 3;        // row-pair index -> rows 2rp, 2rp+1
  const int kq = wid >> 2;       // k-quarter -> k = 8kq .. 8kq+7
  const int r0m = 2 * rp, r1m = 2 * rp + 1;
  const uint32_t ws_a = smem_u32(Ws);
  const uint32_t ev_a = smem_u32(ev);
  const uint32_t y_a  = smem_u32(y1s);

  bool conv = false;
  for (int it = 0; it < NITER; it++) {
    const bool last = conv || (it == NITER - 1);

    // ---- M1: gk[r][k] = sum_j W[k][j] e[r][j] ----
    {
      unsigned long long e0[8], e1[8];
      const uint32_t eb0 = ev_a + ((uint32_t)(r0m * 512 + lane * 4) << 2);
      const uint32_t eb1 = ev_a + ((uint32_t)(r1m * 512 + lane * 4) << 2);
#pragma unroll
      for (int s = 0; s < 4; s++) {
        lds_v2b64(e0[2 * s], e0[2 * s + 1], eb0 + 512 * s);
        lds_v2b64(e1[2 * s], e1[2 * s + 1], eb1 + 512 * s);
      }
#pragma unroll
      for (int kk = 0; kk < 8; kk++) {
        const int k = kq * 8 + kk;
        const uint32_t wb = ws_a + ((uint32_t)(k * 512 + lane * 4) << 2);
        unsigned long long a00 = 0ull, a01 = 0ull, a10 = 0ull, a11 = 0ull, w0, w1;
#pragma unroll
        for (int s = 0; s < 4; s++) {
          lds_v2b64(w0, w1, wb + 512 * s);
          a00 = ffma2(w0, e0[2 * s], a00);
          a01 = ffma2(w1, e0[2 * s + 1], a01);
          a10 = ffma2(w0, e1[2 * s], a10);
          a11 = ffma2(w1, e1[2 * s + 1], a11);
        }
        float2 f0 = unpack2(fadd2(a00, a01));
        float2 f1 = unpack2(fadd2(a10, a11));
        float v0 = f0.x + f0.y;
        float v1 = f1.x + f1.y;
#pragma unroll
        for (int o = 16; o > 0; o >>= 1) {
          v0 += __shfl_down_sync(0xffffffffu, v0, o);
          v1 += __shfl_down_sync(0xffffffffu, v1, o);
        }
        if (lane == 0) { gk[r0m * 32 + k] = v0; gk[r1m * 32 + k] = v1; }
      }
    }
    __syncthreads();

    // ---- Solve: y1 = Sinv(0.5*gk + |p_k| + tcap); relaxed p_k update ----
    if (wid < AROWS) {
      const int r = wid;
      float pkv = 0.f;
      if (lane < KDIM) {
        pkv = pk[r * 32 + lane];
        ts[r * 32 + lane] = 0.5f * gk[r * 32 + lane] + fabsf(pkv) + tcap[lane];
      }
      __syncwarp(0xffffffffu);
      float dk = 0.f;
      if (lane < KDIM) {
        float y = 0.f;
#pragma unroll
        for (int m = 0; m < KDIM; m++) y += Ssm[lane * 33 + m] * ts[r * 32 + m];
        y1s[r * 32 + lane] = y;
        float xk = 0.5f * (fabsf(pkv) - y);
        float npk = fmaf(ALPHA, xk - fmaxf(pkv, 0.f), pkv);
        pk[r * 32 + lane] = npk;
        dk = fabsf(npk - pkv);
        if (last)
          out[(size_t)(row0 + r) * N2_DIM + RDIM + lane] = xk;
      }
#pragma unroll
      for (int o = 16; o > 0; o >>= 1) dk = fmaxf(dk, __shfl_down_sync(0xffffffffu, dk, o));
      if (lane == 0) wmax[16 + r] = dk;
    }
    __syncthreads();

    // ---- M2+E: wt_j = (W^T y1)_j; relaxed p_r/p_s update; recompute e ----
    float dm = 0.f;
#pragma unroll
    for (int r = 0; r < AROWS; r++) {
      unsigned long long a0 = 0ull, a1 = 0ull, y0, y1v;
      const uint32_t yb = y_a + (uint32_t)(r * 128);
#pragma unroll
      for (int kk8 = 0; kk8 < 8; kk8++) {
        lds_v2b64(y0, y1v, yb + kk8 * 16);
        a0 = ffma2(Wr2[2 * kk8], y0, a0);
        a1 = ffma2(Wr2[2 * kk8 + 1], y1v, a1);
      }
      float2 f = unpack2(fadd2(a0, a1));
      float wt = f.x + f.y;

      float e0 = ev[r * 512 + j];
      float xr = 0.25f * (e0 - wt) + 0.5f;
      float xs = 1.f - xr;
      float np = fmaf(ALPHA, xr - fmaxf(prr[r], 0.f), prr[r]);
      float ns = fmaf(ALPHA, xs - fmaxf(psr[r], 0.f), psr[r]);
      dm = fmaxf(dm, fmaxf(fabsf(np - prr[r]), fabsf(ns - psr[r])));
      prr[r] = np;
      psr[r] = ns;
      ev[r * 512 + j] = cst[r * 512 + j] + fabsf(np) - fabsf(ns);
      if (last && j < RDIM) {
        out[(size_t)(row0 + r) * N2_DIM + j] = xr;
        out[(size_t)(row0 + r) * N2_DIM + RDIM + KDIM + j] = xs;
      }
    }
#pragma unroll
    for (int o = 16; o > 0; o >>= 1) dm = fmaxf(dm, __shfl_down_sync(0xffffffffu, dm, o));
    if (lane == 0) wmax[wid] = dm;
    __syncthreads();

    if (last) break;
    float mx = 0.f;
#pragma unroll
    for (int q = 0; q < 24; q++) mx = fmaxf(mx, wmax[q]);
    conv = (mx < ADMM_EPS);
  }
}

// ---------------------------------------------------------------------------
extern "C" void kernel_launch(void* const* d_in, const int* in_sizes, int n_in,
                              void* d_out, int out_size) {
  const float* d   = (const float*)d_in[0];  // [1024,32]
  const float* W1  = (const float*)d_in[1];  // [3200,32]
  const float* b1  = (const float*)d_in[2];  // [3200]
  const float* W2  = (const float*)d_in[3];  // [3200,3200]
  const float* b2  = (const float*)d_in[4];  // [3200]
  const float* W3  = (const float*)d_in[5];  // [500,3200]
  const float* b3  = (const float*)d_in[6];  // [500]
  const float* Wm  = (const float*)d_in[7];  // [30,500]
  const float* cap = (const float*)d_in[8];  // [30]
  float* out = (float*)d_out;                // [1024,1030]

  __nv_bfloat16 *dh, *dl, *w1h, *w1l, *w2h, *w2l, *w3h, *w3l, *h1h, *h1l, *h2h, *h2l;
  float *costP, *sinv;
  cudaGetSymbolAddress((void**)&dh, g_dh);   cudaGetSymbolAddress((void**)&dl, g_dl);
  cudaGetSymbolAddress((void**)&w1h, g_W1h); cudaGetSymbolAddress((void**)&w1l, g_W1l);
  cudaGetSymbolAddress((void**)&w2h, g_W2h); cudaGetSymbolAddress((void**)&w2l, g_W2l);
  cudaGetSymbolAddress((void**)&w3h, g_W3h); cudaGetSymbolAddress((void**)&w3l, g_W3l);
  cudaGetSymbolAddress((void**)&h1h, g_h1h); cudaGetSymbolAddress((void**)&h1l, g_h1l);
  cudaGetSymbolAddress((void**)&h2h, g_h2h); cudaGetSymbolAddress((void**)&h2l, g_h2l);
  cudaGetSymbolAddress((void**)&costP, g_costP);
  cudaGetSymbolAddress((void**)&sinv, g_Sinv);

  // 1) Fused hi/lo bf16 splits of all inputs
  cvt_all<<<(CVT_C4 + 255) / 256, 256>>>(d, W1, W2, W3, dh, dl, w1h, w1l, w2h, w2l, w3h, w3l);

  // 2) Sinv = (I + 0.5 W W^T)^-1
  setup_sinv<<<1, 1024>>>(Wm, sinv);

  const int gemm_smem = 3 * STAGE_B;  // 73728 B
  cudaFuncSetAttribute(mma_gemm<0>, cudaFuncAttributeMaxDynamicSharedMemorySize, gemm_smem);
  cudaFuncSetAttribute(mma_gemm<1>, cudaFuncAttributeMaxDynamicSharedMemorySize, gemm_smem);

  // 3-5) MLP on tensor cores (bf16x3 split via mma.sync); 64M x 128N tiles, 3 CTA/SM
  mma_gemm<0><<<dim3(HDIM / 128, BDIM / 64), 256, gemm_smem>>>(
      dh, dl, w1h, w1l, b1, nullptr, h1h, h1l, BDIM, HDIM, CDIM, CDIM);
  mma_gemm<0><<<dim3(HDIM / 128, BDIM / 64), 256, gemm_smem>>>(
      h1h, h1l, w2h, w2l, b2, nullptr, h2h, h2l, BDIM, HDIM, HDIM, HDIM);
  mma_gemm<1><<<dim3((RDIM + 127) / 128, BDIM / 64, KSPLIT), 256, gemm_smem>>>(
      h2h, h2l, w3h, w3l, nullptr, costP, nullptr, nullptr, BDIM, RDIM, HDIM, HDIM / KSPLIT);

  // 6) ADMM (persistent; over-relaxed; early exit on block convergence)
  const int admm_smem = (32 * 512 + 2 * AROWS * 512 + 4 * AROWS * 32 + 32 + KDIM * 33 + 24) * (int)sizeof(float);
  cudaFuncSetAttribute(admm_kernel, cudaFuncAttributeMaxDynamicSharedMemorySize, admm_smem);
  admm_kernel<<<BDIM / AROWS, 512, admm_smem>>>(costP, b3, Wm, cap, sinv, out);
}

// round 15
// speedup vs baseline: 6.9872x; 1.0258x over previous
#include <cuda_runtime.h>
#include <cuda_bf16.h>
#include <cstdint>

// Problem constants
#define CDIM 32
#define HDIM 3200
#define BDIM 1024
#define RDIM 500
#define KDIM 30
#define N2_DIM 1030
#define NITER 200
#define KSPLIT 4
#define PSTRIDE 512
#define ADMM_EPS 6e-4f
#define ALPHA 1.6f   // ADMM over-relaxation (fixed point unchanged)

// ---------------------------------------------------------------------------
// Device-global scratch (no allocation allowed)
// ---------------------------------------------------------------------------
__device__ __nv_bfloat16 g_dh[BDIM * CDIM],  g_dl[BDIM * CDIM];
__device__ __nv_bfloat16 g_W1h[HDIM * CDIM], g_W1l[HDIM * CDIM];
__device__ __nv_bfloat16 g_W2h[HDIM * HDIM], g_W2l[HDIM * HDIM];
__device__ __nv_bfloat16 g_W3h[RDIM * HDIM], g_W3l[RDIM * HDIM];
__device__ __nv_bfloat16 g_h1h[BDIM * HDIM], g_h1l[BDIM * HDIM];
__device__ __nv_bfloat16 g_h2h[BDIM * HDIM], g_h2l[BDIM * HDIM];
__device__ float g_costP[KSPLIT * BDIM * PSTRIDE];
__device__ float g_Sinv[KDIM * KDIM];

// ---------------------------------------------------------------------------
// PTX helpers (plain sm_80+/sm_100 base features — no arch-'a' gated instrs)
// ---------------------------------------------------------------------------
__device__ __forceinline__ uint32_t smem_u32(const void* p) {
  uint32_t a;
  asm("{ .reg .u64 t; cvta.to.shared.u64 t, %1; cvt.u32.u64 %0, t; }" : "=r"(a) : "l"(p));
  return a;
}
__device__ __forceinline__ void ldsm4(uint32_t* r, uint32_t a) {
  asm volatile("ldmatrix.sync.aligned.m8n8.x4.shared.b16 {%0,%1,%2,%3}, [%4];"
               : "=r"(r[0]), "=r"(r[1]), "=r"(r[2]), "=r"(r[3]) : "r"(a));
}
__device__ __forceinline__ void mma16816(float* c, const uint32_t* a, const uint32_t* b) {
  asm volatile(
      "mma.sync.aligned.m16n8k16.row.col.f32.bf16.bf16.f32 "
      "{%0,%1,%2,%3}, {%4,%5,%6,%7}, {%8,%9}, {%0,%1,%2,%3};"
      : "+f"(c[0]), "+f"(c[1]), "+f"(c[2]), "+f"(c[3])
      : "r"(a[0]), "r"(a[1]), "r"(a[2]), "r"(a[3]), "r"(b[0]), "r"(b[1]));
}
#define CP_COMMIT() asm volatile("cp.async.commit_group;" ::: "memory")
#define CP_WAIT(n)  asm volatile("cp.async.wait_group %0;" :: "n"(n) : "memory")

// Packed fp32x2 (Blackwell FFMA2 path; base PTX, sm_100+)
__device__ __forceinline__ unsigned long long ffma2(unsigned long long a, unsigned long long b,
                                                    unsigned long long c) {
  unsigned long long d;
  asm("fma.rn.f32x2 %0, %1, %2, %3;" : "=l"(d) : "l"(a), "l"(b), "l"(c));
  return d;
}
__device__ __forceinline__ unsigned long long fadd2(unsigned long long a, unsigned long long b) {
  unsigned long long d;
  asm("add.rn.f32x2 %0, %1, %2;" : "=l"(d) : "l"(a), "l"(b));
  return d;
}
__device__ __forceinline__ void lds_v2b64(unsigned long long& a, unsigned long long& b, uint32_t addr) {
  asm volatile("ld.shared.v2.b64 {%0,%1}, [%2];" : "=l"(a), "=l"(b) : "r"(addr));
}
__device__ __forceinline__ float2 unpack2(unsigned long long v) {
  float2 f;
  asm("mov.b64 {%0,%1}, %2;" : "=f"(f.x), "=f"(f.y) : "l"(v));
  return f;
}
__device__ __forceinline__ unsigned long long pack2(float x, float y) {
  unsigned long long v;
  asm("mov.b64 %0, {%1,%2};" : "=l"(v) : "f"(x), "f"(y));
  return v;
}

// SW64 swizzle for 64-byte rows (conflict-free ldmatrix over 8-row atoms)
__device__ __forceinline__ uint32_t sw64(uint32_t bo) { return bo ^ ((bo >> 3) & 0x30); }

// ---------------------------------------------------------------------------
// Fused fp32 -> (bf16 hi, bf16 lo) split; 2 x float4 per thread (MLP=2).
// Counts below are in float4 PAIRS (8 floats).
// ---------------------------------------------------------------------------
#define CVT_P_D   4096
#define CVT_P_W1  12800
#define CVT_P_W2  1280000
#define CVT_P_W3  200000
#define CVT_B1 (CVT_P_D)
#define CVT_B2 (CVT_B1 + CVT_P_W1)
#define CVT_B3 (CVT_B2 + CVT_P_W2)
#define CVT_B4 (CVT_B3 + CVT_P_W3)

__device__ __forceinline__ void cvt_one(float4 v, uint2& phv, uint2& plv) {
  __nv_bfloat16 h0 = __float2bfloat16_rn(v.x), h1 = __float2bfloat16_rn(v.y);
  __nv_bfloat16 h2 = __float2bfloat16_rn(v.z), h3 = __float2bfloat16_rn(v.w);
  __nv_bfloat16 l0 = __float2bfloat16_rn(v.x - __bfloat162float(h0));
  __nv_bfloat16 l1 = __float2bfloat16_rn(v.y - __bfloat162float(h1));
  __nv_bfloat16 l2 = __float2bfloat16_rn(v.z - __bfloat162float(h2));
  __nv_bfloat16 l3 = __float2bfloat16_rn(v.w - __bfloat162float(h3));
  phv.x = ((uint32_t)__bfloat16_as_ushort(h1) << 16) | __bfloat16_as_ushort(h0);
  phv.y = ((uint32_t)__bfloat16_as_ushort(h3) << 16) | __bfloat16_as_ushort(h2);
  plv.x = ((uint32_t)__bfloat16_as_ushort(l1) << 16) | __bfloat16_as_ushort(l0);
  plv.y = ((uint32_t)__bfloat16_as_ushort(l3) << 16) | __bfloat16_as_ushort(l2);
}

__global__ void cvt_all(const float* __restrict__ d, const float* __restrict__ W1,
                        const float* __restrict__ W2, const float* __restrict__ W3,
                        __nv_bfloat16* dh, __nv_bfloat16* dl,
                        __nv_bfloat16* w1h, __nv_bfloat16* w1l,
                        __nv_bfloat16* w2h, __nv_bfloat16* w2l,
                        __nv_bfloat16* w3h, __nv_bfloat16* w3l) {
  int i = blockIdx.x * 256 + threadIdx.x;
  const float* src;
  __nv_bfloat16 *ph, *pl;
  int off;
  if (i < CVT_B1)      { src = d;  ph = dh;  pl = dl;  off = i; }
  else if (i < CVT_B2) { src = W1; ph = w1h; pl = w1l; off = i - CVT_B1; }
  else if (i < CVT_B3) { src = W2; ph = w2h; pl = w2l; off = i - CVT_B2; }
  else if (i < CVT_B4) { src = W3; ph = w3h; pl = w3l; off = i - CVT_B3; }
  else return;
  float4 v0 = reinterpret_cast<const float4*>(src)[2 * off + 0];
  float4 v1 = reinterpret_cast<const float4*>(src)[2 * off + 1];
  uint2 ph0, pl0, ph1, pl1;
  cvt_one(v0, ph0, pl0);
  cvt_one(v1, ph1, pl1);
  reinterpret_cast<uint2*>(ph)[2 * off + 0] = ph0;
  reinterpret_cast<uint2*>(ph)[2 * off + 1] = ph1;
  reinterpret_cast<uint2*>(pl)[2 * off + 0] = pl0;
  reinterpret_cast<uint2*>(pl)[2 * off + 1] = pl1;
}

// ---------------------------------------------------------------------------
// Async tile loader: ROWS x 32 bf16 (64 B/row), SW64 swizzle, cp.async 16B.
// NTH = threads in block (128).
// ---------------------------------------------------------------------------
template <int ROWS, int NTH>
__device__ __forceinline__ void load_tile_async(uint32_t tile, const __nv_bfloat16* __restrict__ g,
                                                int row0, int rmax, int ldk, int k0, int kend,
                                                int tid) {
  constexpr int NV = ROWS * 4;     // 16B vectors per tile
#pragma unroll
  for (int t = 0; t < NV / NTH; t++) {
    int v = tid + t * NTH;
    int r = v >> 2;                 // tile row
    int cs = v & 3;                 // 16B segment (4 per 64B row)
    int gr = row0 + r;
    int gk = k0 + cs * 8;
    uint32_t dst = tile + sw64(((uint32_t)r << 6) + ((uint32_t)cs << 4));
    if (gr < rmax && gk < kend) {
      const void* src = g + (size_t)gr * ldk + gk;
      asm volatile("cp.async.cg.shared.global [%0], [%1], 16;" :: "r"(dst), "l"(src));
    } else {
      asm volatile("st.shared.v4.b32 [%0], {%1,%1,%1,%1};" :: "r"(dst), "r"(0u));
    }
  }
}

// ---------------------------------------------------------------------------
// bf16x3 split GEMM via mma.sync m16n8k16.
// Tile 64M x 128N, BK=32, 3-stage cp.async, ONE barrier per chunk.
// 128 threads = 4 warps (2 warp_m x 2 warp_n); warp tile 32M x 64N
//  -> 20 ldsm4/warp/chunk = 40KB LDS/CTA/chunk (was 64KB at 8 warps).
// 3 CTAs/SM (smem 72KB); grid 400 = 1 wave; 170 regs/thread available.
// MODE 0: full-K, bias+lrelu, emit bf16 hi/lo. MODE 1: split-K fp32 partials.
// ---------------------------------------------------------------------------
#define STAGE_B 24576  // Ah 4KB | Al 4KB | Bh 8KB | Bl 8KB

template <int MODE>
__global__ __launch_bounds__(128, 3)
void mma_gemm(const __nv_bfloat16* __restrict__ Ah, const __nv_bfloat16* __restrict__ Al,
              const __nv_bfloat16* __restrict__ Bh, const __nv_bfloat16* __restrict__ Bl,
              const float* __restrict__ bias, float* __restrict__ Pf,
              __nv_bfloat16* __restrict__ Ch, __nv_bfloat16* __restrict__ Cl,
              int M, int N, int K, int kchunk) {
  extern __shared__ char smem[];
  const uint32_t sb = smem_u32(smem);
  const int tid = threadIdx.x, wid = tid >> 5, lane = tid & 31;
  const int m0 = blockIdx.y * 64, n0 = blockIdx.x * 128;
  const int warp_m = wid & 1;    // 2 x 32 rows
  const int warp_n = wid >> 1;   // 2 x 64 cols

  const int kbeg = (MODE == 1) ? blockIdx.z * kchunk : 0;
  const int kend = (kbeg + kchunk < K) ? (kbeg + kchunk) : K;
  const int NC = (kend - kbeg + 31) / 32;

  // acc[mt][g2][nt2][4]: mt = 16-row tile (2), g2 = 16-col group (4), nt2 = n8 (2)
  float acc[2][4][2][4];
#pragma unroll
  for (int mt = 0; mt < 2; mt++)
#pragma unroll
    for (int g2 = 0; g2 < 4; g2++)
#pragma unroll
      for (int n2 = 0; n2 < 2; n2++)
#pragma unroll
        for (int i = 0; i < 4; i++) acc[mt][g2][n2][i] = 0.f;

  // Prologue: stages 0,1 (skip stage 1 if K fits in one chunk)
#pragma unroll
  for (int s = 0; s < 2; s++) {
    if (s == 1 && NC < 2) break;
    uint32_t tb = sb + s * STAGE_B;
    int k0 = kbeg + s * 32;
    load_tile_async<64, 128>(tb + 0,      Ah, m0, M, K, k0, kend, tid);
    load_tile_async<64, 128>(tb + 4096,   Al, m0, M, K, k0, kend, tid);
    load_tile_async<128, 128>(tb + 8192,  Bh, n0, N, K, k0, kend, tid);
    load_tile_async<128, 128>(tb + 16384, Bl, n0, N, K, k0, kend, tid);
    CP_COMMIT();
  }

  const int a_r = (lane & 15);
  const uint32_t a_koff = (lane & 16) ? 16u : 0u;
  const int b_r = ((lane & 16) ? 8 : 0) + (lane & 7);
  const uint32_t b_koff = (lane & 8) ? 16u : 0u;

  for (int c = 0; c < NC; c++) {
    if (c + 1 < NC) { CP_WAIT(1); } else { CP_WAIT(0); }
    __syncthreads();  // chunk c visible; buf (c-1)%3 reads all complete

    if (c + 2 < NC) {
      uint32_t tb = sb + ((c + 2) % 3) * STAGE_B;
      int k0 = kbeg + (c + 2) * 32;
      load_tile_async<64, 128>(tb + 0,      Ah, m0, M, K, k0, kend, tid);
      load_tile_async<64, 128>(tb + 4096,   Al, m0, M, K, k0, kend, tid);
      load_tile_async<128, 128>(tb + 8192,  Bh, n0, N, K, k0, kend, tid);
      load_tile_async<128, 128>(tb + 16384, Bl, n0, N, K, k0, kend, tid);
      CP_COMMIT();
    }

    const uint32_t tb = sb + (c % 3) * STAGE_B;
#pragma unroll
    for (int ks = 0; ks < 2; ks++) {
      const uint32_t kb = ks * 32;
      uint32_t ah[2][4], al[2][4];
#pragma unroll
      for (int mt = 0; mt < 2; mt++) {
        uint32_t sw = sw64(((uint32_t)(warp_m * 32 + mt * 16 + a_r) << 6) + kb + a_koff);
        ldsm4(ah[mt], tb + sw);
        ldsm4(al[mt], tb + 4096 + sw);
      }
#pragma unroll
      for (int g2 = 0; g2 < 4; g2++) {
        uint32_t bh[4], bl[4];
        uint32_t sw = sw64(((uint32_t)(warp_n * 64 + g2 * 16 + b_r) << 6) + kb + b_koff);
        ldsm4(bh, tb + 8192 + sw);
        ldsm4(bl, tb + 16384 + sw);
#pragma unroll
        for (int mt = 0; mt < 2; mt++) {
#pragma unroll
          for (int n2 = 0; n2 < 2; n2++) {
            mma16816(acc[mt][g2][n2], ah[mt], bh + n2 * 2);
            mma16816(acc[mt][g2][n2], al[mt], bh + n2 * 2);
            mma16816(acc[mt][g2][n2], ah[mt], bl + n2 * 2);
          }
        }
      }
    }
  }

  // Epilogue
#pragma unroll
  for (int mt = 0; mt < 2; mt++) {
#pragma unroll
    for (int g2 = 0; g2 < 4; g2++) {
#pragma unroll
      for (int n2 = 0; n2 < 2; n2++) {
        const int col = n0 + warp_n * 64 + g2 * 16 + n2 * 8 + ((lane & 3) << 1);
        const int r0 = m0 + warp_m * 32 + mt * 16 + (lane >> 2);
#pragma unroll
        for (int h = 0; h < 2; h++) {
          const int row = r0 + h * 8;
          float v0 = acc[mt][g2][n2][h * 2 + 0];
          float v1 = acc[mt][g2][n2][h * 2 + 1];
          if (MODE == 0) {
            if (col < N) {
              v0 += bias[col];
              v1 += bias[col + 1];
              v0 = (v0 > 0.f) ? v0 : 0.1f * v0;
              v1 = (v1 > 0.f) ? v1 : 0.1f * v1;
              __nv_bfloat16 h0 = __float2bfloat16_rn(v0), h1 = __float2bfloat16_rn(v1);
              __nv_bfloat16 l0 = __float2bfloat16_rn(v0 - __bfloat162float(h0));
              __nv_bfloat16 l1 = __float2bfloat16_rn(v1 - __bfloat162float(h1));
              uint32_t ph = ((uint32_t)__bfloat16_as_ushort(h1) << 16) | __bfloat16_as_ushort(h0);
              uint32_t pl = ((uint32_t)__bfloat16_as_ushort(l1) << 16) | __bfloat16_as_ushort(l0);
              *reinterpret_cast<uint32_t*>(Ch + (size_t)row * N + col) = ph;
              *reinterpret_cast<uint32_t*>(Cl + (size_t)row * N + col) = pl;
            }
          } else {
            if (col < PSTRIDE) {
              float* dst = Pf + (size_t)blockIdx.z * BDIM * PSTRIDE + (size_t)row * PSTRIDE + col;
              *reinterpret_cast<float2*>(dst) = make_float2(v0, v1);
            }
          }
        }
      }
    }
  }
}

// ---------------------------------------------------------------------------
// Setup: S = I + 0.5 * W W^T (30x30), invert via Gauss-Jordan. 1024 threads.
// ---------------------------------------------------------------------------
__global__ void setup_sinv(const float* __restrict__ W, float* __restrict__ Sinv) {
  __shared__ float aug[KDIM][64];
  __shared__ float fac[KDIM];
  __shared__ float pivinv;
  const int tid = threadIdx.x;  // 1024 threads

  if (tid < KDIM * KDIM) {
    int a = tid / KDIM, b = tid % KDIM;
    float s = 0.f;
    for (int j = 0; j < RDIM; j++) s += W[a * RDIM + j] * W[b * RDIM + j];
    aug[a][b] = 0.5f * s + (a == b ? 1.f : 0.f);
  }
  for (int idx = tid; idx < KDIM * 34; idx += 1024) {
    int a = idx / 34, c = 30 + idx % 34;
    aug[a][c] = (c - 30 == a) ? 1.f : 0.f;
  }
  __syncthreads();

  for (int i = 0; i < KDIM; i++) {
    if (tid == 0) pivinv = 1.f / aug[i][i];
    __syncthreads();
    if (tid < 64) aug[i][tid] *= pivinv;
    __syncthreads();
    if (tid < KDIM) fac[tid] = aug[tid][i];
    __syncthreads();
    for (int idx = tid; idx < KDIM * 64; idx += 1024) {
      int r = idx / 64, c = idx % 64;
      if (r != i) aug[r][c] -= fac[r] * aug[i][c];
    }
    __syncthreads();
  }
  for (int idx = tid; idx < KDIM * KDIM; idx += 1024)
    Sinv[idx] = aug[idx / KDIM][30 + idx % KDIM];
}

// ---------------------------------------------------------------------------
// Persistent ADMM kernel — 512 threads, 8 rows/block, 128 blocks.
//  * over-relaxation alpha=1.6: p <- p + alpha*(x - max(p,0)); same fixed point
//  * deterministic early exit: block leaves once max|dp| < ADMM_EPS
//  * M1: warps = (row-pair x k-quarter); pr/ps in registers; FFMA2 matvecs
// ---------------------------------------------------------------------------
#define AROWS 8

__global__ __launch_bounds__(512, 1)
void admm_kernel(const float* __restrict__ costP, const float* __restrict__ b3,
                 const float* __restrict__ W, const float* __restrict__ cap,
                 const float* __restrict__ SinvG, float* __restrict__ out) {
  extern __shared__ float sm[];
  float* Ws   = sm;                     // [32][512] (rows 30,31 zero)
  float* ev   = Ws + 32 * 512;          // [8][512]
  float* cst  = ev + AROWS * 512;       // [8][512]
  float* pk   = cst + AROWS * 512;      // [8][32]
  float* gk   = pk + AROWS * 32;        // [8][32]
  float* ts   = gk + AROWS * 32;        // [8][32]
  float* y1s  = ts + AROWS * 32;        // [8][32] (lanes 30,31 stay zero)
  float* tcap = y1s + AROWS * 32;       // [32]
  float* Ssm  = tcap + 32;              // [30][33]
  float* wmax = Ssm + KDIM * 33;        // [24]

  const int tid = threadIdx.x;          // 0..511
  const int lane = tid & 31;
  const int wid = tid >> 5;             // 0..15
  const int row0 = blockIdx.x * AROWS;  // 128 blocks x 8 = 1024 exact
  const int j = tid;

  // ---- init ----
  for (int idx = tid; idx < 32 * 512; idx += 512) {
    int k = idx >> 9, jj = idx & 511;
    Ws[idx] = (k < KDIM && jj < RDIM) ? W[k * RDIM + jj] : 0.f;
  }
#pragma unroll
  for (int r = 0; r < AROWS; r++) {
    float cv = 0.f;
    if (j < RDIM) {
      cv = b3[j];
#pragma unroll
      for (int z = 0; z < KSPLIT; z++)
        cv += costP[(size_t)z * BDIM * PSTRIDE + (size_t)(row0 + r) * PSTRIDE + j];
    }
    cst[r * 512 + j] = cv;
    ev[r * 512 + j] = cv;   // p = 0 -> e = cost
  }
  for (int idx = tid; idx < KDIM * 33; idx += 512) {
    int k = idx / 33, m = idx % 33;
    Ssm[idx] = (m < KDIM) ? SinvG[k * KDIM + m] : 0.f;
  }
  for (int idx = tid; idx < AROWS * 32; idx += 512) {
    pk[idx] = 0.f; gk[idx] = 0.f; ts[idx] = 0.f; y1s[idx] = 0.f;
  }
  if (tid < 24) wmax[tid] = 1e30f;
  __syncthreads();

  // tcap_k = (sum_j W[k][j]) - 2*cap_k
  {
    int k = wid * 2;
#pragma unroll
    for (int q = 0; q < 2; q++, k++) {
      if (k < KDIM) {
        float s = 0.f;
#pragma unroll
        for (int m = 0; m < 16; m++) s += Ws[k * 512 + lane + 32 * m];
#pragma unroll
        for (int o = 16; o > 0; o >>= 1) s += __shfl_down_sync(0xffffffffu, s, o);
        if (lane == 0) tcap[k] = s - 2.f * cap[k];
      }
    }
  }
  __syncthreads();

  // M2 weights: Wr2[kk] = (Ws[2kk][j], Ws[2kk+1][j]) (k up to 31, zero-padded)
  unsigned long long Wr2[16];
#pragma unroll
  for (int kk = 0; kk < 16; kk++)
    Wr2[kk] = pack2(Ws[(2 * kk) * 512 + j], Ws[(2 * kk + 1) * 512 + j]);

  // Per-thread persistent state (owner thread = j)
  float prr[AROWS], psr[AROWS];
#pragma unroll
  for (int r = 0; r < AROWS; r++) { prr[r] = 0.f; psr[r] = 0.f; }

  const int rp = wid & 3;        // row-pair index -> rows 2rp, 2rp+1
  const int kq = wid >> 2;       // k-quarter -> k = 8kq .. 8kq+7
  const int r0m = 2 * rp, r1m = 2 * rp + 1;
  const uint32_t ws_a = smem_u32(Ws);
  const uint32_t ev_a = smem_u32(ev);
  const uint32_t y_a  = smem_u32(y1s);

  bool conv = false;
  for (int it = 0; it < NITER; it++) {
    const bool last = conv || (it == NITER - 1);

    // ---- M1: gk[r][k] = sum_j W[k][j] e[r][j] ----
    {
      unsigned long long e0[8], e1[8];
      const uint32_t eb0 = ev_a + ((uint32_t)(r0m * 512 + lane * 4) << 2);
      const uint32_t eb1 = ev_a + ((uint32_t)(r1m * 512 + lane * 4) << 2);
#pragma unroll
      for (int s = 0; s < 4; s++) {
        lds_v2b64(e0[2 * s], e0[2 * s + 1], eb0 + 512 * s);
        lds_v2b64(e1[2 * s], e1[2 * s + 1], eb1 + 512 * s);
      }
#pragma unroll
      for (int kk = 0; kk < 8; kk++) {
        const int k = kq * 8 + kk;
        const uint32_t wb = ws_a + ((uint32_t)(k * 512 + lane * 4) << 2);
        unsigned long long a00 = 0ull, a01 = 0ull, a10 = 0ull, a11 = 0ull, w0, w1;
#pragma unroll
        for (int s = 0; s < 4; s++) {
          lds_v2b64(w0, w1, wb + 512 * s);
          a00 = ffma2(w0, e0[2 * s], a00);
          a01 = ffma2(w1, e0[2 * s + 1], a01);
          a10 = ffma2(w0, e1[2 * s], a10);
          a11 = ffma2(w1, e1[2 * s + 1], a11);
        }
        float2 f0 = unpack2(fadd2(a00, a01));
        float2 f1 = unpack2(fadd2(a10, a11));
        float v0 = f0.x + f0.y;
        float v1 = f1.x + f1.y;
#pragma unroll
        for (int o = 16; o > 0; o >>= 1) {
          v0 += __shfl_down_sync(0xffffffffu, v0, o);
          v1 += __shfl_down_sync(0xffffffffu, v1, o);
        }
        if (lane == 0) { gk[r0m * 32 + k] = v0; gk[r1m * 32 + k] = v1; }
      }
    }
    __syncthreads();

    // ---- Solve: y1 = Sinv(0.5*gk + |p_k| + tcap); relaxed p_k update ----
    if (wid < AROWS) {
      const int r = wid;
      float pkv = 0.f;
      if (lane < KDIM) {
        pkv = pk[r * 32 + lane];
        ts[r * 32 + lane] = 0.5f * gk[r * 32 + lane] + fabsf(pkv) + tcap[lane];
      }
      __syncwarp(0xffffffffu);
      float dk = 0.f;
      if (lane < KDIM) {
        float y = 0.f;
#pragma unroll
        for (int m = 0; m < KDIM; m++) y += Ssm[lane * 33 + m] * ts[r * 32 + m];
        y1s[r * 32 + lane] = y;
        float xk = 0.5f * (fabsf(pkv) - y);
        float npk = fmaf(ALPHA, xk - fmaxf(pkv, 0.f), pkv);
        pk[r * 32 + lane] = npk;
        dk = fabsf(npk - pkv);
        if (last)
          out[(size_t)(row0 + r) * N2_DIM + RDIM + lane] = xk;
      }
#pragma unroll
      for (int o = 16; o > 0; o >>= 1) dk = fmaxf(dk, __shfl_down_sync(0xffffffffu, dk, o));
      if (lane == 0) wmax[16 + r] = dk;
    }
    __syncthreads();

    // ---- M2+E: wt_j = (W^T y1)_j; relaxed p_r/p_s update; recompute e ----
    float dm = 0.f;
#pragma unroll
    for (int r = 0; r < AROWS; r++) {
      unsigned long long a0 = 0ull, a1 = 0ull, y0, y1v;
      const uint32_t yb = y_a + (uint32_t)(r * 128);
#pragma unroll
      for (int kk8 = 0; kk8 < 8; kk8++) {
        lds_v2b64(y0, y1v, yb + kk8 * 16);
        a0 = ffma2(Wr2[2 * kk8], y0, a0);
        a1 = ffma2(Wr2[2 * kk8 + 1], y1v, a1);
      }
      float2 f = unpack2(fadd2(a0, a1));
      float wt = f.x + f.y;

      float e0 = ev[r * 512 + j];
      float xr = 0.25f * (e0 - wt) + 0.5f;
      float xs = 1.f - xr;
      float np = fmaf(ALPHA, xr - fmaxf(prr[r], 0.f), prr[r]);
      float ns = fmaf(ALPHA, xs - fmaxf(psr[r], 0.f), psr[r]);
      dm = fmaxf(dm, fmaxf(fabsf(np - prr[r]), fabsf(ns - psr[r])));
      prr[r] = np;
      psr[r] = ns;
      ev[r * 512 + j] = cst[r * 512 + j] + fabsf(np) - fabsf(ns);
      if (last && j < RDIM) {
        out[(size_t)(row0 + r) * N2_DIM + j] = xr;
        out[(size_t)(row0 + r) * N2_DIM + RDIM + KDIM + j] = xs;
      }
    }
#pragma unroll
    for (int o = 16; o > 0; o >>= 1) dm = fmaxf(dm, __shfl_down_sync(0xffffffffu, dm, o));
    if (lane == 0) wmax[wid] = dm;
    __syncthreads();

    if (last) break;
    float mx = 0.f;
#pragma unroll
    for (int q = 0; q < 24; q++) mx = fmaxf(mx, wmax[q]);
    conv = (mx < ADMM_EPS);
  }
}

// ---------------------------------------------------------------------------
extern "C" void kernel_launch(void* const* d_in, const int* in_sizes, int n_in,
                              void* d_out, int out_size) {
  const float* d   = (const float*)d_in[0];  // [1024,32]
  const float* W1  = (const float*)d_in[1];  // [3200,32]
  const float* b1  = (const float*)d_in[2];  // [3200]
  const float* W2  = (const float*)d_in[3];  // [3200,3200]
  const float* b2  = (const float*)d_in[4];  // [3200]
  const float* W3  = (const float*)d_in[5];  // [500,3200]
  const float* b3  = (const float*)d_in[6];  // [500]
  const float* Wm  = (const float*)d_in[7];  // [30,500]
  const float* cap = (const float*)d_in[8];  // [30]
  float* out = (float*)d_out;                // [1024,1030]

  __nv_bfloat16 *dh, *dl, *w1h, *w1l, *w2h, *w2l, *w3h, *w3l, *h1h, *h1l, *h2h, *h2l;
  float *costP, *sinv;
  cudaGetSymbolAddress((void**)&dh, g_dh);   cudaGetSymbolAddress((void**)&dl, g_dl);
  cudaGetSymbolAddress((void**)&w1h, g_W1h); cudaGetSymbolAddress((void**)&w1l, g_W1l);
  cudaGetSymbolAddress((void**)&w2h, g_W2h); cudaGetSymbolAddress((void**)&w2l, g_W2l);
  cudaGetSymbolAddress((void**)&w3h, g_W3h); cudaGetSymbolAddress((void**)&w3l, g_W3l);
  cudaGetSymbolAddress((void**)&h1h, g_h1h); cudaGetSymbolAddress((void**)&h1l, g_h1l);
  cudaGetSymbolAddress((void**)&h2h, g_h2h); cudaGetSymbolAddress((void**)&h2l, g_h2l);
  cudaGetSymbolAddress((void**)&costP, g_costP);
  cudaGetSymbolAddress((void**)&sinv, g_Sinv);

  // 1) Fused hi/lo bf16 splits of all inputs (2 float4 per thread)
  cvt_all<<<(CVT_B4 + 255) / 256, 256>>>(d, W1, W2, W3, dh, dl, w1h, w1l, w2h, w2l, w3h, w3l);

  // 2) Sinv = (I + 0.5 W W^T)^-1
  setup_sinv<<<1, 1024>>>(Wm, sinv);

  const int gemm_smem = 3 * STAGE_B;  // 73728 B
  cudaFuncSetAttribute(mma_gemm<0>, cudaFuncAttributeMaxDynamicSharedMemorySize, gemm_smem);
  cudaFuncSetAttribute(mma_gemm<1>, cudaFuncAttributeMaxDynamicSharedMemorySize, gemm_smem);

  // 3-5) MLP on tensor cores; 64M x 128N tiles, 128 threads, 3 CTA/SM
  mma_gemm<0><<<dim3(HDIM / 128, BDIM / 64), 128, gemm_smem>>>(
      dh, dl, w1h, w1l, b1, nullptr, h1h, h1l, BDIM, HDIM, CDIM, CDIM);
  mma_gemm<0><<<dim3(HDIM / 128, BDIM / 64), 128, gemm_smem>>>(
      h1h, h1l, w2h, w2l, b2, nullptr, h2h, h2l, BDIM, HDIM, HDIM, HDIM);
  mma_gemm<1><<<dim3((RDIM + 127) / 128, BDIM / 64, KSPLIT), 128, gemm_smem>>>(
      h2h, h2l, w3h, w3l, nullptr, costP, nullptr, nullptr, BDIM, RDIM, HDIM, HDIM / KSPLIT);

  // 6) ADMM (persistent; over-relaxed; early exit on block convergence)
  const int admm_smem = (32 * 512 + 2 * AROWS * 512 + 4 * AROWS * 32 + 32 + KDIM * 33 + 24) * (int)sizeof(float);
  cudaFuncSetAttribute(admm_kernel, cudaFuncAttributeMaxDynamicSharedMemorySize, admm_smem);
  admm_kernel<<<BDIM / AROWS, 512, admm_smem>>>(costP, b3, Wm, cap, sinv, out);
}